// round 1
// baseline (speedup 1.0000x reference)
#include <cuda_runtime.h>
#include <cuda_bf16.h>
#include <math.h>

// ---------------------------------------------------------------------------
// Problem constants
// ---------------------------------------------------------------------------
#define B_  2
#define T_  2048
#define E_  1024
#define H_  16
#define D_  64
#define M_  (B_ * T_)          // 4096 rows
#define QKV_N (3 * E_)         // 3072
#define FC_N  (4 * E_)         // 4096

// ---------------------------------------------------------------------------
// Scratch buffers (device globals; no allocations allowed)
// ---------------------------------------------------------------------------
__device__ float g_ln  [(size_t)M_ * E_];     // layernorm output (reused for ln1 and ln2)
__device__ float g_qkv [(size_t)M_ * QKV_N];  // qkv projection
__device__ float g_attn[(size_t)M_ * E_];     // attention output (heads merged)
__device__ float g_x1  [(size_t)M_ * E_];     // x + attn @ W_o + b_o
__device__ float g_fc  [(size_t)M_ * FC_N];   // gelu(ln2 @ W_fc + b_fc)

// ---------------------------------------------------------------------------
// LayerNorm: one block per row of 1024, 256 threads, float4 per thread
// ---------------------------------------------------------------------------
__global__ void layernorm_kernel(const float* __restrict__ x,
                                 const float* __restrict__ gamma,
                                 const float* __restrict__ beta,
                                 float* __restrict__ out)
{
    const int row = blockIdx.x;
    const int tid = threadIdx.x;
    const float4 xv = ((const float4*)(x + (size_t)row * E_))[tid];

    float s  = xv.x + xv.y + xv.z + xv.w;
    float ss = xv.x*xv.x + xv.y*xv.y + xv.z*xv.z + xv.w*xv.w;

    // warp reduce
    #pragma unroll
    for (int o = 16; o > 0; o >>= 1) {
        s  += __shfl_xor_sync(0xffffffffu, s,  o);
        ss += __shfl_xor_sync(0xffffffffu, ss, o);
    }
    __shared__ float sbuf[8], ssbuf[8];
    const int wid = tid >> 5, lane = tid & 31;
    if (lane == 0) { sbuf[wid] = s; ssbuf[wid] = ss; }
    __syncthreads();
    float tot = 0.f, tots = 0.f;
    #pragma unroll
    for (int i = 0; i < 8; i++) { tot += sbuf[i]; tots += ssbuf[i]; }

    const float mean = tot * (1.0f / E_);
    const float var  = tots * (1.0f / E_) - mean * mean;
    const float r    = rsqrtf(var + 1e-5f);

    const float4 gv = ((const float4*)gamma)[tid];
    const float4 bv = ((const float4*)beta)[tid];
    float4 ov;
    ov.x = (xv.x - mean) * r * gv.x + bv.x;
    ov.y = (xv.y - mean) * r * gv.y + bv.y;
    ov.z = (xv.z - mean) * r * gv.z + bv.z;
    ov.w = (xv.w - mean) * r * gv.w + bv.w;
    ((float4*)(out + (size_t)row * E_))[tid] = ov;
}

// ---------------------------------------------------------------------------
// SGEMM: C[M,N] = A[M,K] @ W[K,N] + bias (+ residual | gelu)
// BM=BN=64, BK=16, 256 threads, 4x4 micro-tile per thread.
// EPI: 0 = bias, 1 = bias + residual, 2 = bias + exact GELU
// ---------------------------------------------------------------------------
template<int EPI>
__global__ void __launch_bounds__(256)
sgemm_kernel(const float* __restrict__ A, const float* __restrict__ W,
             const float* __restrict__ bias, const float* __restrict__ res,
             float* __restrict__ C, int M, int N, int K)
{
    __shared__ float As[16][64];   // [k][m]
    __shared__ float Bs[16][64];   // [k][n]

    const int tid = threadIdx.x;
    const int tx = tid & 15;       // 0..15  (n groups of 4)
    const int ty = tid >> 4;       // 0..15  (m groups of 4)
    const int m0 = blockIdx.y * 64;
    const int n0 = blockIdx.x * 64;

    float acc[4][4];
    #pragma unroll
    for (int i = 0; i < 4; i++)
        #pragma unroll
        for (int j = 0; j < 4; j++) acc[i][j] = 0.f;

    for (int k0 = 0; k0 < K; k0 += 16) {
        // load A tile (64 rows x 16 k), store transposed As[k][m]
        #pragma unroll
        for (int i = 0; i < 4; i++) {
            int lin = tid + i * 256;
            int r = lin >> 4, c = lin & 15;
            As[c][r] = A[(size_t)(m0 + r) * K + k0 + c];
        }
        // load W tile (16 k x 64 n)
        #pragma unroll
        for (int i = 0; i < 4; i++) {
            int lin = tid + i * 256;
            int kk = lin >> 6, n = lin & 63;
            Bs[kk][n] = W[(size_t)(k0 + kk) * N + n0 + n];
        }
        __syncthreads();

        #pragma unroll
        for (int kk = 0; kk < 16; kk++) {
            const float4 a = *(const float4*)&As[kk][ty * 4];
            const float4 b = *(const float4*)&Bs[kk][tx * 4];
            acc[0][0] += a.x * b.x; acc[0][1] += a.x * b.y; acc[0][2] += a.x * b.z; acc[0][3] += a.x * b.w;
            acc[1][0] += a.y * b.x; acc[1][1] += a.y * b.y; acc[1][2] += a.y * b.z; acc[1][3] += a.y * b.w;
            acc[2][0] += a.z * b.x; acc[2][1] += a.z * b.y; acc[2][2] += a.z * b.z; acc[2][3] += a.z * b.w;
            acc[3][0] += a.w * b.x; acc[3][1] += a.w * b.y; acc[3][2] += a.w * b.z; acc[3][3] += a.w * b.w;
        }
        __syncthreads();
    }

    #pragma unroll
    for (int i = 0; i < 4; i++) {
        const int row = m0 + ty * 4 + i;
        #pragma unroll
        for (int j = 0; j < 4; j++) {
            const int col = n0 + tx * 4 + j;
            float v = acc[i][j] + bias[col];
            if (EPI == 1) v += res[(size_t)row * N + col];
            if (EPI == 2) v = 0.5f * v * (1.0f + erff(v * 0.70710678118654752f));
            C[(size_t)row * N + col] = v;
        }
    }
}

// ---------------------------------------------------------------------------
// Flash attention (fp32, causal). One block per (b*h, 64-query tile).
// 64 threads: thread = one query row; q and o accumulator in registers.
// qkv row layout: [q(0..1023) | k(1024..2047) | v(2048..3071)], head h at h*64.
// ---------------------------------------------------------------------------
__global__ void __launch_bounds__(64)
flash_attn_kernel(const float* __restrict__ qkv, float* __restrict__ out)
{
    __shared__ float Ks[64][64];
    __shared__ float Vs[64][64];
    __shared__ float Ss[64][64];   // scores, [j][query_thread]

    const int bh = blockIdx.y;               // 0..31
    const int b  = bh >> 4;
    const int h  = bh & 15;
    const int m0 = blockIdx.x * 64;
    const int tid = threadIdx.x;
    const int tq  = m0 + tid;

    const size_t rowQ = ((size_t)(b * T_ + tq)) * QKV_N + h * D_;
    float q[64];
    #pragma unroll
    for (int d = 0; d < 64; d++) q[d] = qkv[rowQ + d] * 0.125f;  // 1/sqrt(64)

    float o[64];
    #pragma unroll
    for (int d = 0; d < 64; d++) o[d] = 0.f;
    float mi = -INFINITY, li = 0.f;

    for (int j0 = 0; j0 <= m0; j0 += 64) {
        const size_t baseK = ((size_t)(b * T_ + j0)) * QKV_N + E_ + h * D_;
        const size_t baseV = baseK + E_;

        __syncthreads();  // protect smem reuse from previous iteration
        for (int i = 0; i < 64; i++) {
            Ks[i][tid] = qkv[baseK + (size_t)i * QKV_N + tid];
            Vs[i][tid] = qkv[baseV + (size_t)i * QKV_N + tid];
        }
        __syncthreads();

        // pass 1: scores + running max
        float tmax = mi;
        for (int j = 0; j < 64; j++) {
            const float4* kr = (const float4*)Ks[j];
            float sx = 0.f, sy = 0.f, sz = 0.f, sw = 0.f;
            #pragma unroll
            for (int d4 = 0; d4 < 16; d4++) {
                const float4 k4 = kr[d4];
                sx += q[d4 * 4 + 0] * k4.x;
                sy += q[d4 * 4 + 1] * k4.y;
                sz += q[d4 * 4 + 2] * k4.z;
                sw += q[d4 * 4 + 3] * k4.w;
            }
            float s = (sx + sy) + (sz + sw);
            if (j0 + j > tq) s = -INFINITY;   // causal mask
            Ss[j][tid] = s;
            tmax = fmaxf(tmax, s);
        }

        const float mnew  = tmax;
        const float alpha = __expf(mi - mnew);
        li *= alpha;
        #pragma unroll
        for (int d = 0; d < 64; d++) o[d] *= alpha;

        // pass 2: softmax weights + PV accumulation
        for (int j = 0; j < 64; j++) {
            const float p = __expf(Ss[j][tid] - mnew);
            li += p;
            const float4* vr = (const float4*)Vs[j];
            #pragma unroll
            for (int d4 = 0; d4 < 16; d4++) {
                const float4 v4 = vr[d4];
                o[d4 * 4 + 0] += p * v4.x;
                o[d4 * 4 + 1] += p * v4.y;
                o[d4 * 4 + 2] += p * v4.z;
                o[d4 * 4 + 3] += p * v4.w;
            }
        }
        mi = mnew;
    }

    const float inv = 1.0f / li;
    const size_t rowO = ((size_t)(b * T_ + tq)) * E_ + h * D_;
    #pragma unroll
    for (int d = 0; d < 64; d++) out[rowO + d] = o[d] * inv;
}

// ---------------------------------------------------------------------------
// Launch
// ---------------------------------------------------------------------------
extern "C" void kernel_launch(void* const* d_in, const int* in_sizes, int n_in,
                              void* d_out, int out_size)
{
    const float* x      = (const float*)d_in[0];
    const float* ln1_g  = (const float*)d_in[1];
    const float* ln1_b  = (const float*)d_in[2];
    const float* ln2_g  = (const float*)d_in[3];
    const float* ln2_b  = (const float*)d_in[4];
    const float* W_qkv  = (const float*)d_in[5];
    const float* b_qkv  = (const float*)d_in[6];
    const float* W_o    = (const float*)d_in[7];
    const float* b_o    = (const float*)d_in[8];
    const float* W_fc   = (const float*)d_in[9];
    const float* b_fc   = (const float*)d_in[10];
    const float* W_proj = (const float*)d_in[11];
    const float* b_proj = (const float*)d_in[12];
    float* out = (float*)d_out;

    float *p_ln, *p_qkv, *p_attn, *p_x1, *p_fc;
    cudaGetSymbolAddress((void**)&p_ln,   g_ln);
    cudaGetSymbolAddress((void**)&p_qkv,  g_qkv);
    cudaGetSymbolAddress((void**)&p_attn, g_attn);
    cudaGetSymbolAddress((void**)&p_x1,   g_x1);
    cudaGetSymbolAddress((void**)&p_fc,   g_fc);

    // 1. ln1 = LN(x)
    layernorm_kernel<<<M_, 256>>>(x, ln1_g, ln1_b, p_ln);
    // 2. qkv = ln1 @ W_qkv + b_qkv
    sgemm_kernel<0><<<dim3(QKV_N / 64, M_ / 64), 256>>>(p_ln, W_qkv, b_qkv, nullptr, p_qkv, M_, QKV_N, E_);
    // 3. attn = causal softmax(q k^T / sqrt(d)) v, heads merged
    flash_attn_kernel<<<dim3(T_ / 64, B_ * H_), 64>>>(p_qkv, p_attn);
    // 4. x1 = x + attn @ W_o + b_o
    sgemm_kernel<1><<<dim3(E_ / 64, M_ / 64), 256>>>(p_attn, W_o, b_o, x, p_x1, M_, E_, E_);
    // 5. ln2 = LN(x1)
    layernorm_kernel<<<M_, 256>>>(p_x1, ln2_g, ln2_b, p_ln);
    // 6. fc = gelu(ln2 @ W_fc + b_fc)
    sgemm_kernel<2><<<dim3(FC_N / 64, M_ / 64), 256>>>(p_ln, W_fc, b_fc, nullptr, p_fc, M_, FC_N, E_);
    // 7. out = x1 + fc @ W_proj + b_proj
    sgemm_kernel<1><<<dim3(E_ / 64, M_ / 64), 256>>>(p_fc, W_proj, b_proj, p_x1, out, M_, E_, FC_N);
}

// round 2
// speedup vs baseline: 1.6021x; 1.6021x over previous
#include <cuda_runtime.h>
#include <cuda_bf16.h>
#include <math.h>

// ---------------------------------------------------------------------------
// Problem constants
// ---------------------------------------------------------------------------
#define B_  2
#define T_  2048
#define E_  1024
#define H_  16
#define D_  64
#define M_  (B_ * T_)          // 4096 rows
#define QKV_N (3 * E_)         // 3072
#define FC_N  (4 * E_)         // 4096

// ---------------------------------------------------------------------------
// Scratch buffers (device globals; no allocations allowed)
// ---------------------------------------------------------------------------
__device__ float g_ln  [(size_t)M_ * E_];
__device__ float g_qkv [(size_t)M_ * QKV_N];
__device__ float g_attn[(size_t)M_ * E_];
__device__ float g_x1  [(size_t)M_ * E_];
__device__ float g_fc  [(size_t)M_ * FC_N];

// ---------------------------------------------------------------------------
// LayerNorm: one block per row of 1024, 256 threads, float4 per thread
// ---------------------------------------------------------------------------
__global__ void layernorm_kernel(const float* __restrict__ x,
                                 const float* __restrict__ gamma,
                                 const float* __restrict__ beta,
                                 float* __restrict__ out)
{
    const int row = blockIdx.x;
    const int tid = threadIdx.x;
    const float4 xv = ((const float4*)(x + (size_t)row * E_))[tid];

    float s  = xv.x + xv.y + xv.z + xv.w;
    float ss = xv.x*xv.x + xv.y*xv.y + xv.z*xv.z + xv.w*xv.w;

    #pragma unroll
    for (int o = 16; o > 0; o >>= 1) {
        s  += __shfl_xor_sync(0xffffffffu, s,  o);
        ss += __shfl_xor_sync(0xffffffffu, ss, o);
    }
    __shared__ float sbuf[8], ssbuf[8];
    const int wid = tid >> 5, lane = tid & 31;
    if (lane == 0) { sbuf[wid] = s; ssbuf[wid] = ss; }
    __syncthreads();
    float tot = 0.f, tots = 0.f;
    #pragma unroll
    for (int i = 0; i < 8; i++) { tot += sbuf[i]; tots += ssbuf[i]; }

    const float mean = tot * (1.0f / E_);
    const float var  = tots * (1.0f / E_) - mean * mean;
    const float r    = rsqrtf(var + 1e-5f);

    const float4 gv = ((const float4*)gamma)[tid];
    const float4 bv = ((const float4*)beta)[tid];
    float4 ov;
    ov.x = (xv.x - mean) * r * gv.x + bv.x;
    ov.y = (xv.y - mean) * r * gv.y + bv.y;
    ov.z = (xv.z - mean) * r * gv.z + bv.z;
    ov.w = (xv.w - mean) * r * gv.w + bv.w;
    ((float4*)(out + (size_t)row * E_))[tid] = ov;
}

// ---------------------------------------------------------------------------
// SGEMM: C[M,N] = A[M,K] @ W[K,N] + bias (+ residual | gelu)
// BM=BN=128, BK=16, 256 threads (8 warps, 2x4), 8x8 micro-tile per thread.
// Double-buffered smem with register prefetch. One __syncthreads per k-tile.
// EPI: 0 = bias, 1 = bias + residual, 2 = bias + exact GELU
// ---------------------------------------------------------------------------
template<int EPI>
__global__ void __launch_bounds__(256, 2)
sgemm128_kernel(const float* __restrict__ A, const float* __restrict__ W,
                const float* __restrict__ bias, const float* __restrict__ res,
                float* __restrict__ C, int M, int N, int K)
{
    __shared__ float As[2][16][132];   // [buf][k][m], padded row
    __shared__ float Bs[2][16][132];   // [buf][k][n], padded row

    const int tid  = threadIdx.x;
    const int wid  = tid >> 5;
    const int lane = tid & 31;
    const int tm   = lane >> 2;            // 0..7
    const int tn   = lane & 3;             // 0..3
    const int wm0  = (wid >> 2) * 64;      // warp m offset (0 or 64)
    const int wn0  = (wid & 3) * 32;       // warp n offset (0,32,64,96)
    const int m0   = blockIdx.y * 128;
    const int n0   = blockIdx.x * 128;

    // A-tile load coords: 512 float4s, thread handles idx=tid and idx=tid+256
    const int ar0 = tid >> 2;              // 0..63
    const int ac4 = tid & 3;               // float4 index within 16-k row
    // B-tile load coords
    const int bk0 = tid >> 5;              // 0..7
    const int bn4 = tid & 31;              // float4 index within 128-n row

    float acc[8][8];
    #pragma unroll
    for (int i = 0; i < 8; i++)
        #pragma unroll
        for (int j = 0; j < 8; j++) acc[i][j] = 0.f;

    const int nt = K >> 4;

    // ---- prologue: load tile 0 into buffer 0 ----
    {
        const float4 a0 = *(const float4*)(A + (size_t)(m0 + ar0)      * K + ac4 * 4);
        const float4 a1 = *(const float4*)(A + (size_t)(m0 + ar0 + 64) * K + ac4 * 4);
        const float4 b0 = *(const float4*)(W + (size_t)(bk0)     * N + n0 + bn4 * 4);
        const float4 b1 = *(const float4*)(W + (size_t)(bk0 + 8) * N + n0 + bn4 * 4);
        As[0][ac4*4+0][ar0]    = a0.x; As[0][ac4*4+1][ar0]    = a0.y;
        As[0][ac4*4+2][ar0]    = a0.z; As[0][ac4*4+3][ar0]    = a0.w;
        As[0][ac4*4+0][ar0+64] = a1.x; As[0][ac4*4+1][ar0+64] = a1.y;
        As[0][ac4*4+2][ar0+64] = a1.z; As[0][ac4*4+3][ar0+64] = a1.w;
        *(float4*)&Bs[0][bk0][bn4*4]     = b0;
        *(float4*)&Bs[0][bk0 + 8][bn4*4] = b1;
    }
    __syncthreads();

    for (int t = 0; t < nt; ++t) {
        const int buf = t & 1;
        float4 pa0, pa1, pb0, pb1;
        const bool more = (t + 1 < nt);
        if (more) {
            const int k0 = (t + 1) << 4;
            pa0 = *(const float4*)(A + (size_t)(m0 + ar0)      * K + k0 + ac4 * 4);
            pa1 = *(const float4*)(A + (size_t)(m0 + ar0 + 64) * K + k0 + ac4 * 4);
            pb0 = *(const float4*)(W + (size_t)(k0 + bk0)     * N + n0 + bn4 * 4);
            pb1 = *(const float4*)(W + (size_t)(k0 + bk0 + 8) * N + n0 + bn4 * 4);
        }

        #pragma unroll
        for (int kk = 0; kk < 16; kk++) {
            const float4 aL = *(const float4*)&As[buf][kk][wm0 + tm * 4];
            const float4 aH = *(const float4*)&As[buf][kk][wm0 + tm * 4 + 32];
            const float4 bL = *(const float4*)&Bs[buf][kk][wn0 + tn * 4];
            const float4 bH = *(const float4*)&Bs[buf][kk][wn0 + tn * 4 + 16];
            const float a[8] = {aL.x, aL.y, aL.z, aL.w, aH.x, aH.y, aH.z, aH.w};
            const float b[8] = {bL.x, bL.y, bL.z, bL.w, bH.x, bH.y, bH.z, bH.w};
            #pragma unroll
            for (int i = 0; i < 8; i++)
                #pragma unroll
                for (int j = 0; j < 8; j++)
                    acc[i][j] += a[i] * b[j];
        }

        if (more) {
            const int nb = buf ^ 1;
            As[nb][ac4*4+0][ar0]    = pa0.x; As[nb][ac4*4+1][ar0]    = pa0.y;
            As[nb][ac4*4+2][ar0]    = pa0.z; As[nb][ac4*4+3][ar0]    = pa0.w;
            As[nb][ac4*4+0][ar0+64] = pa1.x; As[nb][ac4*4+1][ar0+64] = pa1.y;
            As[nb][ac4*4+2][ar0+64] = pa1.z; As[nb][ac4*4+3][ar0+64] = pa1.w;
            *(float4*)&Bs[nb][bk0][bn4*4]     = pb0;
            *(float4*)&Bs[nb][bk0 + 8][bn4*4] = pb1;
            __syncthreads();
        }
    }

    // ---- epilogue ----
    const int colL = n0 + wn0 + tn * 4;
    const int colH = colL + 16;
    const float4 biasL = *(const float4*)(bias + colL);
    const float4 biasH = *(const float4*)(bias + colH);

    #pragma unroll
    for (int ii = 0; ii < 8; ii++) {
        const size_t row = (size_t)(m0 + wm0 + tm * 4 + (ii & 3) + (ii >> 2) * 32);
        #pragma unroll
        for (int h = 0; h < 2; h++) {
            const int col = h ? colH : colL;
            const float4 bv = h ? biasH : biasL;
            float4 v;
            v.x = acc[ii][h*4+0] + bv.x;
            v.y = acc[ii][h*4+1] + bv.y;
            v.z = acc[ii][h*4+2] + bv.z;
            v.w = acc[ii][h*4+3] + bv.w;
            if (EPI == 1) {
                const float4 r4 = *(const float4*)(res + row * N + col);
                v.x += r4.x; v.y += r4.y; v.z += r4.z; v.w += r4.w;
            }
            if (EPI == 2) {
                v.x = 0.5f * v.x * (1.0f + erff(v.x * 0.70710678118654752f));
                v.y = 0.5f * v.y * (1.0f + erff(v.y * 0.70710678118654752f));
                v.z = 0.5f * v.z * (1.0f + erff(v.z * 0.70710678118654752f));
                v.w = 0.5f * v.w * (1.0f + erff(v.w * 0.70710678118654752f));
            }
            *(float4*)(C + row * N + col) = v;
        }
    }
}

// ---------------------------------------------------------------------------
// Flash attention (fp32, causal). One block per (b*h, 64-query tile).
// ---------------------------------------------------------------------------
__global__ void __launch_bounds__(64)
flash_attn_kernel(const float* __restrict__ qkv, float* __restrict__ out)
{
    __shared__ float Ks[64][64];
    __shared__ float Vs[64][64];
    __shared__ float Ss[64][64];

    const int bh = blockIdx.y;
    const int b  = bh >> 4;
    const int h  = bh & 15;
    const int m0 = blockIdx.x * 64;
    const int tid = threadIdx.x;
    const int tq  = m0 + tid;

    const size_t rowQ = ((size_t)(b * T_ + tq)) * QKV_N + h * D_;
    float q[64];
    #pragma unroll
    for (int d = 0; d < 64; d++) q[d] = qkv[rowQ + d] * 0.125f;

    float o[64];
    #pragma unroll
    for (int d = 0; d < 64; d++) o[d] = 0.f;
    float mi = -INFINITY, li = 0.f;

    for (int j0 = 0; j0 <= m0; j0 += 64) {
        const size_t baseK = ((size_t)(b * T_ + j0)) * QKV_N + E_ + h * D_;
        const size_t baseV = baseK + E_;

        __syncthreads();
        for (int i = 0; i < 64; i++) {
            Ks[i][tid] = qkv[baseK + (size_t)i * QKV_N + tid];
            Vs[i][tid] = qkv[baseV + (size_t)i * QKV_N + tid];
        }
        __syncthreads();

        float tmax = mi;
        for (int j = 0; j < 64; j++) {
            const float4* kr = (const float4*)Ks[j];
            float sx = 0.f, sy = 0.f, sz = 0.f, sw = 0.f;
            #pragma unroll
            for (int d4 = 0; d4 < 16; d4++) {
                const float4 k4 = kr[d4];
                sx += q[d4 * 4 + 0] * k4.x;
                sy += q[d4 * 4 + 1] * k4.y;
                sz += q[d4 * 4 + 2] * k4.z;
                sw += q[d4 * 4 + 3] * k4.w;
            }
            float s = (sx + sy) + (sz + sw);
            if (j0 + j > tq) s = -INFINITY;
            Ss[j][tid] = s;
            tmax = fmaxf(tmax, s);
        }

        const float mnew  = tmax;
        const float alpha = __expf(mi - mnew);
        li *= alpha;
        #pragma unroll
        for (int d = 0; d < 64; d++) o[d] *= alpha;

        for (int j = 0; j < 64; j++) {
            const float p = __expf(Ss[j][tid] - mnew);
            li += p;
            const float4* vr = (const float4*)Vs[j];
            #pragma unroll
            for (int d4 = 0; d4 < 16; d4++) {
                const float4 v4 = vr[d4];
                o[d4 * 4 + 0] += p * v4.x;
                o[d4 * 4 + 1] += p * v4.y;
                o[d4 * 4 + 2] += p * v4.z;
                o[d4 * 4 + 3] += p * v4.w;
            }
        }
        mi = mnew;
    }

    const float inv = 1.0f / li;
    const size_t rowO = ((size_t)(b * T_ + tq)) * E_ + h * D_;
    #pragma unroll
    for (int d = 0; d < 64; d++) out[rowO + d] = o[d] * inv;
}

// ---------------------------------------------------------------------------
// Launch
// ---------------------------------------------------------------------------
extern "C" void kernel_launch(void* const* d_in, const int* in_sizes, int n_in,
                              void* d_out, int out_size)
{
    const float* x      = (const float*)d_in[0];
    const float* ln1_g  = (const float*)d_in[1];
    const float* ln1_b  = (const float*)d_in[2];
    const float* ln2_g  = (const float*)d_in[3];
    const float* ln2_b  = (const float*)d_in[4];
    const float* W_qkv  = (const float*)d_in[5];
    const float* b_qkv  = (const float*)d_in[6];
    const float* W_o    = (const float*)d_in[7];
    const float* b_o    = (const float*)d_in[8];
    const float* W_fc   = (const float*)d_in[9];
    const float* b_fc   = (const float*)d_in[10];
    const float* W_proj = (const float*)d_in[11];
    const float* b_proj = (const float*)d_in[12];
    float* out = (float*)d_out;

    float *p_ln, *p_qkv, *p_attn, *p_x1, *p_fc;
    cudaGetSymbolAddress((void**)&p_ln,   g_ln);
    cudaGetSymbolAddress((void**)&p_qkv,  g_qkv);
    cudaGetSymbolAddress((void**)&p_attn, g_attn);
    cudaGetSymbolAddress((void**)&p_x1,   g_x1);
    cudaGetSymbolAddress((void**)&p_fc,   g_fc);

    // 1. ln1 = LN(x)
    layernorm_kernel<<<M_, 256>>>(x, ln1_g, ln1_b, p_ln);
    // 2. qkv = ln1 @ W_qkv + b_qkv
    sgemm128_kernel<0><<<dim3(QKV_N / 128, M_ / 128), 256>>>(p_ln, W_qkv, b_qkv, nullptr, p_qkv, M_, QKV_N, E_);
    // 3. attn = causal softmax(q k^T / sqrt(d)) v
    flash_attn_kernel<<<dim3(T_ / 64, B_ * H_), 64>>>(p_qkv, p_attn);
    // 4. x1 = x + attn @ W_o + b_o
    sgemm128_kernel<1><<<dim3(E_ / 128, M_ / 128), 256>>>(p_attn, W_o, b_o, x, p_x1, M_, E_, E_);
    // 5. ln2 = LN(x1)
    layernorm_kernel<<<M_, 256>>>(p_x1, ln2_g, ln2_b, p_ln);
    // 6. fc = gelu(ln2 @ W_fc + b_fc)
    sgemm128_kernel<2><<<dim3(FC_N / 128, M_ / 128), 256>>>(p_ln, W_fc, b_fc, nullptr, p_fc, M_, FC_N, E_);
    // 7. out = x1 + fc @ W_proj + b_proj
    sgemm128_kernel<1><<<dim3(E_ / 128, M_ / 128), 256>>>(p_fc, W_proj, b_proj, p_x1, out, M_, E_, FC_N);
}

// round 4
// speedup vs baseline: 2.9893x; 1.8658x over previous
#include <cuda_runtime.h>
#include <cuda_bf16.h>
#include <math.h>
#include <stdint.h>

// ---------------------------------------------------------------------------
// Problem constants
// ---------------------------------------------------------------------------
#define B_  2
#define T_  2048
#define E_  1024
#define H_  16
#define D_  64
#define M_  (B_ * T_)          // 4096
#define QKV_N (3 * E_)         // 3072
#define FC_N  (4 * E_)         // 4096

// ---------------------------------------------------------------------------
// Scratch (device globals; allocations forbidden)
// ---------------------------------------------------------------------------
__device__ float g_ln  [(size_t)M_ * E_];
__device__ float g_qkv [(size_t)M_ * QKV_N];
__device__ float g_attn[(size_t)M_ * E_];
__device__ float g_x1  [(size_t)M_ * E_];
__device__ float g_fc  [(size_t)M_ * FC_N];
__device__ float g_wqkvP [(size_t)QKV_N * E_];   // fragment-packed weights (tf32)
__device__ float g_woP   [(size_t)E_ * E_];
__device__ float g_wfcP  [(size_t)FC_N * E_];
__device__ float g_wprojP[(size_t)E_ * FC_N];

// ---------------------------------------------------------------------------
// Helpers
// ---------------------------------------------------------------------------
__device__ __forceinline__ uint32_t smem_u32(const void* p) {
    uint32_t a;
    asm("{ .reg .u64 t; cvta.to.shared.u64 t, %1; cvt.u32.u64 %0, t; }" : "=r"(a) : "l"(p));
    return a;
}
__device__ __forceinline__ float rna_tf32(float x) {
    uint32_t u;
    asm("cvt.rna.tf32.f32 %0, %1;" : "=r"(u) : "f"(x));
    return __uint_as_float(u);
}
#define CP_ASYNC16(dst, src) \
    asm volatile("cp.async.cg.shared.global [%0], [%1], 16;" :: "r"(dst), "l"(src) : "memory")
#define CP_COMMIT() asm volatile("cp.async.commit_group;" ::: "memory")

__device__ __forceinline__ void mma_tf32(float (&c)[4],
                                         float a0, float a1, float a2, float a3,
                                         float b0, float b1) {
    asm volatile(
        "mma.sync.aligned.m16n8k8.row.col.f32.tf32.tf32.f32 "
        "{%0,%1,%2,%3}, {%4,%5,%6,%7}, {%8,%9}, {%0,%1,%2,%3};"
        : "+f"(c[0]), "+f"(c[1]), "+f"(c[2]), "+f"(c[3])
        : "r"(__float_as_uint(a0)), "r"(__float_as_uint(a1)),
          "r"(__float_as_uint(a2)), "r"(__float_as_uint(a3)),
          "r"(__float_as_uint(b0)), "r"(__float_as_uint(b1)));
}

// ---------------------------------------------------------------------------
// Weight pack: W[K,N] row-major -> fragment-major tiles for mma.sync B operand.
// Tile = 128 n x 32 k. Superfrag = 16n x 8k = 128 floats, lane-major:
//   float4 of lane l (group g=l>>2 -> n8-row, tig=l&3 -> k) =
//     { B[n0+g][k0+tig], B[n0+g][k0+tig+4], B[n0+8+g][k0+tig], B[n0+8+g][k0+tig+4] }
// Superfrag id s = kb*8 + nb  (kb: k8 block 0..3, nb: n16 block 0..7).
// One block per tile. Values tf32-rounded (rna).
// ---------------------------------------------------------------------------
__global__ void pack_weight_kernel(const float* __restrict__ W, float* __restrict__ Wp,
                                   int K, int N)
{
    const int nt = blockIdx.x, kt = blockIdx.y;
    const int t = threadIdx.x;                 // 256
    const size_t tile_base = ((size_t)nt * (K >> 5) + kt) * 4096;
    const int nn = t >> 1;                     // 0..127
    #pragma unroll
    for (int i = 0; i < 16; i++) {
        const int kk = (t & 1) * 16 + i;       // 0..31
        const int kb = kk >> 3, kr = kk & 7;
        const int nb = nn >> 4, nr = nn & 15;
        const int lane = (nr & 7) * 4 + (kr & 3);
        const int j = ((nr >> 3) << 1) + (kr >> 2);
        const int off = (kb * 8 + nb) * 128 + lane * 4 + j;
        const float v = W[(size_t)(kt * 32 + kk) * N + nt * 128 + nn];
        Wp[tile_base + off] = rna_tf32(v);
    }
}

// ---------------------------------------------------------------------------
// tf32 mma.sync GEMM: C[M,N] = A[M,K] @ W + bias (+res | gelu)
// A row-major fp32 (values already tf32-rounded by producers).
// W pre-packed by pack_weight_kernel.
// BM=BN=128, BK=32, 256 threads, 8 warps (4M x 2N), warp tile 32x64.
// cp.async double-buffered. EPI: 0=bias, 1=bias+res, 2=bias+GELU(->tf32)
// ---------------------------------------------------------------------------
#define SA_STRIDE 36                       // floats per A smem row (pad kills conflicts)
#define SA_BYTES  (128 * SA_STRIDE * 4)    // 18432
#define SB_BYTES  16384
#define BUF_BYTES (SA_BYTES + SB_BYTES)    // 34816
#define GEMM_SMEM_BYTES (2 * BUF_BYTES)    // 69632

template<int EPI>
__global__ void __launch_bounds__(256, 2)
gemm_mma_kernel(const float* __restrict__ A, const float* __restrict__ Wp,
                const float* __restrict__ bias, const float* __restrict__ res,
                float* __restrict__ C, int N, int K)
{
    extern __shared__ char smem[];
    const uint32_t sbase = smem_u32(smem);
    const int tid  = threadIdx.x;
    const int wid  = tid >> 5;
    const int lane = tid & 31;
    const int g    = lane >> 2;            // group 0..7
    const int tig  = lane & 3;             // 0..3
    const int wm   = (wid >> 1) * 32;      // warp m offset
    const int wn   = (wid & 1) * 64;       // warp n offset
    const int m0   = blockIdx.y * 128;
    const int n0   = blockIdx.x * 128;

    const int ntile = K >> 5;
    const size_t wtile0 = (size_t)blockIdx.x * ntile * 4096;

    // A copy coords: chunk ch = tid + i*256 (i<4): m = ch>>3, kc = ch&7
    const int am = tid >> 3;               // base row (0..31), +32*i
    const int ac = tid & 7;                // 16B chunk within 32-float k row

    float acc[2][8][4];
    #pragma unroll
    for (int mt = 0; mt < 2; mt++)
        #pragma unroll
        for (int q = 0; q < 8; q++)
            #pragma unroll
            for (int r = 0; r < 4; r++) acc[mt][q][r] = 0.f;

    // ---- tile loader ----
    auto load_tile = [&](int buf, int kt) {
        const uint32_t sA = sbase + buf * BUF_BYTES;
        const uint32_t sB = sA + SA_BYTES;
        const float* asrc = A + (size_t)(m0 + am) * K + kt * 32 + ac * 4;
        #pragma unroll
        for (int i = 0; i < 4; i++) {
            CP_ASYNC16(sA + (uint32_t)(am + i * 32) * (SA_STRIDE * 4) + ac * 16,
                       asrc + (size_t)i * 32 * K);
        }
        const float* bsrc = Wp + wtile0 + (size_t)kt * 4096 + tid * 4;
        #pragma unroll
        for (int i = 0; i < 4; i++) {
            CP_ASYNC16(sB + (tid + i * 256) * 16, bsrc + i * 1024);
        }
        CP_COMMIT();
    };

    load_tile(0, 0);

    for (int t = 0; t < ntile; t++) {
        const int cur = t & 1;
        if (t + 1 < ntile) {
            load_tile(cur ^ 1, t + 1);
            asm volatile("cp.async.wait_group 1;" ::: "memory");
        } else {
            asm volatile("cp.async.wait_group 0;" ::: "memory");
        }
        __syncthreads();

        const float* As = (const float*)(smem + cur * BUF_BYTES);
        const float* Bs = (const float*)(smem + cur * BUF_BYTES + SA_BYTES);

        #pragma unroll
        for (int kb = 0; kb < 4; kb++) {
            float a[2][4];
            #pragma unroll
            for (int mt = 0; mt < 2; mt++) {
                const int r = wm + mt * 16 + g;
                a[mt][0] = As[r * SA_STRIDE + kb * 8 + tig];
                a[mt][1] = As[(r + 8) * SA_STRIDE + kb * 8 + tig];
                a[mt][2] = As[r * SA_STRIDE + kb * 8 + tig + 4];
                a[mt][3] = As[(r + 8) * SA_STRIDE + kb * 8 + tig + 4];
            }
            float4 bq[4];
            #pragma unroll
            for (int q = 0; q < 4; q++) {
                const int s = kb * 8 + (wn >> 4) + q;
                bq[q] = *(const float4*)(Bs + s * 128 + lane * 4);
            }
            #pragma unroll
            for (int mt = 0; mt < 2; mt++) {
                #pragma unroll
                for (int q = 0; q < 4; q++) {
                    mma_tf32(acc[mt][2 * q + 0], a[mt][0], a[mt][1], a[mt][2], a[mt][3],
                             bq[q].x, bq[q].y);
                    mma_tf32(acc[mt][2 * q + 1], a[mt][0], a[mt][1], a[mt][2], a[mt][3],
                             bq[q].z, bq[q].w);
                }
            }
        }
        __syncthreads();
    }

    // ---- epilogue: acc c0,c1 -> (row, col..col+1); c2,c3 -> (row+8, ...) ----
    #pragma unroll
    for (int mt = 0; mt < 2; mt++) {
        const size_t r0 = (size_t)(m0 + wm + mt * 16 + g);
        #pragma unroll
        for (int q = 0; q < 8; q++) {
            const int col = n0 + wn + q * 8 + 2 * tig;
            const float2 bv = *(const float2*)(bias + col);
            #pragma unroll
            for (int hh = 0; hh < 2; hh++) {
                const size_t row = r0 + hh * 8;
                float vx = acc[mt][q][hh * 2 + 0] + bv.x;
                float vy = acc[mt][q][hh * 2 + 1] + bv.y;
                if (EPI == 1) {
                    const float2 r2 = *(const float2*)(res + row * N + col);
                    vx += r2.x; vy += r2.y;
                }
                if (EPI == 2) {
                    vx = rna_tf32(0.5f * vx * (1.0f + erff(vx * 0.70710678118654752f)));
                    vy = rna_tf32(0.5f * vy * (1.0f + erff(vy * 0.70710678118654752f)));
                }
                float2 o2; o2.x = vx; o2.y = vy;
                *(float2*)(C + row * N + col) = o2;
            }
        }
    }
}

// ---------------------------------------------------------------------------
// LayerNorm (output tf32-rounded: it only feeds tensor GEMMs)
// ---------------------------------------------------------------------------
__global__ void layernorm_kernel(const float* __restrict__ x,
                                 const float* __restrict__ gamma,
                                 const float* __restrict__ beta,
                                 float* __restrict__ out)
{
    const int row = blockIdx.x;
    const int tid = threadIdx.x;
    const float4 xv = ((const float4*)(x + (size_t)row * E_))[tid];

    float s  = xv.x + xv.y + xv.z + xv.w;
    float ss = xv.x*xv.x + xv.y*xv.y + xv.z*xv.z + xv.w*xv.w;
    #pragma unroll
    for (int o = 16; o > 0; o >>= 1) {
        s  += __shfl_xor_sync(0xffffffffu, s,  o);
        ss += __shfl_xor_sync(0xffffffffu, ss, o);
    }
    __shared__ float sbuf[8], ssbuf[8];
    const int wid = tid >> 5, lane = tid & 31;
    if (lane == 0) { sbuf[wid] = s; ssbuf[wid] = ss; }
    __syncthreads();
    float tot = 0.f, tots = 0.f;
    #pragma unroll
    for (int i = 0; i < 8; i++) { tot += sbuf[i]; tots += ssbuf[i]; }

    const float mean = tot * (1.0f / E_);
    const float var  = tots * (1.0f / E_) - mean * mean;
    const float r    = rsqrtf(var + 1e-5f);

    const float4 gv = ((const float4*)gamma)[tid];
    const float4 bv = ((const float4*)beta)[tid];
    float4 ov;
    ov.x = rna_tf32((xv.x - mean) * r * gv.x + bv.x);
    ov.y = rna_tf32((xv.y - mean) * r * gv.y + bv.y);
    ov.z = rna_tf32((xv.z - mean) * r * gv.z + bv.z);
    ov.w = rna_tf32((xv.w - mean) * r * gv.w + bv.w);
    ((float4*)(out + (size_t)row * E_))[tid] = ov;
}

// ---------------------------------------------------------------------------
// Flash attention (fp32, causal) — output tf32-rounded (feeds W_o GEMM)
// ---------------------------------------------------------------------------
__global__ void __launch_bounds__(64)
flash_attn_kernel(const float* __restrict__ qkv, float* __restrict__ out)
{
    __shared__ float Ks[64][64];
    __shared__ float Vs[64][64];
    __shared__ float Ss[64][64];

    const int bh = blockIdx.y;
    const int b  = bh >> 4;
    const int h  = bh & 15;
    const int m0 = blockIdx.x * 64;
    const int tid = threadIdx.x;
    const int tq  = m0 + tid;

    const size_t rowQ = ((size_t)(b * T_ + tq)) * QKV_N + h * D_;
    float q[64];
    #pragma unroll
    for (int d = 0; d < 64; d++) q[d] = qkv[rowQ + d] * 0.125f;

    float o[64];
    #pragma unroll
    for (int d = 0; d < 64; d++) o[d] = 0.f;
    float mi = -INFINITY, li = 0.f;

    for (int j0 = 0; j0 <= m0; j0 += 64) {
        const size_t baseK = ((size_t)(b * T_ + j0)) * QKV_N + E_ + h * D_;
        const size_t baseV = baseK + E_;

        __syncthreads();
        for (int i = 0; i < 64; i++) {
            Ks[i][tid] = qkv[baseK + (size_t)i * QKV_N + tid];
            Vs[i][tid] = qkv[baseV + (size_t)i * QKV_N + tid];
        }
        __syncthreads();

        float tmax = mi;
        for (int j = 0; j < 64; j++) {
            const float4* kr = (const float4*)Ks[j];
            float sx = 0.f, sy = 0.f, sz = 0.f, sw = 0.f;
            #pragma unroll
            for (int d4 = 0; d4 < 16; d4++) {
                const float4 k4 = kr[d4];
                sx += q[d4 * 4 + 0] * k4.x;
                sy += q[d4 * 4 + 1] * k4.y;
                sz += q[d4 * 4 + 2] * k4.z;
                sw += q[d4 * 4 + 3] * k4.w;
            }
            float s = (sx + sy) + (sz + sw);
            if (j0 + j > tq) s = -INFINITY;
            Ss[j][tid] = s;
            tmax = fmaxf(tmax, s);
        }

        const float mnew  = tmax;
        const float alpha = __expf(mi - mnew);
        li *= alpha;
        #pragma unroll
        for (int d = 0; d < 64; d++) o[d] *= alpha;

        for (int j = 0; j < 64; j++) {
            const float p = __expf(Ss[j][tid] - mnew);
            li += p;
            const float4* vr = (const float4*)Vs[j];
            #pragma unroll
            for (int d4 = 0; d4 < 16; d4++) {
                const float4 v4 = vr[d4];
                o[d4 * 4 + 0] += p * v4.x;
                o[d4 * 4 + 1] += p * v4.y;
                o[d4 * 4 + 2] += p * v4.z;
                o[d4 * 4 + 3] += p * v4.w;
            }
        }
        mi = mnew;
    }

    const float inv = 1.0f / li;
    const size_t rowO = ((size_t)(b * T_ + tq)) * E_ + h * D_;
    #pragma unroll
    for (int d = 0; d < 64; d++) out[rowO + d] = rna_tf32(o[d] * inv);
}

// ---------------------------------------------------------------------------
// Launch
// ---------------------------------------------------------------------------
extern "C" void kernel_launch(void* const* d_in, const int* in_sizes, int n_in,
                              void* d_out, int out_size)
{
    const float* x      = (const float*)d_in[0];
    const float* ln1_g  = (const float*)d_in[1];
    const float* ln1_b  = (const float*)d_in[2];
    const float* ln2_g  = (const float*)d_in[3];
    const float* ln2_b  = (const float*)d_in[4];
    const float* W_qkv  = (const float*)d_in[5];
    const float* b_qkv  = (const float*)d_in[6];
    const float* W_o    = (const float*)d_in[7];
    const float* b_o    = (const float*)d_in[8];
    const float* W_fc   = (const float*)d_in[9];
    const float* b_fc   = (const float*)d_in[10];
    const float* W_proj = (const float*)d_in[11];
    const float* b_proj = (const float*)d_in[12];
    float* out = (float*)d_out;

    float *p_ln, *p_qkv, *p_attn, *p_x1, *p_fc;
    float *p_wqkvP, *p_woP, *p_wfcP, *p_wprojP;
    cudaGetSymbolAddress((void**)&p_ln,     g_ln);
    cudaGetSymbolAddress((void**)&p_qkv,    g_qkv);
    cudaGetSymbolAddress((void**)&p_attn,   g_attn);
    cudaGetSymbolAddress((void**)&p_x1,     g_x1);
    cudaGetSymbolAddress((void**)&p_fc,     g_fc);
    cudaGetSymbolAddress((void**)&p_wqkvP,  g_wqkvP);
    cudaGetSymbolAddress((void**)&p_woP,    g_woP);
    cudaGetSymbolAddress((void**)&p_wfcP,   g_wfcP);
    cudaGetSymbolAddress((void**)&p_wprojP, g_wprojP);

    cudaFuncSetAttribute(gemm_mma_kernel<0>, cudaFuncAttributeMaxDynamicSharedMemorySize, GEMM_SMEM_BYTES);
    cudaFuncSetAttribute(gemm_mma_kernel<1>, cudaFuncAttributeMaxDynamicSharedMemorySize, GEMM_SMEM_BYTES);
    cudaFuncSetAttribute(gemm_mma_kernel<2>, cudaFuncAttributeMaxDynamicSharedMemorySize, GEMM_SMEM_BYTES);

    // weight packing (tf32-rounded, fragment-major)
    pack_weight_kernel<<<dim3(QKV_N / 128, E_ / 32), 256>>>(W_qkv,  p_wqkvP,  E_,   QKV_N);
    pack_weight_kernel<<<dim3(E_ / 128,    E_ / 32), 256>>>(W_o,    p_woP,    E_,   E_);
    pack_weight_kernel<<<dim3(FC_N / 128,  E_ / 32), 256>>>(W_fc,   p_wfcP,   E_,   FC_N);
    pack_weight_kernel<<<dim3(E_ / 128,  FC_N / 32), 256>>>(W_proj, p_wprojP, FC_N, E_);

    // 1. ln1 = LN(x)
    layernorm_kernel<<<M_, 256>>>(x, ln1_g, ln1_b, p_ln);
    // 2. qkv = ln1 @ W_qkv + b_qkv
    gemm_mma_kernel<0><<<dim3(QKV_N / 128, M_ / 128), 256, GEMM_SMEM_BYTES>>>(
        p_ln, p_wqkvP, b_qkv, nullptr, p_qkv, QKV_N, E_);
    // 3. attention
    flash_attn_kernel<<<dim3(T_ / 64, B_ * H_), 64>>>(p_qkv, p_attn);
    // 4. x1 = x + attn @ W_o + b_o
    gemm_mma_kernel<1><<<dim3(E_ / 128, M_ / 128), 256, GEMM_SMEM_BYTES>>>(
        p_attn, p_woP, b_o, x, p_x1, E_, E_);
    // 5. ln2 = LN(x1)
    layernorm_kernel<<<M_, 256>>>(p_x1, ln2_g, ln2_b, p_ln);
    // 6. fc = gelu(ln2 @ W_fc + b_fc)
    gemm_mma_kernel<2><<<dim3(FC_N / 128, M_ / 128), 256, GEMM_SMEM_BYTES>>>(
        p_ln, p_wfcP, b_fc, nullptr, p_fc, FC_N, E_);
    // 7. out = x1 + fc @ W_proj + b_proj
    gemm_mma_kernel<1><<<dim3(E_ / 128, M_ / 128), 256, GEMM_SMEM_BYTES>>>(
        p_fc, p_wprojP, b_proj, p_x1, out, E_, FC_N);
}

// round 5
// speedup vs baseline: 5.9658x; 1.9957x over previous
#include <cuda_runtime.h>
#include <cuda_bf16.h>
#include <math.h>
#include <stdint.h>

// ---------------------------------------------------------------------------
// Problem constants
// ---------------------------------------------------------------------------
#define B_  2
#define T_  2048
#define E_  1024
#define H_  16
#define D_  64
#define M_  (B_ * T_)          // 4096
#define QKV_N (3 * E_)         // 3072
#define FC_N  (4 * E_)         // 4096

// ---------------------------------------------------------------------------
// Scratch (device globals; allocations forbidden)
// ---------------------------------------------------------------------------
__device__ float g_ln  [(size_t)M_ * E_];
__device__ float g_qkv [(size_t)M_ * QKV_N];
__device__ float g_attn[(size_t)M_ * E_];
__device__ float g_x1  [(size_t)M_ * E_];
__device__ float g_fc  [(size_t)M_ * FC_N];
__device__ float g_wqkvP [(size_t)QKV_N * E_];
__device__ float g_woP   [(size_t)E_ * E_];
__device__ float g_wfcP  [(size_t)FC_N * E_];
__device__ float g_wprojP[(size_t)E_ * FC_N];

// ---------------------------------------------------------------------------
// Helpers
// ---------------------------------------------------------------------------
__device__ __forceinline__ uint32_t smem_u32(const void* p) {
    uint32_t a;
    asm("{ .reg .u64 t; cvta.to.shared.u64 t, %1; cvt.u32.u64 %0, t; }" : "=r"(a) : "l"(p));
    return a;
}
__device__ __forceinline__ float rna_tf32(float x) {
    uint32_t u;
    asm("cvt.rna.tf32.f32 %0, %1;" : "=r"(u) : "f"(x));
    return __uint_as_float(u);
}
#define CP_ASYNC16(dst, src) \
    asm volatile("cp.async.cg.shared.global [%0], [%1], 16;" :: "r"(dst), "l"(src) : "memory")
#define CP_COMMIT() asm volatile("cp.async.commit_group;" ::: "memory")

__device__ __forceinline__ void mma_tf32(float (&c)[4],
                                         float a0, float a1, float a2, float a3,
                                         float b0, float b1) {
    asm volatile(
        "mma.sync.aligned.m16n8k8.row.col.f32.tf32.tf32.f32 "
        "{%0,%1,%2,%3}, {%4,%5,%6,%7}, {%8,%9}, {%0,%1,%2,%3};"
        : "+f"(c[0]), "+f"(c[1]), "+f"(c[2]), "+f"(c[3])
        : "r"(__float_as_uint(a0)), "r"(__float_as_uint(a1)),
          "r"(__float_as_uint(a2)), "r"(__float_as_uint(a3)),
          "r"(__float_as_uint(b0)), "r"(__float_as_uint(b1)));
}

// ---------------------------------------------------------------------------
// Weight pack: W[K,N] row-major -> fragment-major tiles (see Round-4 comment)
// ---------------------------------------------------------------------------
__global__ void pack_weight_kernel(const float* __restrict__ W, float* __restrict__ Wp,
                                   int K, int N)
{
    const int nt = blockIdx.x, kt = blockIdx.y;
    const int t = threadIdx.x;                 // 256
    const size_t tile_base = ((size_t)nt * (K >> 5) + kt) * 4096;
    const int nn = t >> 1;                     // 0..127
    #pragma unroll
    for (int i = 0; i < 16; i++) {
        const int kk = (t & 1) * 16 + i;       // 0..31
        const int kb = kk >> 3, kr = kk & 7;
        const int nb = nn >> 4, nr = nn & 15;
        const int lane = (nr & 7) * 4 + (kr & 3);
        const int j = ((nr >> 3) << 1) + (kr >> 2);
        const int off = (kb * 8 + nb) * 128 + lane * 4 + j;
        const float v = W[(size_t)(kt * 32 + kk) * N + nt * 128 + nn];
        Wp[tile_base + off] = rna_tf32(v);
    }
}

// ---------------------------------------------------------------------------
// tf32 mma.sync GEMM (unchanged from Round 4)
// ---------------------------------------------------------------------------
#define SA_STRIDE 36
#define SA_BYTES  (128 * SA_STRIDE * 4)
#define SB_BYTES  16384
#define BUF_BYTES (SA_BYTES + SB_BYTES)
#define GEMM_SMEM_BYTES (2 * BUF_BYTES)

template<int EPI>
__global__ void __launch_bounds__(256, 2)
gemm_mma_kernel(const float* __restrict__ A, const float* __restrict__ Wp,
                const float* __restrict__ bias, const float* __restrict__ res,
                float* __restrict__ C, int N, int K)
{
    extern __shared__ char smem[];
    const uint32_t sbase = smem_u32(smem);
    const int tid  = threadIdx.x;
    const int wid  = tid >> 5;
    const int lane = tid & 31;
    const int g    = lane >> 2;
    const int tig  = lane & 3;
    const int wm   = (wid >> 1) * 32;
    const int wn   = (wid & 1) * 64;
    const int m0   = blockIdx.y * 128;
    const int n0   = blockIdx.x * 128;

    const int ntile = K >> 5;
    const size_t wtile0 = (size_t)blockIdx.x * ntile * 4096;

    const int am = tid >> 3;
    const int ac = tid & 7;

    float acc[2][8][4];
    #pragma unroll
    for (int mt = 0; mt < 2; mt++)
        #pragma unroll
        for (int q = 0; q < 8; q++)
            #pragma unroll
            for (int r = 0; r < 4; r++) acc[mt][q][r] = 0.f;

    auto load_tile = [&](int buf, int kt) {
        const uint32_t sA = sbase + buf * BUF_BYTES;
        const uint32_t sB = sA + SA_BYTES;
        const float* asrc = A + (size_t)(m0 + am) * K + kt * 32 + ac * 4;
        #pragma unroll
        for (int i = 0; i < 4; i++) {
            CP_ASYNC16(sA + (uint32_t)(am + i * 32) * (SA_STRIDE * 4) + ac * 16,
                       asrc + (size_t)i * 32 * K);
        }
        const float* bsrc = Wp + wtile0 + (size_t)kt * 4096 + tid * 4;
        #pragma unroll
        for (int i = 0; i < 4; i++) {
            CP_ASYNC16(sB + (tid + i * 256) * 16, bsrc + i * 1024);
        }
        CP_COMMIT();
    };

    load_tile(0, 0);

    for (int t = 0; t < ntile; t++) {
        const int cur = t & 1;
        if (t + 1 < ntile) {
            load_tile(cur ^ 1, t + 1);
            asm volatile("cp.async.wait_group 1;" ::: "memory");
        } else {
            asm volatile("cp.async.wait_group 0;" ::: "memory");
        }
        __syncthreads();

        const float* As = (const float*)(smem + cur * BUF_BYTES);
        const float* Bs = (const float*)(smem + cur * BUF_BYTES + SA_BYTES);

        #pragma unroll
        for (int kb = 0; kb < 4; kb++) {
            float a[2][4];
            #pragma unroll
            for (int mt = 0; mt < 2; mt++) {
                const int r = wm + mt * 16 + g;
                a[mt][0] = As[r * SA_STRIDE + kb * 8 + tig];
                a[mt][1] = As[(r + 8) * SA_STRIDE + kb * 8 + tig];
                a[mt][2] = As[r * SA_STRIDE + kb * 8 + tig + 4];
                a[mt][3] = As[(r + 8) * SA_STRIDE + kb * 8 + tig + 4];
            }
            float4 bq[4];
            #pragma unroll
            for (int q = 0; q < 4; q++) {
                const int s = kb * 8 + (wn >> 4) + q;
                bq[q] = *(const float4*)(Bs + s * 128 + lane * 4);
            }
            #pragma unroll
            for (int mt = 0; mt < 2; mt++) {
                #pragma unroll
                for (int q = 0; q < 4; q++) {
                    mma_tf32(acc[mt][2 * q + 0], a[mt][0], a[mt][1], a[mt][2], a[mt][3],
                             bq[q].x, bq[q].y);
                    mma_tf32(acc[mt][2 * q + 1], a[mt][0], a[mt][1], a[mt][2], a[mt][3],
                             bq[q].z, bq[q].w);
                }
            }
        }
        __syncthreads();
    }

    #pragma unroll
    for (int mt = 0; mt < 2; mt++) {
        const size_t r0 = (size_t)(m0 + wm + mt * 16 + g);
        #pragma unroll
        for (int q = 0; q < 8; q++) {
            const int col = n0 + wn + q * 8 + 2 * tig;
            const float2 bv = *(const float2*)(bias + col);
            #pragma unroll
            for (int hh = 0; hh < 2; hh++) {
                const size_t row = r0 + hh * 8;
                float vx = acc[mt][q][hh * 2 + 0] + bv.x;
                float vy = acc[mt][q][hh * 2 + 1] + bv.y;
                if (EPI == 1) {
                    const float2 r2 = *(const float2*)(res + row * N + col);
                    vx += r2.x; vy += r2.y;
                }
                if (EPI == 2) {
                    vx = rna_tf32(0.5f * vx * (1.0f + erff(vx * 0.70710678118654752f)));
                    vy = rna_tf32(0.5f * vy * (1.0f + erff(vy * 0.70710678118654752f)));
                }
                float2 o2; o2.x = vx; o2.y = vy;
                *(float2*)(C + row * N + col) = o2;
            }
        }
    }
}

// ---------------------------------------------------------------------------
// LayerNorm (output tf32-rounded)
// ---------------------------------------------------------------------------
__global__ void layernorm_kernel(const float* __restrict__ x,
                                 const float* __restrict__ gamma,
                                 const float* __restrict__ beta,
                                 float* __restrict__ out)
{
    const int row = blockIdx.x;
    const int tid = threadIdx.x;
    const float4 xv = ((const float4*)(x + (size_t)row * E_))[tid];

    float s  = xv.x + xv.y + xv.z + xv.w;
    float ss = xv.x*xv.x + xv.y*xv.y + xv.z*xv.z + xv.w*xv.w;
    #pragma unroll
    for (int o = 16; o > 0; o >>= 1) {
        s  += __shfl_xor_sync(0xffffffffu, s,  o);
        ss += __shfl_xor_sync(0xffffffffu, ss, o);
    }
    __shared__ float sbuf[8], ssbuf[8];
    const int wid = tid >> 5, lane = tid & 31;
    if (lane == 0) { sbuf[wid] = s; ssbuf[wid] = ss; }
    __syncthreads();
    float tot = 0.f, tots = 0.f;
    #pragma unroll
    for (int i = 0; i < 8; i++) { tot += sbuf[i]; tots += ssbuf[i]; }

    const float mean = tot * (1.0f / E_);
    const float var  = tots * (1.0f / E_) - mean * mean;
    const float r    = rsqrtf(var + 1e-5f);

    const float4 gv = ((const float4*)gamma)[tid];
    const float4 bv = ((const float4*)beta)[tid];
    float4 ov;
    ov.x = rna_tf32((xv.x - mean) * r * gv.x + bv.x);
    ov.y = rna_tf32((xv.y - mean) * r * gv.y + bv.y);
    ov.z = rna_tf32((xv.z - mean) * r * gv.z + bv.z);
    ov.w = rna_tf32((xv.w - mean) * r * gv.w + bv.w);
    ((float4*)(out + (size_t)row * E_))[tid] = ov;
}

// ---------------------------------------------------------------------------
// Flash attention via mma.sync tf32.
// Block = 64 queries x 1 head, 128 threads (4 warps x 16 queries).
// K-tile = 64 keys. Fragment conventions identical to gemm_mma_kernel.
//   smem: Ks[64][68], Vs[64][72], Ps[64][68] (Ps doubles as Q staging)
// ---------------------------------------------------------------------------
#define KS_STR 68
#define VS_STR 72
#define PS_STR 68
#define ATT_SMEM ((64 * KS_STR + 64 * VS_STR + 64 * PS_STR) * 4)   // 53248

__global__ void __launch_bounds__(128, 2)
attn_mma_kernel(const float* __restrict__ qkv, float* __restrict__ out)
{
    extern __shared__ float smf[];
    float* Ks = smf;
    float* Vs = smf + 64 * KS_STR;
    float* Ps = smf + 64 * KS_STR + 64 * VS_STR;
    const uint32_t sKs = smem_u32(Ks);
    const uint32_t sVs = smem_u32(Vs);

    const int bh  = blockIdx.y;
    const int b   = bh >> 4;
    const int h   = bh & 15;
    const int m0  = blockIdx.x * 64;
    const int tid = threadIdx.x;
    const int wid = tid >> 5;
    const int lane = tid & 31;
    const int g    = lane >> 2;
    const int tig  = lane & 3;
    const int qr   = wid * 16;               // warp's query-row base within tile
    const float NEG_INF = __int_as_float(0xff800000);

    // ---- stage Q tile into Ps (scaled, tf32-rounded), then load A-fragments ----
    const size_t baseQ = ((size_t)(b * T_ + m0)) * QKV_N + h * D_;
    #pragma unroll
    for (int i = 0; i < 8; i++) {
        const int idx = tid + i * 128;        // 0..1023
        const int r = idx >> 4, c4 = idx & 15;
        float4 v = *(const float4*)(qkv + baseQ + (size_t)r * QKV_N + c4 * 4);
        v.x = rna_tf32(v.x * 0.125f); v.y = rna_tf32(v.y * 0.125f);
        v.z = rna_tf32(v.z * 0.125f); v.w = rna_tf32(v.w * 0.125f);
        *(float4*)(Ps + r * PS_STR + c4 * 4) = v;
    }
    __syncthreads();

    float qf[8][4];
    #pragma unroll
    for (int kb = 0; kb < 8; kb++) {
        qf[kb][0] = Ps[(qr + g)     * PS_STR + kb * 8 + tig];
        qf[kb][1] = Ps[(qr + g + 8) * PS_STR + kb * 8 + tig];
        qf[kb][2] = Ps[(qr + g)     * PS_STR + kb * 8 + tig + 4];
        qf[kb][3] = Ps[(qr + g + 8) * PS_STR + kb * 8 + tig + 4];
    }

    float oacc[8][4];
    #pragma unroll
    for (int nb = 0; nb < 8; nb++)
        #pragma unroll
        for (int r = 0; r < 4; r++) oacc[nb][r] = 0.f;
    float mr0 = NEG_INF, mr1 = NEG_INF, l0 = 0.f, l1 = 0.f;

    const int tq0 = m0 + qr + g;
    const int tq1 = tq0 + 8;
    const int ntile = (m0 >> 6) + 1;

    for (int t = 0; t < ntile; t++) {
        const int j0 = t * 64;
        __syncthreads();   // everyone done with previous Ks/Vs (and Q staging on t=0)

        // load K and V tiles (64 x 64 each) via cp.async
        const size_t baseK = ((size_t)(b * T_ + j0)) * QKV_N + E_ + h * D_;
        #pragma unroll
        for (int i = 0; i < 8; i++) {
            const int idx = tid + i * 128;
            const int r = idx >> 4, c4 = idx & 15;
            const float* src = qkv + baseK + (size_t)r * QKV_N + c4 * 4;
            CP_ASYNC16(sKs + (uint32_t)(r * KS_STR + c4 * 4) * 4, src);
            CP_ASYNC16(sVs + (uint32_t)(r * VS_STR + c4 * 4) * 4, src + E_);
        }
        CP_COMMIT();
        asm volatile("cp.async.wait_group 0;" ::: "memory");
        __syncthreads();

        // ---- QK^T: scores S[16 x 64] per warp ----
        float sc[8][4];
        #pragma unroll
        for (int jb = 0; jb < 8; jb++) {
            sc[jb][0] = sc[jb][1] = sc[jb][2] = sc[jb][3] = 0.f;
            #pragma unroll
            for (int kb = 0; kb < 8; kb++) {
                const float b0 = Ks[(jb * 8 + g) * KS_STR + kb * 8 + tig];
                const float b1 = Ks[(jb * 8 + g) * KS_STR + kb * 8 + tig + 4];
                mma_tf32(sc[jb], qf[kb][0], qf[kb][1], qf[kb][2], qf[kb][3], b0, b1);
            }
        }

        // ---- causal mask + row max ----
        float tm0 = NEG_INF, tm1 = NEG_INF;
        #pragma unroll
        for (int jb = 0; jb < 8; jb++) {
            const int c0 = j0 + jb * 8 + 2 * tig;
            const int c1 = c0 + 1;
            if (c0 > tq0) sc[jb][0] = NEG_INF;
            if (c1 > tq0) sc[jb][1] = NEG_INF;
            if (c0 > tq1) sc[jb][2] = NEG_INF;
            if (c1 > tq1) sc[jb][3] = NEG_INF;
            tm0 = fmaxf(tm0, fmaxf(sc[jb][0], sc[jb][1]));
            tm1 = fmaxf(tm1, fmaxf(sc[jb][2], sc[jb][3]));
        }
        tm0 = fmaxf(tm0, __shfl_xor_sync(0xffffffffu, tm0, 1));
        tm0 = fmaxf(tm0, __shfl_xor_sync(0xffffffffu, tm0, 2));
        tm1 = fmaxf(tm1, __shfl_xor_sync(0xffffffffu, tm1, 1));
        tm1 = fmaxf(tm1, __shfl_xor_sync(0xffffffffu, tm1, 2));

        const float mn0 = fmaxf(mr0, tm0);
        const float mn1 = fmaxf(mr1, tm1);
        const float a0 = __expf(mr0 - mn0);
        const float a1 = __expf(mr1 - mn1);
        l0 *= a0; l1 *= a1;
        #pragma unroll
        for (int nb = 0; nb < 8; nb++) {
            oacc[nb][0] *= a0; oacc[nb][1] *= a0;
            oacc[nb][2] *= a1; oacc[nb][3] *= a1;
        }

        // ---- P = exp(S - m), rna-rounded; store to Ps; accumulate l ----
        float ps0 = 0.f, ps1 = 0.f;
        #pragma unroll
        for (int jb = 0; jb < 8; jb++) {
            const float p0 = rna_tf32(__expf(sc[jb][0] - mn0));
            const float p1 = rna_tf32(__expf(sc[jb][1] - mn0));
            const float p2 = rna_tf32(__expf(sc[jb][2] - mn1));
            const float p3 = rna_tf32(__expf(sc[jb][3] - mn1));
            ps0 += p0 + p1; ps1 += p2 + p3;
            float2 lo; lo.x = p0; lo.y = p1;
            float2 hi; hi.x = p2; hi.y = p3;
            *(float2*)(Ps + (qr + g)     * PS_STR + jb * 8 + 2 * tig) = lo;
            *(float2*)(Ps + (qr + g + 8) * PS_STR + jb * 8 + 2 * tig) = hi;
        }
        ps0 += __shfl_xor_sync(0xffffffffu, ps0, 1);
        ps0 += __shfl_xor_sync(0xffffffffu, ps0, 2);
        ps1 += __shfl_xor_sync(0xffffffffu, ps1, 1);
        ps1 += __shfl_xor_sync(0xffffffffu, ps1, 2);
        l0 += ps0; l1 += ps1;
        mr0 = mn0; mr1 = mn1;
        __syncwarp();   // Ps rows are warp-private; order STS -> LDS within warp

        // ---- PV: A = P fragments, B = V ----
        float af[8][4];
        #pragma unroll
        for (int kb = 0; kb < 8; kb++) {
            af[kb][0] = Ps[(qr + g)     * PS_STR + kb * 8 + tig];
            af[kb][1] = Ps[(qr + g + 8) * PS_STR + kb * 8 + tig];
            af[kb][2] = Ps[(qr + g)     * PS_STR + kb * 8 + tig + 4];
            af[kb][3] = Ps[(qr + g + 8) * PS_STR + kb * 8 + tig + 4];
        }
        #pragma unroll
        for (int nb = 0; nb < 8; nb++) {
            #pragma unroll
            for (int kb = 0; kb < 8; kb++) {
                const float b0 = Vs[(kb * 8 + tig)     * VS_STR + nb * 8 + g];
                const float b1 = Vs[(kb * 8 + tig + 4) * VS_STR + nb * 8 + g];
                mma_tf32(oacc[nb], af[kb][0], af[kb][1], af[kb][2], af[kb][3], b0, b1);
            }
        }
    }

    // ---- epilogue: normalize, tf32-round (feeds W_o GEMM), store ----
    const float inv0 = 1.0f / l0;
    const float inv1 = 1.0f / l1;
    const size_t row0 = (size_t)(b * T_ + tq0);
    const size_t row1 = (size_t)(b * T_ + tq1);
    #pragma unroll
    for (int nb = 0; nb < 8; nb++) {
        const int col = h * D_ + nb * 8 + 2 * tig;
        float2 lo, hi;
        lo.x = rna_tf32(oacc[nb][0] * inv0); lo.y = rna_tf32(oacc[nb][1] * inv0);
        hi.x = rna_tf32(oacc[nb][2] * inv1); hi.y = rna_tf32(oacc[nb][3] * inv1);
        *(float2*)(out + row0 * E_ + col) = lo;
        *(float2*)(out + row1 * E_ + col) = hi;
    }
}

// ---------------------------------------------------------------------------
// Launch
// ---------------------------------------------------------------------------
extern "C" void kernel_launch(void* const* d_in, const int* in_sizes, int n_in,
                              void* d_out, int out_size)
{
    const float* x      = (const float*)d_in[0];
    const float* ln1_g  = (const float*)d_in[1];
    const float* ln1_b  = (const float*)d_in[2];
    const float* ln2_g  = (const float*)d_in[3];
    const float* ln2_b  = (const float*)d_in[4];
    const float* W_qkv  = (const float*)d_in[5];
    const float* b_qkv  = (const float*)d_in[6];
    const float* W_o    = (const float*)d_in[7];
    const float* b_o    = (const float*)d_in[8];
    const float* W_fc   = (const float*)d_in[9];
    const float* b_fc   = (const float*)d_in[10];
    const float* W_proj = (const float*)d_in[11];
    const float* b_proj = (const float*)d_in[12];
    float* out = (float*)d_out;

    float *p_ln, *p_qkv, *p_attn, *p_x1, *p_fc;
    float *p_wqkvP, *p_woP, *p_wfcP, *p_wprojP;
    cudaGetSymbolAddress((void**)&p_ln,     g_ln);
    cudaGetSymbolAddress((void**)&p_qkv,    g_qkv);
    cudaGetSymbolAddress((void**)&p_attn,   g_attn);
    cudaGetSymbolAddress((void**)&p_x1,     g_x1);
    cudaGetSymbolAddress((void**)&p_fc,     g_fc);
    cudaGetSymbolAddress((void**)&p_wqkvP,  g_wqkvP);
    cudaGetSymbolAddress((void**)&p_woP,    g_woP);
    cudaGetSymbolAddress((void**)&p_wfcP,   g_wfcP);
    cudaGetSymbolAddress((void**)&p_wprojP, g_wprojP);

    cudaFuncSetAttribute(gemm_mma_kernel<0>, cudaFuncAttributeMaxDynamicSharedMemorySize, GEMM_SMEM_BYTES);
    cudaFuncSetAttribute(gemm_mma_kernel<1>, cudaFuncAttributeMaxDynamicSharedMemorySize, GEMM_SMEM_BYTES);
    cudaFuncSetAttribute(gemm_mma_kernel<2>, cudaFuncAttributeMaxDynamicSharedMemorySize, GEMM_SMEM_BYTES);
    cudaFuncSetAttribute(attn_mma_kernel,    cudaFuncAttributeMaxDynamicSharedMemorySize, ATT_SMEM);

    // weight packing (tf32-rounded, fragment-major)
    pack_weight_kernel<<<dim3(QKV_N / 128, E_ / 32), 256>>>(W_qkv,  p_wqkvP,  E_,   QKV_N);
    pack_weight_kernel<<<dim3(E_ / 128,    E_ / 32), 256>>>(W_o,    p_woP,    E_,   E_);
    pack_weight_kernel<<<dim3(FC_N / 128,  E_ / 32), 256>>>(W_fc,   p_wfcP,   E_,   FC_N);
    pack_weight_kernel<<<dim3(E_ / 128,  FC_N / 32), 256>>>(W_proj, p_wprojP, FC_N, E_);

    // 1. ln1 = LN(x)
    layernorm_kernel<<<M_, 256>>>(x, ln1_g, ln1_b, p_ln);
    // 2. qkv = ln1 @ W_qkv + b_qkv
    gemm_mma_kernel<0><<<dim3(QKV_N / 128, M_ / 128), 256, GEMM_SMEM_BYTES>>>(
        p_ln, p_wqkvP, b_qkv, nullptr, p_qkv, QKV_N, E_);
    // 3. attention (mma.sync tf32 flash)
    attn_mma_kernel<<<dim3(T_ / 64, B_ * H_), 128, ATT_SMEM>>>(p_qkv, p_attn);
    // 4. x1 = x + attn @ W_o + b_o
    gemm_mma_kernel<1><<<dim3(E_ / 128, M_ / 128), 256, GEMM_SMEM_BYTES>>>(
        p_attn, p_woP, b_o, x, p_x1, E_, E_);
    // 5. ln2 = LN(x1)
    layernorm_kernel<<<M_, 256>>>(p_x1, ln2_g, ln2_b, p_ln);
    // 6. fc = gelu(ln2 @ W_fc + b_fc)
    gemm_mma_kernel<2><<<dim3(FC_N / 128, M_ / 128), 256, GEMM_SMEM_BYTES>>>(
        p_ln, p_wfcP, b_fc, nullptr, p_fc, FC_N, E_);
    // 7. out = x1 + fc @ W_proj + b_proj
    gemm_mma_kernel<1><<<dim3(E_ / 128, M_ / 128), 256, GEMM_SMEM_BYTES>>>(
        p_fc, p_wprojP, b_proj, p_x1, out, E_, FC_N);
}

// round 6
// speedup vs baseline: 6.1415x; 1.0294x over previous
#include <cuda_runtime.h>
#include <cuda_bf16.h>
#include <math.h>
#include <stdint.h>

// ---------------------------------------------------------------------------
// Problem constants
// ---------------------------------------------------------------------------
#define B_  2
#define T_  2048
#define E_  1024
#define H_  16
#define D_  64
#define M_  (B_ * T_)          // 4096
#define QKV_N (3 * E_)         // 3072
#define FC_N  (4 * E_)         // 4096

// ---------------------------------------------------------------------------
// Scratch (device globals; allocations forbidden)
// ---------------------------------------------------------------------------
__device__ float g_ln  [(size_t)M_ * E_];
__device__ float g_qkv [(size_t)M_ * QKV_N];
__device__ float g_attn[(size_t)M_ * E_];
__device__ float g_x1  [(size_t)M_ * E_];
__device__ float g_fc  [(size_t)M_ * FC_N];
__device__ float g_wqkvP [(size_t)QKV_N * E_];
__device__ float g_woP   [(size_t)E_ * E_];
__device__ float g_wfcP  [(size_t)FC_N * E_];
__device__ float g_wprojP[(size_t)E_ * FC_N];

// ---------------------------------------------------------------------------
// Helpers
// ---------------------------------------------------------------------------
__device__ __forceinline__ uint32_t smem_u32(const void* p) {
    uint32_t a;
    asm("{ .reg .u64 t; cvta.to.shared.u64 t, %1; cvt.u32.u64 %0, t; }" : "=r"(a) : "l"(p));
    return a;
}
__device__ __forceinline__ float rna_tf32(float x) {
    uint32_t u;
    asm("cvt.rna.tf32.f32 %0, %1;" : "=r"(u) : "f"(x));
    return __uint_as_float(u);
}
#define CP_ASYNC16(dst, src) \
    asm volatile("cp.async.cg.shared.global [%0], [%1], 16;" :: "r"(dst), "l"(src) : "memory")
#define CP_COMMIT() asm volatile("cp.async.commit_group;" ::: "memory")

__device__ __forceinline__ void mma_tf32(float (&c)[4],
                                         float a0, float a1, float a2, float a3,
                                         float b0, float b1) {
    asm volatile(
        "mma.sync.aligned.m16n8k8.row.col.f32.tf32.tf32.f32 "
        "{%0,%1,%2,%3}, {%4,%5,%6,%7}, {%8,%9}, {%0,%1,%2,%3};"
        : "+f"(c[0]), "+f"(c[1]), "+f"(c[2]), "+f"(c[3])
        : "r"(__float_as_uint(a0)), "r"(__float_as_uint(a1)),
          "r"(__float_as_uint(a2)), "r"(__float_as_uint(a3)),
          "r"(__float_as_uint(b0)), "r"(__float_as_uint(b1)));
}

// ---------------------------------------------------------------------------
// Weight pack (coalesced writes, inverted mapping).
// Output layout identical to Round-4 pack: tile = 128n x 32k, superfrag
// s = kb*8+nb holds 128 floats, float4 of lane l at j gives
//   nr = (j>>1)*8 + (l>>2), kr = (j&1)*4 + (l&3), n = nb*16+nr, k = kb*8+kr.
// Thread writes float4s at o4 = tid + i*256; reads gathered from W (L2 hit).
// ---------------------------------------------------------------------------
__global__ void pack_weight_kernel(const float* __restrict__ W, float* __restrict__ Wp,
                                   int K, int N)
{
    const int nt = blockIdx.x, kt = blockIdx.y;
    const int tid = threadIdx.x;               // 256
    float4* dst = (float4*)(Wp + ((size_t)nt * (K >> 5) + kt) * 4096);
    const float* src = W + (size_t)(kt * 32) * N + nt * 128;
    #pragma unroll
    for (int i = 0; i < 4; i++) {
        const int o4 = tid + i * 256;          // 0..1023
        const int kb = o4 >> 8;
        const int nb = (o4 >> 5) & 7;
        const int g  = (o4 & 31) >> 2;
        const int tig = o4 & 3;
        float4 v;
        v.x = rna_tf32(src[(size_t)(kb * 8 + tig)     * N + nb * 16 + g]);
        v.y = rna_tf32(src[(size_t)(kb * 8 + tig + 4) * N + nb * 16 + g]);
        v.z = rna_tf32(src[(size_t)(kb * 8 + tig)     * N + nb * 16 + g + 8]);
        v.w = rna_tf32(src[(size_t)(kb * 8 + tig + 4) * N + nb * 16 + g + 8]);
        dst[o4] = v;
    }
}

// ---------------------------------------------------------------------------
// tf32 mma.sync GEMM: C[M,N] = A[M,K] @ W + bias (+res | gelu)
// BM=BN=128, BK=32, 128 threads, 4 warps (2M x 2N), warp tile 64x64.
// cp.async double-buffered. EPI: 0=bias, 1=bias+res, 2=bias+GELU(->tf32)
// ---------------------------------------------------------------------------
#define SA_STRIDE 36
#define SA_BYTES  (128 * SA_STRIDE * 4)    // 18432
#define SB_BYTES  16384
#define BUF_BYTES (SA_BYTES + SB_BYTES)    // 34816
#define GEMM_SMEM_BYTES (2 * BUF_BYTES)    // 69632

template<int EPI>
__global__ void __launch_bounds__(128, 2)
gemm_mma_kernel(const float* __restrict__ A, const float* __restrict__ Wp,
                const float* __restrict__ bias, const float* __restrict__ res,
                float* __restrict__ C, int N, int K)
{
    extern __shared__ char smem[];
    const uint32_t sbase = smem_u32(smem);
    const int tid  = threadIdx.x;
    const int wid  = tid >> 5;
    const int lane = tid & 31;
    const int g    = lane >> 2;
    const int tig  = lane & 3;
    const int wm   = (wid >> 1) * 64;      // warp M offset: 0 / 64
    const int wn   = (wid & 1) * 64;       // warp N offset: 0 / 64
    const int m0   = blockIdx.y * 128;
    const int n0   = blockIdx.x * 128;

    const int ntile = K >> 5;
    const size_t wtile0 = (size_t)blockIdx.x * ntile * 4096;

    // A copy: 1024 float4 chunks, 8 per thread
    const int am = tid >> 3;               // 0..15 (+16*i)
    const int ac = tid & 7;

    float acc[4][8][4];
    #pragma unroll
    for (int mt = 0; mt < 4; mt++)
        #pragma unroll
        for (int q = 0; q < 8; q++)
            #pragma unroll
            for (int r = 0; r < 4; r++) acc[mt][q][r] = 0.f;

    auto load_tile = [&](int buf, int kt) {
        const uint32_t sA = sbase + buf * BUF_BYTES;
        const uint32_t sB = sA + SA_BYTES;
        const float* asrc = A + (size_t)(m0 + am) * K + kt * 32 + ac * 4;
        #pragma unroll
        for (int i = 0; i < 8; i++) {
            CP_ASYNC16(sA + (uint32_t)(am + i * 16) * (SA_STRIDE * 4) + ac * 16,
                       asrc + (size_t)i * 16 * K);
        }
        const float* bsrc = Wp + wtile0 + (size_t)kt * 4096 + tid * 4;
        #pragma unroll
        for (int i = 0; i < 8; i++) {
            CP_ASYNC16(sB + (uint32_t)(tid + i * 128) * 16, bsrc + i * 512);
        }
        CP_COMMIT();
    };

    load_tile(0, 0);

    for (int t = 0; t < ntile; t++) {
        const int cur = t & 1;
        if (t + 1 < ntile) {
            load_tile(cur ^ 1, t + 1);
            asm volatile("cp.async.wait_group 1;" ::: "memory");
        } else {
            asm volatile("cp.async.wait_group 0;" ::: "memory");
        }
        __syncthreads();

        const float* As = (const float*)(smem + cur * BUF_BYTES);
        const float* Bs = (const float*)(smem + cur * BUF_BYTES + SA_BYTES);

        #pragma unroll
        for (int kb = 0; kb < 4; kb++) {
            float a[4][4];
            #pragma unroll
            for (int mt = 0; mt < 4; mt++) {
                const int r = wm + mt * 16 + g;
                a[mt][0] = As[r * SA_STRIDE + kb * 8 + tig];
                a[mt][1] = As[(r + 8) * SA_STRIDE + kb * 8 + tig];
                a[mt][2] = As[r * SA_STRIDE + kb * 8 + tig + 4];
                a[mt][3] = As[(r + 8) * SA_STRIDE + kb * 8 + tig + 4];
            }
            float4 bq[4];
            #pragma unroll
            for (int q = 0; q < 4; q++) {
                const int s = kb * 8 + (wn >> 4) + q;
                bq[q] = *(const float4*)(Bs + s * 128 + lane * 4);
            }
            #pragma unroll
            for (int mt = 0; mt < 4; mt++) {
                #pragma unroll
                for (int q = 0; q < 4; q++) {
                    mma_tf32(acc[mt][2 * q + 0], a[mt][0], a[mt][1], a[mt][2], a[mt][3],
                             bq[q].x, bq[q].y);
                    mma_tf32(acc[mt][2 * q + 1], a[mt][0], a[mt][1], a[mt][2], a[mt][3],
                             bq[q].z, bq[q].w);
                }
            }
        }
        __syncthreads();
    }

    #pragma unroll
    for (int mt = 0; mt < 4; mt++) {
        const size_t r0 = (size_t)(m0 + wm + mt * 16 + g);
        #pragma unroll
        for (int q = 0; q < 8; q++) {
            const int col = n0 + wn + q * 8 + 2 * tig;
            const float2 bv = *(const float2*)(bias + col);
            #pragma unroll
            for (int hh = 0; hh < 2; hh++) {
                const size_t row = r0 + hh * 8;
                float vx = acc[mt][q][hh * 2 + 0] + bv.x;
                float vy = acc[mt][q][hh * 2 + 1] + bv.y;
                if (EPI == 1) {
                    const float2 r2 = *(const float2*)(res + row * N + col);
                    vx += r2.x; vy += r2.y;
                }
                if (EPI == 2) {
                    vx = rna_tf32(0.5f * vx * (1.0f + erff(vx * 0.70710678118654752f)));
                    vy = rna_tf32(0.5f * vy * (1.0f + erff(vy * 0.70710678118654752f)));
                }
                float2 o2; o2.x = vx; o2.y = vy;
                *(float2*)(C + row * N + col) = o2;
            }
        }
    }
}

// ---------------------------------------------------------------------------
// LayerNorm (output tf32-rounded)
// ---------------------------------------------------------------------------
__global__ void layernorm_kernel(const float* __restrict__ x,
                                 const float* __restrict__ gamma,
                                 const float* __restrict__ beta,
                                 float* __restrict__ out)
{
    const int row = blockIdx.x;
    const int tid = threadIdx.x;
    const float4 xv = ((const float4*)(x + (size_t)row * E_))[tid];

    float s  = xv.x + xv.y + xv.z + xv.w;
    float ss = xv.x*xv.x + xv.y*xv.y + xv.z*xv.z + xv.w*xv.w;
    #pragma unroll
    for (int o = 16; o > 0; o >>= 1) {
        s  += __shfl_xor_sync(0xffffffffu, s,  o);
        ss += __shfl_xor_sync(0xffffffffu, ss, o);
    }
    __shared__ float sbuf[8], ssbuf[8];
    const int wid = tid >> 5, lane = tid & 31;
    if (lane == 0) { sbuf[wid] = s; ssbuf[wid] = ss; }
    __syncthreads();
    float tot = 0.f, tots = 0.f;
    #pragma unroll
    for (int i = 0; i < 8; i++) { tot += sbuf[i]; tots += ssbuf[i]; }

    const float mean = tot * (1.0f / E_);
    const float var  = tots * (1.0f / E_) - mean * mean;
    const float r    = rsqrtf(var + 1e-5f);

    const float4 gv = ((const float4*)gamma)[tid];
    const float4 bv = ((const float4*)beta)[tid];
    float4 ov;
    ov.x = rna_tf32((xv.x - mean) * r * gv.x + bv.x);
    ov.y = rna_tf32((xv.y - mean) * r * gv.y + bv.y);
    ov.z = rna_tf32((xv.z - mean) * r * gv.z + bv.z);
    ov.w = rna_tf32((xv.w - mean) * r * gv.w + bv.w);
    ((float4*)(out + (size_t)row * E_))[tid] = ov;
}

// ---------------------------------------------------------------------------
// Flash attention via mma.sync tf32 (unchanged from Round 5)
// ---------------------------------------------------------------------------
#define KS_STR 68
#define VS_STR 72
#define PS_STR 68
#define ATT_SMEM ((64 * KS_STR + 64 * VS_STR + 64 * PS_STR) * 4)   // 53248

__global__ void __launch_bounds__(128, 2)
attn_mma_kernel(const float* __restrict__ qkv, float* __restrict__ out)
{
    extern __shared__ float smf[];
    float* Ks = smf;
    float* Vs = smf + 64 * KS_STR;
    float* Ps = smf + 64 * KS_STR + 64 * VS_STR;
    const uint32_t sKs = smem_u32(Ks);
    const uint32_t sVs = smem_u32(Vs);

    const int bh  = blockIdx.y;
    const int b   = bh >> 4;
    const int h   = bh & 15;
    const int m0  = blockIdx.x * 64;
    const int tid = threadIdx.x;
    const int wid = tid >> 5;
    const int lane = tid & 31;
    const int g    = lane >> 2;
    const int tig  = lane & 3;
    const int qr   = wid * 16;
    const float NEG_INF = __int_as_float(0xff800000);

    const size_t baseQ = ((size_t)(b * T_ + m0)) * QKV_N + h * D_;
    #pragma unroll
    for (int i = 0; i < 8; i++) {
        const int idx = tid + i * 128;
        const int r = idx >> 4, c4 = idx & 15;
        float4 v = *(const float4*)(qkv + baseQ + (size_t)r * QKV_N + c4 * 4);
        v.x = rna_tf32(v.x * 0.125f); v.y = rna_tf32(v.y * 0.125f);
        v.z = rna_tf32(v.z * 0.125f); v.w = rna_tf32(v.w * 0.125f);
        *(float4*)(Ps + r * PS_STR + c4 * 4) = v;
    }
    __syncthreads();

    float qf[8][4];
    #pragma unroll
    for (int kb = 0; kb < 8; kb++) {
        qf[kb][0] = Ps[(qr + g)     * PS_STR + kb * 8 + tig];
        qf[kb][1] = Ps[(qr + g + 8) * PS_STR + kb * 8 + tig];
        qf[kb][2] = Ps[(qr + g)     * PS_STR + kb * 8 + tig + 4];
        qf[kb][3] = Ps[(qr + g + 8) * PS_STR + kb * 8 + tig + 4];
    }

    float oacc[8][4];
    #pragma unroll
    for (int nb = 0; nb < 8; nb++)
        #pragma unroll
        for (int r = 0; r < 4; r++) oacc[nb][r] = 0.f;
    float mr0 = NEG_INF, mr1 = NEG_INF, l0 = 0.f, l1 = 0.f;

    const int tq0 = m0 + qr + g;
    const int tq1 = tq0 + 8;
    const int ntile = (m0 >> 6) + 1;

    for (int t = 0; t < ntile; t++) {
        const int j0 = t * 64;
        __syncthreads();

        const size_t baseK = ((size_t)(b * T_ + j0)) * QKV_N + E_ + h * D_;
        #pragma unroll
        for (int i = 0; i < 8; i++) {
            const int idx = tid + i * 128;
            const int r = idx >> 4, c4 = idx & 15;
            const float* src = qkv + baseK + (size_t)r * QKV_N + c4 * 4;
            CP_ASYNC16(sKs + (uint32_t)(r * KS_STR + c4 * 4) * 4, src);
            CP_ASYNC16(sVs + (uint32_t)(r * VS_STR + c4 * 4) * 4, src + E_);
        }
        CP_COMMIT();
        asm volatile("cp.async.wait_group 0;" ::: "memory");
        __syncthreads();

        float sc[8][4];
        #pragma unroll
        for (int jb = 0; jb < 8; jb++) {
            sc[jb][0] = sc[jb][1] = sc[jb][2] = sc[jb][3] = 0.f;
            #pragma unroll
            for (int kb = 0; kb < 8; kb++) {
                const float b0 = Ks[(jb * 8 + g) * KS_STR + kb * 8 + tig];
                const float b1 = Ks[(jb * 8 + g) * KS_STR + kb * 8 + tig + 4];
                mma_tf32(sc[jb], qf[kb][0], qf[kb][1], qf[kb][2], qf[kb][3], b0, b1);
            }
        }

        float tm0 = NEG_INF, tm1 = NEG_INF;
        #pragma unroll
        for (int jb = 0; jb < 8; jb++) {
            const int c0 = j0 + jb * 8 + 2 * tig;
            const int c1 = c0 + 1;
            if (c0 > tq0) sc[jb][0] = NEG_INF;
            if (c1 > tq0) sc[jb][1] = NEG_INF;
            if (c0 > tq1) sc[jb][2] = NEG_INF;
            if (c1 > tq1) sc[jb][3] = NEG_INF;
            tm0 = fmaxf(tm0, fmaxf(sc[jb][0], sc[jb][1]));
            tm1 = fmaxf(tm1, fmaxf(sc[jb][2], sc[jb][3]));
        }
        tm0 = fmaxf(tm0, __shfl_xor_sync(0xffffffffu, tm0, 1));
        tm0 = fmaxf(tm0, __shfl_xor_sync(0xffffffffu, tm0, 2));
        tm1 = fmaxf(tm1, __shfl_xor_sync(0xffffffffu, tm1, 1));
        tm1 = fmaxf(tm1, __shfl_xor_sync(0xffffffffu, tm1, 2));

        const float mn0 = fmaxf(mr0, tm0);
        const float mn1 = fmaxf(mr1, tm1);
        const float a0 = __expf(mr0 - mn0);
        const float a1 = __expf(mr1 - mn1);
        l0 *= a0; l1 *= a1;
        #pragma unroll
        for (int nb = 0; nb < 8; nb++) {
            oacc[nb][0] *= a0; oacc[nb][1] *= a0;
            oacc[nb][2] *= a1; oacc[nb][3] *= a1;
        }

        float ps0 = 0.f, ps1 = 0.f;
        #pragma unroll
        for (int jb = 0; jb < 8; jb++) {
            const float p0 = rna_tf32(__expf(sc[jb][0] - mn0));
            const float p1 = rna_tf32(__expf(sc[jb][1] - mn0));
            const float p2 = rna_tf32(__expf(sc[jb][2] - mn1));
            const float p3 = rna_tf32(__expf(sc[jb][3] - mn1));
            ps0 += p0 + p1; ps1 += p2 + p3;
            float2 lo; lo.x = p0; lo.y = p1;
            float2 hi; hi.x = p2; hi.y = p3;
            *(float2*)(Ps + (qr + g)     * PS_STR + jb * 8 + 2 * tig) = lo;
            *(float2*)(Ps + (qr + g + 8) * PS_STR + jb * 8 + 2 * tig) = hi;
        }
        ps0 += __shfl_xor_sync(0xffffffffu, ps0, 1);
        ps0 += __shfl_xor_sync(0xffffffffu, ps0, 2);
        ps1 += __shfl_xor_sync(0xffffffffu, ps1, 1);
        ps1 += __shfl_xor_sync(0xffffffffu, ps1, 2);
        l0 += ps0; l1 += ps1;
        mr0 = mn0; mr1 = mn1;
        __syncwarp();

        float af[8][4];
        #pragma unroll
        for (int kb = 0; kb < 8; kb++) {
            af[kb][0] = Ps[(qr + g)     * PS_STR + kb * 8 + tig];
            af[kb][1] = Ps[(qr + g + 8) * PS_STR + kb * 8 + tig];
            af[kb][2] = Ps[(qr + g)     * PS_STR + kb * 8 + tig + 4];
            af[kb][3] = Ps[(qr + g + 8) * PS_STR + kb * 8 + tig + 4];
        }
        #pragma unroll
        for (int nb = 0; nb < 8; nb++) {
            #pragma unroll
            for (int kb = 0; kb < 8; kb++) {
                const float b0 = Vs[(kb * 8 + tig)     * VS_STR + nb * 8 + g];
                const float b1 = Vs[(kb * 8 + tig + 4) * VS_STR + nb * 8 + g];
                mma_tf32(oacc[nb], af[kb][0], af[kb][1], af[kb][2], af[kb][3], b0, b1);
            }
        }
    }

    const float inv0 = 1.0f / l0;
    const float inv1 = 1.0f / l1;
    const size_t row0 = (size_t)(b * T_ + tq0);
    const size_t row1 = (size_t)(b * T_ + tq1);
    #pragma unroll
    for (int nb = 0; nb < 8; nb++) {
        const int col = h * D_ + nb * 8 + 2 * tig;
        float2 lo, hi;
        lo.x = rna_tf32(oacc[nb][0] * inv0); lo.y = rna_tf32(oacc[nb][1] * inv0);
        hi.x = rna_tf32(oacc[nb][2] * inv1); hi.y = rna_tf32(oacc[nb][3] * inv1);
        *(float2*)(out + row0 * E_ + col) = lo;
        *(float2*)(out + row1 * E_ + col) = hi;
    }
}

// ---------------------------------------------------------------------------
// Launch
// ---------------------------------------------------------------------------
extern "C" void kernel_launch(void* const* d_in, const int* in_sizes, int n_in,
                              void* d_out, int out_size)
{
    const float* x      = (const float*)d_in[0];
    const float* ln1_g  = (const float*)d_in[1];
    const float* ln1_b  = (const float*)d_in[2];
    const float* ln2_g  = (const float*)d_in[3];
    const float* ln2_b  = (const float*)d_in[4];
    const float* W_qkv  = (const float*)d_in[5];
    const float* b_qkv  = (const float*)d_in[6];
    const float* W_o    = (const float*)d_in[7];
    const float* b_o    = (const float*)d_in[8];
    const float* W_fc   = (const float*)d_in[9];
    const float* b_fc   = (const float*)d_in[10];
    const float* W_proj = (const float*)d_in[11];
    const float* b_proj = (const float*)d_in[12];
    float* out = (float*)d_out;

    float *p_ln, *p_qkv, *p_attn, *p_x1, *p_fc;
    float *p_wqkvP, *p_woP, *p_wfcP, *p_wprojP;
    cudaGetSymbolAddress((void**)&p_ln,     g_ln);
    cudaGetSymbolAddress((void**)&p_qkv,    g_qkv);
    cudaGetSymbolAddress((void**)&p_attn,   g_attn);
    cudaGetSymbolAddress((void**)&p_x1,     g_x1);
    cudaGetSymbolAddress((void**)&p_fc,     g_fc);
    cudaGetSymbolAddress((void**)&p_wqkvP,  g_wqkvP);
    cudaGetSymbolAddress((void**)&p_woP,    g_woP);
    cudaGetSymbolAddress((void**)&p_wfcP,   g_wfcP);
    cudaGetSymbolAddress((void**)&p_wprojP, g_wprojP);

    cudaFuncSetAttribute(gemm_mma_kernel<0>, cudaFuncAttributeMaxDynamicSharedMemorySize, GEMM_SMEM_BYTES);
    cudaFuncSetAttribute(gemm_mma_kernel<1>, cudaFuncAttributeMaxDynamicSharedMemorySize, GEMM_SMEM_BYTES);
    cudaFuncSetAttribute(gemm_mma_kernel<2>, cudaFuncAttributeMaxDynamicSharedMemorySize, GEMM_SMEM_BYTES);
    cudaFuncSetAttribute(attn_mma_kernel,    cudaFuncAttributeMaxDynamicSharedMemorySize, ATT_SMEM);

    // weight packing (tf32-rounded, fragment-major, coalesced writes)
    pack_weight_kernel<<<dim3(QKV_N / 128, E_ / 32), 256>>>(W_qkv,  p_wqkvP,  E_,   QKV_N);
    pack_weight_kernel<<<dim3(E_ / 128,    E_ / 32), 256>>>(W_o,    p_woP,    E_,   E_);
    pack_weight_kernel<<<dim3(FC_N / 128,  E_ / 32), 256>>>(W_fc,   p_wfcP,   E_,   FC_N);
    pack_weight_kernel<<<dim3(E_ / 128,  FC_N / 32), 256>>>(W_proj, p_wprojP, FC_N, E_);

    // 1. ln1 = LN(x)
    layernorm_kernel<<<M_, 256>>>(x, ln1_g, ln1_b, p_ln);
    // 2. qkv = ln1 @ W_qkv + b_qkv
    gemm_mma_kernel<0><<<dim3(QKV_N / 128, M_ / 128), 128, GEMM_SMEM_BYTES>>>(
        p_ln, p_wqkvP, b_qkv, nullptr, p_qkv, QKV_N, E_);
    // 3. attention (mma.sync tf32 flash)
    attn_mma_kernel<<<dim3(T_ / 64, B_ * H_), 128, ATT_SMEM>>>(p_qkv, p_attn);
    // 4. x1 = x + attn @ W_o + b_o
    gemm_mma_kernel<1><<<dim3(E_ / 128, M_ / 128), 128, GEMM_SMEM_BYTES>>>(
        p_attn, p_woP, b_o, x, p_x1, E_, E_);
    // 5. ln2 = LN(x1)
    layernorm_kernel<<<M_, 256>>>(p_x1, ln2_g, ln2_b, p_ln);
    // 6. fc = gelu(ln2 @ W_fc + b_fc)
    gemm_mma_kernel<2><<<dim3(FC_N / 128, M_ / 128), 128, GEMM_SMEM_BYTES>>>(
        p_ln, p_wfcP, b_fc, nullptr, p_fc, FC_N, E_);
    // 7. out = x1 + fc @ W_proj + b_proj
    gemm_mma_kernel<1><<<dim3(E_ / 128, M_ / 128), 128, GEMM_SMEM_BYTES>>>(
        p_fc, p_wprojP, b_proj, p_x1, out, E_, FC_N);
}

// round 7
// speedup vs baseline: 8.8634x; 1.4432x over previous
#include <cuda_runtime.h>
#include <cuda_fp16.h>
#include <math.h>
#include <stdint.h>

// ---------------------------------------------------------------------------
// Problem constants
// ---------------------------------------------------------------------------
#define B_  2
#define T_  2048
#define E_  1024
#define H_  16
#define D_  64
#define M_  (B_ * T_)          // 4096
#define QKV_N (3 * E_)         // 3072
#define FC_N  (4 * E_)         // 4096

// ---------------------------------------------------------------------------
// Scratch (device globals; allocations forbidden)
// ---------------------------------------------------------------------------
__device__ __half g_lnH  [(size_t)M_ * E_];     // LN output (half, GEMM A operand)
__device__ float  g_qkv  [(size_t)M_ * QKV_N];  // qkv (fp32, feeds attention)
__device__ __half g_attnH[(size_t)M_ * E_];     // attention out (half, GEMM A)
__device__ float  g_x1   [(size_t)M_ * E_];     // x + attn@W_o + b_o (fp32)
__device__ __half g_fcH  [(size_t)M_ * FC_N];   // gelu(...) (half, GEMM A)
__device__ uint32_t g_wqkvP [(size_t)QKV_N * E_ / 2];   // fragment-packed half2
__device__ uint32_t g_woP   [(size_t)E_ * E_ / 2];
__device__ uint32_t g_wfcP  [(size_t)FC_N * E_ / 2];
__device__ uint32_t g_wprojP[(size_t)E_ * FC_N / 2];

// ---------------------------------------------------------------------------
// Helpers
// ---------------------------------------------------------------------------
__device__ __forceinline__ uint32_t smem_u32(const void* p) {
    uint32_t a;
    asm("{ .reg .u64 t; cvta.to.shared.u64 t, %1; cvt.u32.u64 %0, t; }" : "=r"(a) : "l"(p));
    return a;
}
__device__ __forceinline__ float rna_tf32(float x) {
    uint32_t u;
    asm("cvt.rna.tf32.f32 %0, %1;" : "=r"(u) : "f"(x));
    return __uint_as_float(u);
}
#define CP_ASYNC16(dst, src) \
    asm volatile("cp.async.cg.shared.global [%0], [%1], 16;" :: "r"(dst), "l"(src) : "memory")
#define CP_COMMIT() asm volatile("cp.async.commit_group;" ::: "memory")

// fp16 MMA: m16n8k16, fp32 accumulate
__device__ __forceinline__ void mma_f16(float (&c)[4],
                                        uint32_t a0, uint32_t a1, uint32_t a2, uint32_t a3,
                                        uint32_t b0, uint32_t b1) {
    asm volatile(
        "mma.sync.aligned.m16n8k16.row.col.f32.f16.f16.f32 "
        "{%0,%1,%2,%3}, {%4,%5,%6,%7}, {%8,%9}, {%0,%1,%2,%3};"
        : "+f"(c[0]), "+f"(c[1]), "+f"(c[2]), "+f"(c[3])
        : "r"(a0), "r"(a1), "r"(a2), "r"(a3), "r"(b0), "r"(b1));
}

// tf32 MMA (attention only)
__device__ __forceinline__ void mma_tf32(float (&c)[4],
                                         float a0, float a1, float a2, float a3,
                                         float b0, float b1) {
    asm volatile(
        "mma.sync.aligned.m16n8k8.row.col.f32.tf32.tf32.f32 "
        "{%0,%1,%2,%3}, {%4,%5,%6,%7}, {%8,%9}, {%0,%1,%2,%3};"
        : "+f"(c[0]), "+f"(c[1]), "+f"(c[2]), "+f"(c[3])
        : "r"(__float_as_uint(a0)), "r"(__float_as_uint(a1)),
          "r"(__float_as_uint(a2)), "r"(__float_as_uint(a3)),
          "r"(__float_as_uint(b0)), "r"(__float_as_uint(b1)));
}

// ---------------------------------------------------------------------------
// Weight pack (fp16): W[K,N] fp32 -> fragment-major half2 words.
// Tile = 128n x 32k. Superfrag s = kbb*16 + nb (kbb: k16 block, nb: n8 block);
// word o = s*64 + lane*2 + reg holds halfs { W[k][n], W[k+1][n] } with
//   k = kbb*16 + reg*8 + 2*tig, n = nb*8 + g   (g=lane>>2, tig=lane&3).
// Coalesced u32 writes; gathered fp32 reads (L2).
// ---------------------------------------------------------------------------
__global__ void pack_weight_h_kernel(const float* __restrict__ W, uint32_t* __restrict__ Wp,
                                     int K, int N)
{
    const int nt = blockIdx.x, kt = blockIdx.y;
    const int tid = threadIdx.x;               // 256
    uint32_t* dst = Wp + ((size_t)nt * (K >> 5) + kt) * 2048;
    #pragma unroll
    for (int i = 0; i < 8; i++) {
        const int o = tid + i * 256;           // 0..2047
        const int s = o >> 6;
        const int lane = (o >> 1) & 31;
        const int reg = o & 1;
        const int kbb = s >> 4, nb = s & 15;
        const int g = lane >> 2, tig = lane & 3;
        const int k = kt * 32 + kbb * 16 + reg * 8 + 2 * tig;
        const int n = nt * 128 + nb * 8 + g;
        const float x0 = W[(size_t)k * N + n];
        const float x1 = W[(size_t)(k + 1) * N + n];
        const __half2 h = __floats2half2_rn(x0, x1);
        dst[o] = *(const uint32_t*)&h;
    }
}

// ---------------------------------------------------------------------------
// fp16 mma.sync GEMM: C[M,N] = A[M,K](half) @ W(packed half) + bias (+res|gelu)
// BM=BN=128, BK=32, 128 threads, 4 warps (2M x 2N), warp tile 64x64.
// cp.async double-buffered. EPI: 0=bias (fp32 C), 1=bias+res (fp32 C),
//                                2=bias+GELU (half C)
// ---------------------------------------------------------------------------
#define SA_STR_H   40                        // halfs per A smem row
#define SA_H_BYTES (128 * SA_STR_H * 2)      // 10240
#define SB_H_BYTES 8192
#define BUF_H      (SA_H_BYTES + SB_H_BYTES) // 18432
#define GEMM_H_SMEM (2 * BUF_H)              // 36864

template<int EPI>
__global__ void __launch_bounds__(128, 2)
gemm_h_kernel(const __half* __restrict__ A, const uint32_t* __restrict__ Wp,
              const float* __restrict__ bias, const float* __restrict__ res,
              void* __restrict__ Cv, int N, int K)
{
    extern __shared__ char smem[];
    const uint32_t sbase = smem_u32(smem);
    float* Cf = (float*)Cv;
    __half* Ch = (__half*)Cv;

    const int tid  = threadIdx.x;
    const int wid  = tid >> 5;
    const int lane = tid & 31;
    const int g    = lane >> 2;
    const int tig  = lane & 3;
    const int wm   = (wid >> 1) * 64;
    const int wn   = (wid & 1) * 64;
    const int m0   = blockIdx.y * 128;
    const int n0   = blockIdx.x * 128;

    const int ntile = K >> 5;
    const size_t wtile0 = (size_t)blockIdx.x * ntile * 2048;   // u32 units

    // A copy: 512 16B chunks (8 halfs each), 4 per thread
    const int am = tid >> 2;               // 0..31 (+32*i)
    const int ac = tid & 3;

    float acc[4][8][4];
    #pragma unroll
    for (int mt = 0; mt < 4; mt++)
        #pragma unroll
        for (int nb = 0; nb < 8; nb++)
            #pragma unroll
            for (int r = 0; r < 4; r++) acc[mt][nb][r] = 0.f;

    auto load_tile = [&](int buf, int kt) {
        const uint32_t sA = sbase + buf * BUF_H;
        const uint32_t sB = sA + SA_H_BYTES;
        const __half* asrc = A + (size_t)(m0 + am) * K + kt * 32 + ac * 8;
        #pragma unroll
        for (int i = 0; i < 4; i++) {
            CP_ASYNC16(sA + (uint32_t)(am + i * 32) * (SA_STR_H * 2) + ac * 16,
                       asrc + (size_t)i * 32 * K);
        }
        const uint32_t* bsrc = Wp + wtile0 + (size_t)kt * 2048 + tid * 4;
        #pragma unroll
        for (int i = 0; i < 4; i++) {
            CP_ASYNC16(sB + (uint32_t)(tid + i * 128) * 16, bsrc + i * 512);
        }
        CP_COMMIT();
    };

    load_tile(0, 0);

    for (int t = 0; t < ntile; t++) {
        const int cur = t & 1;
        if (t + 1 < ntile) {
            load_tile(cur ^ 1, t + 1);
            asm volatile("cp.async.wait_group 1;" ::: "memory");
        } else {
            asm volatile("cp.async.wait_group 0;" ::: "memory");
        }
        __syncthreads();

        const __half* As = (const __half*)(smem + cur * BUF_H);
        const uint32_t* Bs = (const uint32_t*)(smem + cur * BUF_H + SA_H_BYTES);

        #pragma unroll
        for (int kbb = 0; kbb < 2; kbb++) {
            uint32_t a[4][4];
            #pragma unroll
            for (int mt = 0; mt < 4; mt++) {
                const int r = wm + mt * 16 + g;
                a[mt][0] = *(const uint32_t*)(As + r * SA_STR_H + kbb * 16 + 2 * tig);
                a[mt][1] = *(const uint32_t*)(As + (r + 8) * SA_STR_H + kbb * 16 + 2 * tig);
                a[mt][2] = *(const uint32_t*)(As + r * SA_STR_H + kbb * 16 + 2 * tig + 8);
                a[mt][3] = *(const uint32_t*)(As + (r + 8) * SA_STR_H + kbb * 16 + 2 * tig + 8);
            }
            #pragma unroll
            for (int nb = 0; nb < 8; nb++) {
                const int s = kbb * 16 + (wn >> 3) + nb;
                const uint32_t b0 = Bs[s * 64 + lane * 2];
                const uint32_t b1 = Bs[s * 64 + lane * 2 + 1];
                #pragma unroll
                for (int mt = 0; mt < 4; mt++)
                    mma_f16(acc[mt][nb], a[mt][0], a[mt][1], a[mt][2], a[mt][3], b0, b1);
            }
        }
        __syncthreads();
    }

    // ---- epilogue ----
    #pragma unroll
    for (int mt = 0; mt < 4; mt++) {
        const size_t r0 = (size_t)(m0 + wm + mt * 16 + g);
        #pragma unroll
        for (int nb = 0; nb < 8; nb++) {
            const int col = n0 + wn + nb * 8 + 2 * tig;
            const float2 bv = *(const float2*)(bias + col);
            #pragma unroll
            for (int hh = 0; hh < 2; hh++) {
                const size_t row = r0 + hh * 8;
                float vx = acc[mt][nb][hh * 2 + 0] + bv.x;
                float vy = acc[mt][nb][hh * 2 + 1] + bv.y;
                if (EPI == 1) {
                    const float2 r2 = *(const float2*)(res + row * N + col);
                    vx += r2.x; vy += r2.y;
                }
                if (EPI == 2) {
                    vx = 0.5f * vx * (1.0f + erff(vx * 0.70710678118654752f));
                    vy = 0.5f * vy * (1.0f + erff(vy * 0.70710678118654752f));
                    *(__half2*)(Ch + row * N + col) = __floats2half2_rn(vx, vy);
                } else {
                    float2 o2; o2.x = vx; o2.y = vy;
                    *(float2*)(Cf + row * N + col) = o2;
                }
            }
        }
    }
}

// ---------------------------------------------------------------------------
// LayerNorm: fp32 in, half out (only feeds fp16 GEMMs)
// ---------------------------------------------------------------------------
__global__ void layernorm_kernel(const float* __restrict__ x,
                                 const float* __restrict__ gamma,
                                 const float* __restrict__ beta,
                                 __half* __restrict__ out)
{
    const int row = blockIdx.x;
    const int tid = threadIdx.x;
    const float4 xv = ((const float4*)(x + (size_t)row * E_))[tid];

    float s  = xv.x + xv.y + xv.z + xv.w;
    float ss = xv.x*xv.x + xv.y*xv.y + xv.z*xv.z + xv.w*xv.w;
    #pragma unroll
    for (int o = 16; o > 0; o >>= 1) {
        s  += __shfl_xor_sync(0xffffffffu, s,  o);
        ss += __shfl_xor_sync(0xffffffffu, ss, o);
    }
    __shared__ float sbuf[8], ssbuf[8];
    const int wid = tid >> 5, lane = tid & 31;
    if (lane == 0) { sbuf[wid] = s; ssbuf[wid] = ss; }
    __syncthreads();
    float tot = 0.f, tots = 0.f;
    #pragma unroll
    for (int i = 0; i < 8; i++) { tot += sbuf[i]; tots += ssbuf[i]; }

    const float mean = tot * (1.0f / E_);
    const float var  = tots * (1.0f / E_) - mean * mean;
    const float r    = rsqrtf(var + 1e-5f);

    const float4 gv = ((const float4*)gamma)[tid];
    const float4 bv = ((const float4*)beta)[tid];
    __half2* op = (__half2*)(out + (size_t)row * E_ + tid * 4);
    op[0] = __floats2half2_rn((xv.x - mean) * r * gv.x + bv.x,
                              (xv.y - mean) * r * gv.y + bv.y);
    op[1] = __floats2half2_rn((xv.z - mean) * r * gv.z + bv.z,
                              (xv.w - mean) * r * gv.w + bv.w);
}

// ---------------------------------------------------------------------------
// Flash attention via mma.sync tf32 (fp32 qkv in, half out)
// ---------------------------------------------------------------------------
#define KS_STR 68
#define VS_STR 72
#define PS_STR 68
#define ATT_SMEM ((64 * KS_STR + 64 * VS_STR + 64 * PS_STR) * 4)   // 53248

__global__ void __launch_bounds__(128, 2)
attn_mma_kernel(const float* __restrict__ qkv, __half* __restrict__ out)
{
    extern __shared__ float smf[];
    float* Ks = smf;
    float* Vs = smf + 64 * KS_STR;
    float* Ps = smf + 64 * KS_STR + 64 * VS_STR;
    const uint32_t sKs = smem_u32(Ks);
    const uint32_t sVs = smem_u32(Vs);

    const int bh  = blockIdx.y;
    const int b   = bh >> 4;
    const int h   = bh & 15;
    const int m0  = blockIdx.x * 64;
    const int tid = threadIdx.x;
    const int wid = tid >> 5;
    const int lane = tid & 31;
    const int g    = lane >> 2;
    const int tig  = lane & 3;
    const int qr   = wid * 16;
    const float NEG_INF = __int_as_float(0xff800000);

    const size_t baseQ = ((size_t)(b * T_ + m0)) * QKV_N + h * D_;
    #pragma unroll
    for (int i = 0; i < 8; i++) {
        const int idx = tid + i * 128;
        const int r = idx >> 4, c4 = idx & 15;
        float4 v = *(const float4*)(qkv + baseQ + (size_t)r * QKV_N + c4 * 4);
        v.x = rna_tf32(v.x * 0.125f); v.y = rna_tf32(v.y * 0.125f);
        v.z = rna_tf32(v.z * 0.125f); v.w = rna_tf32(v.w * 0.125f);
        *(float4*)(Ps + r * PS_STR + c4 * 4) = v;
    }
    __syncthreads();

    float qf[8][4];
    #pragma unroll
    for (int kb = 0; kb < 8; kb++) {
        qf[kb][0] = Ps[(qr + g)     * PS_STR + kb * 8 + tig];
        qf[kb][1] = Ps[(qr + g + 8) * PS_STR + kb * 8 + tig];
        qf[kb][2] = Ps[(qr + g)     * PS_STR + kb * 8 + tig + 4];
        qf[kb][3] = Ps[(qr + g + 8) * PS_STR + kb * 8 + tig + 4];
    }

    float oacc[8][4];
    #pragma unroll
    for (int nb = 0; nb < 8; nb++)
        #pragma unroll
        for (int r = 0; r < 4; r++) oacc[nb][r] = 0.f;
    float mr0 = NEG_INF, mr1 = NEG_INF, l0 = 0.f, l1 = 0.f;

    const int tq0 = m0 + qr + g;
    const int tq1 = tq0 + 8;
    const int ntile = (m0 >> 6) + 1;

    for (int t = 0; t < ntile; t++) {
        const int j0 = t * 64;
        __syncthreads();

        const size_t baseK = ((size_t)(b * T_ + j0)) * QKV_N + E_ + h * D_;
        #pragma unroll
        for (int i = 0; i < 8; i++) {
            const int idx = tid + i * 128;
            const int r = idx >> 4, c4 = idx & 15;
            const float* src = qkv + baseK + (size_t)r * QKV_N + c4 * 4;
            CP_ASYNC16(sKs + (uint32_t)(r * KS_STR + c4 * 4) * 4, src);
            CP_ASYNC16(sVs + (uint32_t)(r * VS_STR + c4 * 4) * 4, src + E_);
        }
        CP_COMMIT();
        asm volatile("cp.async.wait_group 0;" ::: "memory");
        __syncthreads();

        float sc[8][4];
        #pragma unroll
        for (int jb = 0; jb < 8; jb++) {
            sc[jb][0] = sc[jb][1] = sc[jb][2] = sc[jb][3] = 0.f;
            #pragma unroll
            for (int kb = 0; kb < 8; kb++) {
                const float b0 = Ks[(jb * 8 + g) * KS_STR + kb * 8 + tig];
                const float b1 = Ks[(jb * 8 + g) * KS_STR + kb * 8 + tig + 4];
                mma_tf32(sc[jb], qf[kb][0], qf[kb][1], qf[kb][2], qf[kb][3], b0, b1);
            }
        }

        float tm0 = NEG_INF, tm1 = NEG_INF;
        #pragma unroll
        for (int jb = 0; jb < 8; jb++) {
            const int c0 = j0 + jb * 8 + 2 * tig;
            const int c1 = c0 + 1;
            if (c0 > tq0) sc[jb][0] = NEG_INF;
            if (c1 > tq0) sc[jb][1] = NEG_INF;
            if (c0 > tq1) sc[jb][2] = NEG_INF;
            if (c1 > tq1) sc[jb][3] = NEG_INF;
            tm0 = fmaxf(tm0, fmaxf(sc[jb][0], sc[jb][1]));
            tm1 = fmaxf(tm1, fmaxf(sc[jb][2], sc[jb][3]));
        }
        tm0 = fmaxf(tm0, __shfl_xor_sync(0xffffffffu, tm0, 1));
        tm0 = fmaxf(tm0, __shfl_xor_sync(0xffffffffu, tm0, 2));
        tm1 = fmaxf(tm1, __shfl_xor_sync(0xffffffffu, tm1, 1));
        tm1 = fmaxf(tm1, __shfl_xor_sync(0xffffffffu, tm1, 2));

        const float mn0 = fmaxf(mr0, tm0);
        const float mn1 = fmaxf(mr1, tm1);
        const float a0 = __expf(mr0 - mn0);
        const float a1 = __expf(mr1 - mn1);
        l0 *= a0; l1 *= a1;
        #pragma unroll
        for (int nb = 0; nb < 8; nb++) {
            oacc[nb][0] *= a0; oacc[nb][1] *= a0;
            oacc[nb][2] *= a1; oacc[nb][3] *= a1;
        }

        float ps0 = 0.f, ps1 = 0.f;
        #pragma unroll
        for (int jb = 0; jb < 8; jb++) {
            const float p0 = rna_tf32(__expf(sc[jb][0] - mn0));
            const float p1 = rna_tf32(__expf(sc[jb][1] - mn0));
            const float p2 = rna_tf32(__expf(sc[jb][2] - mn1));
            const float p3 = rna_tf32(__expf(sc[jb][3] - mn1));
            ps0 += p0 + p1; ps1 += p2 + p3;
            float2 lo; lo.x = p0; lo.y = p1;
            float2 hi; hi.x = p2; hi.y = p3;
            *(float2*)(Ps + (qr + g)     * PS_STR + jb * 8 + 2 * tig) = lo;
            *(float2*)(Ps + (qr + g + 8) * PS_STR + jb * 8 + 2 * tig) = hi;
        }
        ps0 += __shfl_xor_sync(0xffffffffu, ps0, 1);
        ps0 += __shfl_xor_sync(0xffffffffu, ps0, 2);
        ps1 += __shfl_xor_sync(0xffffffffu, ps1, 1);
        ps1 += __shfl_xor_sync(0xffffffffu, ps1, 2);
        l0 += ps0; l1 += ps1;
        mr0 = mn0; mr1 = mn1;
        __syncwarp();

        float af[8][4];
        #pragma unroll
        for (int kb = 0; kb < 8; kb++) {
            af[kb][0] = Ps[(qr + g)     * PS_STR + kb * 8 + tig];
            af[kb][1] = Ps[(qr + g + 8) * PS_STR + kb * 8 + tig];
            af[kb][2] = Ps[(qr + g)     * PS_STR + kb * 8 + tig + 4];
            af[kb][3] = Ps[(qr + g + 8) * PS_STR + kb * 8 + tig + 4];
        }
        #pragma unroll
        for (int nb = 0; nb < 8; nb++) {
            #pragma unroll
            for (int kb = 0; kb < 8; kb++) {
                const float b0 = Vs[(kb * 8 + tig)     * VS_STR + nb * 8 + g];
                const float b1 = Vs[(kb * 8 + tig + 4) * VS_STR + nb * 8 + g];
                mma_tf32(oacc[nb], af[kb][0], af[kb][1], af[kb][2], af[kb][3], b0, b1);
            }
        }
    }

    const float inv0 = 1.0f / l0;
    const float inv1 = 1.0f / l1;
    const size_t row0 = (size_t)(b * T_ + tq0);
    const size_t row1 = (size_t)(b * T_ + tq1);
    #pragma unroll
    for (int nb = 0; nb < 8; nb++) {
        const int col = h * D_ + nb * 8 + 2 * tig;
        *(__half2*)(out + row0 * E_ + col) =
            __floats2half2_rn(oacc[nb][0] * inv0, oacc[nb][1] * inv0);
        *(__half2*)(out + row1 * E_ + col) =
            __floats2half2_rn(oacc[nb][2] * inv1, oacc[nb][3] * inv1);
    }
}

// ---------------------------------------------------------------------------
// Launch
// ---------------------------------------------------------------------------
extern "C" void kernel_launch(void* const* d_in, const int* in_sizes, int n_in,
                              void* d_out, int out_size)
{
    const float* x      = (const float*)d_in[0];
    const float* ln1_g  = (const float*)d_in[1];
    const float* ln1_b  = (const float*)d_in[2];
    const float* ln2_g  = (const float*)d_in[3];
    const float* ln2_b  = (const float*)d_in[4];
    const float* W_qkv  = (const float*)d_in[5];
    const float* b_qkv  = (const float*)d_in[6];
    const float* W_o    = (const float*)d_in[7];
    const float* b_o    = (const float*)d_in[8];
    const float* W_fc   = (const float*)d_in[9];
    const float* b_fc   = (const float*)d_in[10];
    const float* W_proj = (const float*)d_in[11];
    const float* b_proj = (const float*)d_in[12];
    float* out = (float*)d_out;

    __half *p_lnH, *p_attnH, *p_fcH;
    float *p_qkv, *p_x1;
    uint32_t *p_wqkvP, *p_woP, *p_wfcP, *p_wprojP;
    cudaGetSymbolAddress((void**)&p_lnH,    g_lnH);
    cudaGetSymbolAddress((void**)&p_qkv,    g_qkv);
    cudaGetSymbolAddress((void**)&p_attnH,  g_attnH);
    cudaGetSymbolAddress((void**)&p_x1,     g_x1);
    cudaGetSymbolAddress((void**)&p_fcH,    g_fcH);
    cudaGetSymbolAddress((void**)&p_wqkvP,  g_wqkvP);
    cudaGetSymbolAddress((void**)&p_woP,    g_woP);
    cudaGetSymbolAddress((void**)&p_wfcP,   g_wfcP);
    cudaGetSymbolAddress((void**)&p_wprojP, g_wprojP);

    cudaFuncSetAttribute(gemm_h_kernel<0>, cudaFuncAttributeMaxDynamicSharedMemorySize, GEMM_H_SMEM);
    cudaFuncSetAttribute(gemm_h_kernel<1>, cudaFuncAttributeMaxDynamicSharedMemorySize, GEMM_H_SMEM);
    cudaFuncSetAttribute(gemm_h_kernel<2>, cudaFuncAttributeMaxDynamicSharedMemorySize, GEMM_H_SMEM);
    cudaFuncSetAttribute(attn_mma_kernel,  cudaFuncAttributeMaxDynamicSharedMemorySize, ATT_SMEM);

    // weight packing (fp16, fragment-major, coalesced writes)
    pack_weight_h_kernel<<<dim3(QKV_N / 128, E_ / 32), 256>>>(W_qkv,  p_wqkvP,  E_,   QKV_N);
    pack_weight_h_kernel<<<dim3(E_ / 128,    E_ / 32), 256>>>(W_o,    p_woP,    E_,   E_);
    pack_weight_h_kernel<<<dim3(FC_N / 128,  E_ / 32), 256>>>(W_fc,   p_wfcP,   E_,   FC_N);
    pack_weight_h_kernel<<<dim3(E_ / 128,  FC_N / 32), 256>>>(W_proj, p_wprojP, FC_N, E_);

    // 1. ln1 = LN(x) -> half
    layernorm_kernel<<<M_, 256>>>(x, ln1_g, ln1_b, p_lnH);
    // 2. qkv = ln1 @ W_qkv + b_qkv (fp32 out)
    gemm_h_kernel<0><<<dim3(QKV_N / 128, M_ / 128), 128, GEMM_H_SMEM>>>(
        p_lnH, p_wqkvP, b_qkv, nullptr, p_qkv, QKV_N, E_);
    // 3. attention (tf32 flash, half out)
    attn_mma_kernel<<<dim3(T_ / 64, B_ * H_), 128, ATT_SMEM>>>(p_qkv, p_attnH);
    // 4. x1 = x + attn @ W_o + b_o (fp32 out)
    gemm_h_kernel<1><<<dim3(E_ / 128, M_ / 128), 128, GEMM_H_SMEM>>>(
        p_attnH, p_woP, b_o, x, p_x1, E_, E_);
    // 5. ln2 = LN(x1) -> half
    layernorm_kernel<<<M_, 256>>>(p_x1, ln2_g, ln2_b, p_lnH);
    // 6. fc = gelu(ln2 @ W_fc + b_fc) -> half
    gemm_h_kernel<2><<<dim3(FC_N / 128, M_ / 128), 128, GEMM_H_SMEM>>>(
        p_lnH, p_wfcP, b_fc, nullptr, p_fcH, FC_N, E_);
    // 7. out = x1 + fc @ W_proj + b_proj (fp32 out)
    gemm_h_kernel<1><<<dim3(E_ / 128, M_ / 128), 128, GEMM_H_SMEM>>>(
        p_fcH, p_wprojP, b_proj, p_x1, out, E_, FC_N);
}

// round 8
// speedup vs baseline: 10.1462x; 1.1447x over previous
#include <cuda_runtime.h>
#include <cuda_fp16.h>
#include <math.h>
#include <stdint.h>

// ---------------------------------------------------------------------------
// Problem constants
// ---------------------------------------------------------------------------
#define B_  2
#define T_  2048
#define E_  1024
#define H_  16
#define D_  64
#define M_  (B_ * T_)          // 4096
#define QKV_N (3 * E_)         // 3072
#define FC_N  (4 * E_)         // 4096

// ---------------------------------------------------------------------------
// Scratch (device globals; allocations forbidden)
// ---------------------------------------------------------------------------
__device__ __half g_lnH  [(size_t)M_ * E_];
__device__ __half g_qkvH [(size_t)M_ * QKV_N];  // qkv (half)
__device__ __half g_attnH[(size_t)M_ * E_];
__device__ float  g_x1   [(size_t)M_ * E_];
__device__ __half g_fcH  [(size_t)M_ * FC_N];
__device__ uint32_t g_wqkvP [(size_t)QKV_N * E_ / 2];
__device__ uint32_t g_woP   [(size_t)E_ * E_ / 2];
__device__ uint32_t g_wfcP  [(size_t)FC_N * E_ / 2];
__device__ uint32_t g_wprojP[(size_t)E_ * FC_N / 2];

// ---------------------------------------------------------------------------
// Helpers
// ---------------------------------------------------------------------------
__device__ __forceinline__ uint32_t smem_u32(const void* p) {
    uint32_t a;
    asm("{ .reg .u64 t; cvta.to.shared.u64 t, %1; cvt.u32.u64 %0, t; }" : "=r"(a) : "l"(p));
    return a;
}
#define CP_ASYNC16(dst, src) \
    asm volatile("cp.async.cg.shared.global [%0], [%1], 16;" :: "r"(dst), "l"(src) : "memory")
#define CP_COMMIT() asm volatile("cp.async.commit_group;" ::: "memory")

// fp16 MMA: m16n8k16, fp32 accumulate
__device__ __forceinline__ void mma_f16(float (&c)[4],
                                        uint32_t a0, uint32_t a1, uint32_t a2, uint32_t a3,
                                        uint32_t b0, uint32_t b1) {
    asm volatile(
        "mma.sync.aligned.m16n8k16.row.col.f32.f16.f16.f32 "
        "{%0,%1,%2,%3}, {%4,%5,%6,%7}, {%8,%9}, {%0,%1,%2,%3};"
        : "+f"(c[0]), "+f"(c[1]), "+f"(c[2]), "+f"(c[3])
        : "r"(a0), "r"(a1), "r"(a2), "r"(a3), "r"(b0), "r"(b1));
}
__device__ __forceinline__ uint32_t pack_h2(float lo, float hi) {
    const __half2 h = __floats2half2_rn(lo, hi);
    return *(const uint32_t*)&h;
}

// ---------------------------------------------------------------------------
// Weight pack (fp16): W[K,N] fp32 -> fragment-major half2 words (Round-7 layout)
// ---------------------------------------------------------------------------
__global__ void pack_weight_h_kernel(const float* __restrict__ W, uint32_t* __restrict__ Wp,
                                     int K, int N)
{
    const int nt = blockIdx.x, kt = blockIdx.y;
    const int tid = threadIdx.x;               // 256
    uint32_t* dst = Wp + ((size_t)nt * (K >> 5) + kt) * 2048;
    #pragma unroll
    for (int i = 0; i < 8; i++) {
        const int o = tid + i * 256;
        const int s = o >> 6;
        const int lane = (o >> 1) & 31;
        const int reg = o & 1;
        const int kbb = s >> 4, nb = s & 15;
        const int g = lane >> 2, tig = lane & 3;
        const int k = kt * 32 + kbb * 16 + reg * 8 + 2 * tig;
        const int n = nt * 128 + nb * 8 + g;
        dst[o] = pack_h2(W[(size_t)k * N + n], W[(size_t)(k + 1) * N + n]);
    }
}

// ---------------------------------------------------------------------------
// fp16 mma.sync GEMM (Round-7 structure).
// EPI: 0=bias (fp32 C), 1=bias+res (fp32 C), 2=bias+GELU (half C), 3=bias (half C)
// ---------------------------------------------------------------------------
#define SA_STR_H   40
#define SA_H_BYTES (128 * SA_STR_H * 2)
#define SB_H_BYTES 8192
#define BUF_H      (SA_H_BYTES + SB_H_BYTES)
#define GEMM_H_SMEM (2 * BUF_H)

template<int EPI>
__global__ void __launch_bounds__(128, 2)
gemm_h_kernel(const __half* __restrict__ A, const uint32_t* __restrict__ Wp,
              const float* __restrict__ bias, const float* __restrict__ res,
              void* __restrict__ Cv, int N, int K)
{
    extern __shared__ char smem[];
    const uint32_t sbase = smem_u32(smem);
    float* Cf = (float*)Cv;
    __half* Ch = (__half*)Cv;

    const int tid  = threadIdx.x;
    const int wid  = tid >> 5;
    const int lane = tid & 31;
    const int g    = lane >> 2;
    const int tig  = lane & 3;
    const int wm   = (wid >> 1) * 64;
    const int wn   = (wid & 1) * 64;
    const int m0   = blockIdx.y * 128;
    const int n0   = blockIdx.x * 128;

    const int ntile = K >> 5;
    const size_t wtile0 = (size_t)blockIdx.x * ntile * 2048;

    const int am = tid >> 2;
    const int ac = tid & 3;

    float acc[4][8][4];
    #pragma unroll
    for (int mt = 0; mt < 4; mt++)
        #pragma unroll
        for (int nb = 0; nb < 8; nb++)
            #pragma unroll
            for (int r = 0; r < 4; r++) acc[mt][nb][r] = 0.f;

    auto load_tile = [&](int buf, int kt) {
        const uint32_t sA = sbase + buf * BUF_H;
        const uint32_t sB = sA + SA_H_BYTES;
        const __half* asrc = A + (size_t)(m0 + am) * K + kt * 32 + ac * 8;
        #pragma unroll
        for (int i = 0; i < 4; i++) {
            CP_ASYNC16(sA + (uint32_t)(am + i * 32) * (SA_STR_H * 2) + ac * 16,
                       asrc + (size_t)i * 32 * K);
        }
        const uint32_t* bsrc = Wp + wtile0 + (size_t)kt * 2048 + tid * 4;
        #pragma unroll
        for (int i = 0; i < 4; i++) {
            CP_ASYNC16(sB + (uint32_t)(tid + i * 128) * 16, bsrc + i * 512);
        }
        CP_COMMIT();
    };

    load_tile(0, 0);

    for (int t = 0; t < ntile; t++) {
        const int cur = t & 1;
        if (t + 1 < ntile) {
            load_tile(cur ^ 1, t + 1);
            asm volatile("cp.async.wait_group 1;" ::: "memory");
        } else {
            asm volatile("cp.async.wait_group 0;" ::: "memory");
        }
        __syncthreads();

        const __half* As = (const __half*)(smem + cur * BUF_H);
        const uint32_t* Bs = (const uint32_t*)(smem + cur * BUF_H + SA_H_BYTES);

        #pragma unroll
        for (int kbb = 0; kbb < 2; kbb++) {
            uint32_t a[4][4];
            #pragma unroll
            for (int mt = 0; mt < 4; mt++) {
                const int r = wm + mt * 16 + g;
                a[mt][0] = *(const uint32_t*)(As + r * SA_STR_H + kbb * 16 + 2 * tig);
                a[mt][1] = *(const uint32_t*)(As + (r + 8) * SA_STR_H + kbb * 16 + 2 * tig);
                a[mt][2] = *(const uint32_t*)(As + r * SA_STR_H + kbb * 16 + 2 * tig + 8);
                a[mt][3] = *(const uint32_t*)(As + (r + 8) * SA_STR_H + kbb * 16 + 2 * tig + 8);
            }
            #pragma unroll
            for (int nb = 0; nb < 8; nb++) {
                const int s = kbb * 16 + (wn >> 3) + nb;
                const uint32_t b0 = Bs[s * 64 + lane * 2];
                const uint32_t b1 = Bs[s * 64 + lane * 2 + 1];
                #pragma unroll
                for (int mt = 0; mt < 4; mt++)
                    mma_f16(acc[mt][nb], a[mt][0], a[mt][1], a[mt][2], a[mt][3], b0, b1);
            }
        }
        __syncthreads();
    }

    #pragma unroll
    for (int mt = 0; mt < 4; mt++) {
        const size_t r0 = (size_t)(m0 + wm + mt * 16 + g);
        #pragma unroll
        for (int nb = 0; nb < 8; nb++) {
            const int col = n0 + wn + nb * 8 + 2 * tig;
            const float2 bv = *(const float2*)(bias + col);
            #pragma unroll
            for (int hh = 0; hh < 2; hh++) {
                const size_t row = r0 + hh * 8;
                float vx = acc[mt][nb][hh * 2 + 0] + bv.x;
                float vy = acc[mt][nb][hh * 2 + 1] + bv.y;
                if (EPI == 1) {
                    const float2 r2 = *(const float2*)(res + row * N + col);
                    vx += r2.x; vy += r2.y;
                }
                if (EPI == 2) {
                    vx = 0.5f * vx * (1.0f + erff(vx * 0.70710678118654752f));
                    vy = 0.5f * vy * (1.0f + erff(vy * 0.70710678118654752f));
                }
                if (EPI == 2 || EPI == 3) {
                    *(__half2*)(Ch + row * N + col) = __floats2half2_rn(vx, vy);
                } else {
                    float2 o2; o2.x = vx; o2.y = vy;
                    *(float2*)(Cf + row * N + col) = o2;
                }
            }
        }
    }
}

// ---------------------------------------------------------------------------
// LayerNorm: fp32 in, half out
// ---------------------------------------------------------------------------
__global__ void layernorm_kernel(const float* __restrict__ x,
                                 const float* __restrict__ gamma,
                                 const float* __restrict__ beta,
                                 __half* __restrict__ out)
{
    const int row = blockIdx.x;
    const int tid = threadIdx.x;
    const float4 xv = ((const float4*)(x + (size_t)row * E_))[tid];

    float s  = xv.x + xv.y + xv.z + xv.w;
    float ss = xv.x*xv.x + xv.y*xv.y + xv.z*xv.z + xv.w*xv.w;
    #pragma unroll
    for (int o = 16; o > 0; o >>= 1) {
        s  += __shfl_xor_sync(0xffffffffu, s,  o);
        ss += __shfl_xor_sync(0xffffffffu, ss, o);
    }
    __shared__ float sbuf[8], ssbuf[8];
    const int wid = tid >> 5, lane = tid & 31;
    if (lane == 0) { sbuf[wid] = s; ssbuf[wid] = ss; }
    __syncthreads();
    float tot = 0.f, tots = 0.f;
    #pragma unroll
    for (int i = 0; i < 8; i++) { tot += sbuf[i]; tots += ssbuf[i]; }

    const float mean = tot * (1.0f / E_);
    const float var  = tots * (1.0f / E_) - mean * mean;
    const float r    = rsqrtf(var + 1e-5f);

    const float4 gv = ((const float4*)gamma)[tid];
    const float4 bv = ((const float4*)beta)[tid];
    __half2* op = (__half2*)(out + (size_t)row * E_ + tid * 4);
    op[0] = __floats2half2_rn((xv.x - mean) * r * gv.x + bv.x,
                              (xv.y - mean) * r * gv.y + bv.y);
    op[1] = __floats2half2_rn((xv.z - mean) * r * gv.z + bv.z,
                              (xv.w - mean) * r * gv.w + bv.w);
}

// ---------------------------------------------------------------------------
// Flash attention, fully fp16 mma (m16n8k16), fp32 softmax/accum.
// Block = 64 queries x 1 head, 128 threads (4 warps x 16 queries).
// smem: Qs[64][72], Ks[64][72], Vs[64][72] halfs. P lives in registers.
// ---------------------------------------------------------------------------
#define KVSTR 72
#define ATT_SMEM (3 * 64 * KVSTR * 2)   // 27648

__global__ void __launch_bounds__(128, 2)
attn_h_kernel(const __half* __restrict__ qkv, __half* __restrict__ out)
{
    extern __shared__ __half smh[];
    __half* Qs = smh;
    __half* Ks = smh + 64 * KVSTR;
    __half* Vs = smh + 128 * KVSTR;
    const uint32_t sQs = smem_u32(Qs);
    const uint32_t sKs = smem_u32(Ks);
    const uint32_t sVs = smem_u32(Vs);

    const int bh  = blockIdx.y;
    const int b   = bh >> 4;
    const int h   = bh & 15;
    const int m0  = blockIdx.x * 64;
    const int tid = threadIdx.x;
    const int wid = tid >> 5;
    const int lane = tid & 31;
    const int g    = lane >> 2;
    const int tig  = lane & 3;
    const int qr   = wid * 16;
    const float NEG_INF = __int_as_float(0xff800000);

    // ---- stage Q tile (raw half; 1/8 scale applied to scores later) ----
    const size_t baseQ = ((size_t)(b * T_ + m0)) * QKV_N + h * D_;
    #pragma unroll
    for (int i = 0; i < 4; i++) {
        const int idx = tid + i * 128;       // 0..511
        const int r = idx >> 3, c = idx & 7;
        CP_ASYNC16(sQs + (uint32_t)(r * KVSTR + c * 8) * 2,
                   qkv + baseQ + (size_t)r * QKV_N + c * 8);
    }
    CP_COMMIT();
    asm volatile("cp.async.wait_group 0;" ::: "memory");
    __syncthreads();

    uint32_t qf[4][4];
    #pragma unroll
    for (int kc = 0; kc < 4; kc++) {
        qf[kc][0] = *(const uint32_t*)(Qs + (qr + g)     * KVSTR + kc * 16 + 2 * tig);
        qf[kc][1] = *(const uint32_t*)(Qs + (qr + g + 8) * KVSTR + kc * 16 + 2 * tig);
        qf[kc][2] = *(const uint32_t*)(Qs + (qr + g)     * KVSTR + kc * 16 + 2 * tig + 8);
        qf[kc][3] = *(const uint32_t*)(Qs + (qr + g + 8) * KVSTR + kc * 16 + 2 * tig + 8);
    }

    float oacc[8][4];
    #pragma unroll
    for (int nb = 0; nb < 8; nb++)
        #pragma unroll
        for (int r = 0; r < 4; r++) oacc[nb][r] = 0.f;
    float mr0 = NEG_INF, mr1 = NEG_INF, l0 = 0.f, l1 = 0.f;

    const int tq0 = m0 + qr + g;
    const int tq1 = tq0 + 8;
    const int ntile = (m0 >> 6) + 1;

    for (int t = 0; t < ntile; t++) {
        const int j0 = t * 64;
        __syncthreads();   // previous tile fully consumed

        const size_t baseK = ((size_t)(b * T_ + j0)) * QKV_N + E_ + h * D_;
        #pragma unroll
        for (int i = 0; i < 4; i++) {
            const int idx = tid + i * 128;
            const int r = idx >> 3, c = idx & 7;
            const __half* src = qkv + baseK + (size_t)r * QKV_N + c * 8;
            CP_ASYNC16(sKs + (uint32_t)(r * KVSTR + c * 8) * 2, src);
            CP_ASYNC16(sVs + (uint32_t)(r * KVSTR + c * 8) * 2, src + E_);
        }
        CP_COMMIT();
        asm volatile("cp.async.wait_group 0;" ::: "memory");
        __syncthreads();

        // ---- QK^T (fp16 MMA, fp32 accum), then scale by 1/8 ----
        float sc[8][4];
        #pragma unroll
        for (int jb = 0; jb < 8; jb++) {
            sc[jb][0] = sc[jb][1] = sc[jb][2] = sc[jb][3] = 0.f;
            #pragma unroll
            for (int kc = 0; kc < 4; kc++) {
                const uint32_t b0 = *(const uint32_t*)(Ks + (jb * 8 + g) * KVSTR + kc * 16 + 2 * tig);
                const uint32_t b1 = *(const uint32_t*)(Ks + (jb * 8 + g) * KVSTR + kc * 16 + 2 * tig + 8);
                mma_f16(sc[jb], qf[kc][0], qf[kc][1], qf[kc][2], qf[kc][3], b0, b1);
            }
            sc[jb][0] *= 0.125f; sc[jb][1] *= 0.125f;
            sc[jb][2] *= 0.125f; sc[jb][3] *= 0.125f;
        }

        // ---- causal mask + row max ----
        float tm0 = NEG_INF, tm1 = NEG_INF;
        #pragma unroll
        for (int jb = 0; jb < 8; jb++) {
            const int c0 = j0 + jb * 8 + 2 * tig;
            const int c1 = c0 + 1;
            if (c0 > tq0) sc[jb][0] = NEG_INF;
            if (c1 > tq0) sc[jb][1] = NEG_INF;
            if (c0 > tq1) sc[jb][2] = NEG_INF;
            if (c1 > tq1) sc[jb][3] = NEG_INF;
            tm0 = fmaxf(tm0, fmaxf(sc[jb][0], sc[jb][1]));
            tm1 = fmaxf(tm1, fmaxf(sc[jb][2], sc[jb][3]));
        }
        tm0 = fmaxf(tm0, __shfl_xor_sync(0xffffffffu, tm0, 1));
        tm0 = fmaxf(tm0, __shfl_xor_sync(0xffffffffu, tm0, 2));
        tm1 = fmaxf(tm1, __shfl_xor_sync(0xffffffffu, tm1, 1));
        tm1 = fmaxf(tm1, __shfl_xor_sync(0xffffffffu, tm1, 2));

        const float mn0 = fmaxf(mr0, tm0);
        const float mn1 = fmaxf(mr1, tm1);
        const float a0 = __expf(mr0 - mn0);
        const float a1 = __expf(mr1 - mn1);
        l0 *= a0; l1 *= a1;
        #pragma unroll
        for (int nb = 0; nb < 8; nb++) {
            oacc[nb][0] *= a0; oacc[nb][1] *= a0;
            oacc[nb][2] *= a1; oacc[nb][3] *= a1;
        }

        // ---- P = exp(S - m): straight into A-fragment registers ----
        uint32_t af[4][4];
        float ps0 = 0.f, ps1 = 0.f;
        #pragma unroll
        for (int kc = 0; kc < 4; kc++) {
            const int jA = 2 * kc, jB = 2 * kc + 1;
            const float pA0 = __expf(sc[jA][0] - mn0);
            const float pA1 = __expf(sc[jA][1] - mn0);
            const float pA2 = __expf(sc[jA][2] - mn1);
            const float pA3 = __expf(sc[jA][3] - mn1);
            const float pB0 = __expf(sc[jB][0] - mn0);
            const float pB1 = __expf(sc[jB][1] - mn0);
            const float pB2 = __expf(sc[jB][2] - mn1);
            const float pB3 = __expf(sc[jB][3] - mn1);
            ps0 += (pA0 + pA1) + (pB0 + pB1);
            ps1 += (pA2 + pA3) + (pB2 + pB3);
            af[kc][0] = pack_h2(pA0, pA1);   // row g,   keys kc*16+2tig,+1
            af[kc][1] = pack_h2(pA2, pA3);   // row g+8, same keys
            af[kc][2] = pack_h2(pB0, pB1);   // row g,   keys kc*16+8+2tig,+1
            af[kc][3] = pack_h2(pB2, pB3);   // row g+8
        }
        ps0 += __shfl_xor_sync(0xffffffffu, ps0, 1);
        ps0 += __shfl_xor_sync(0xffffffffu, ps0, 2);
        ps1 += __shfl_xor_sync(0xffffffffu, ps1, 1);
        ps1 += __shfl_xor_sync(0xffffffffu, ps1, 2);
        l0 += ps0; l1 += ps1;
        mr0 = mn0; mr1 = mn1;

        // ---- PV (fp16 MMA): B packed from key-major Vs ----
        #pragma unroll
        for (int nb = 0; nb < 8; nb++) {
            #pragma unroll
            for (int kc = 0; kc < 4; kc++) {
                const int kr = kc * 16 + 2 * tig;
                const int dc = nb * 8 + g;
                const __half2 b0h = __halves2half2(Vs[(kr)     * KVSTR + dc],
                                                   Vs[(kr + 1) * KVSTR + dc]);
                const __half2 b1h = __halves2half2(Vs[(kr + 8) * KVSTR + dc],
                                                   Vs[(kr + 9) * KVSTR + dc]);
                mma_f16(oacc[nb], af[kc][0], af[kc][1], af[kc][2], af[kc][3],
                        *(const uint32_t*)&b0h, *(const uint32_t*)&b1h);
            }
        }
    }

    // ---- epilogue: normalize, half out ----
    const float inv0 = 1.0f / l0;
    const float inv1 = 1.0f / l1;
    const size_t row0 = (size_t)(b * T_ + tq0);
    const size_t row1 = (size_t)(b * T_ + tq1);
    #pragma unroll
    for (int nb = 0; nb < 8; nb++) {
        const int col = h * D_ + nb * 8 + 2 * tig;
        *(__half2*)(out + row0 * E_ + col) =
            __floats2half2_rn(oacc[nb][0] * inv0, oacc[nb][1] * inv0);
        *(__half2*)(out + row1 * E_ + col) =
            __floats2half2_rn(oacc[nb][2] * inv1, oacc[nb][3] * inv1);
    }
}

// ---------------------------------------------------------------------------
// Launch
// ---------------------------------------------------------------------------
extern "C" void kernel_launch(void* const* d_in, const int* in_sizes, int n_in,
                              void* d_out, int out_size)
{
    const float* x      = (const float*)d_in[0];
    const float* ln1_g  = (const float*)d_in[1];
    const float* ln1_b  = (const float*)d_in[2];
    const float* ln2_g  = (const float*)d_in[3];
    const float* ln2_b  = (const float*)d_in[4];
    const float* W_qkv  = (const float*)d_in[5];
    const float* b_qkv  = (const float*)d_in[6];
    const float* W_o    = (const float*)d_in[7];
    const float* b_o    = (const float*)d_in[8];
    const float* W_fc   = (const float*)d_in[9];
    const float* b_fc   = (const float*)d_in[10];
    const float* W_proj = (const float*)d_in[11];
    const float* b_proj = (const float*)d_in[12];
    float* out = (float*)d_out;

    __half *p_lnH, *p_qkvH, *p_attnH, *p_fcH;
    float *p_x1;
    uint32_t *p_wqkvP, *p_woP, *p_wfcP, *p_wprojP;
    cudaGetSymbolAddress((void**)&p_lnH,    g_lnH);
    cudaGetSymbolAddress((void**)&p_qkvH,   g_qkvH);
    cudaGetSymbolAddress((void**)&p_attnH,  g_attnH);
    cudaGetSymbolAddress((void**)&p_x1,     g_x1);
    cudaGetSymbolAddress((void**)&p_fcH,    g_fcH);
    cudaGetSymbolAddress((void**)&p_wqkvP,  g_wqkvP);
    cudaGetSymbolAddress((void**)&p_woP,    g_woP);
    cudaGetSymbolAddress((void**)&p_wfcP,   g_wfcP);
    cudaGetSymbolAddress((void**)&p_wprojP, g_wprojP);

    cudaFuncSetAttribute(gemm_h_kernel<0>, cudaFuncAttributeMaxDynamicSharedMemorySize, GEMM_H_SMEM);
    cudaFuncSetAttribute(gemm_h_kernel<1>, cudaFuncAttributeMaxDynamicSharedMemorySize, GEMM_H_SMEM);
    cudaFuncSetAttribute(gemm_h_kernel<2>, cudaFuncAttributeMaxDynamicSharedMemorySize, GEMM_H_SMEM);
    cudaFuncSetAttribute(gemm_h_kernel<3>, cudaFuncAttributeMaxDynamicSharedMemorySize, GEMM_H_SMEM);
    cudaFuncSetAttribute(attn_h_kernel,    cudaFuncAttributeMaxDynamicSharedMemorySize, ATT_SMEM);

    // weight packing
    pack_weight_h_kernel<<<dim3(QKV_N / 128, E_ / 32), 256>>>(W_qkv,  p_wqkvP,  E_,   QKV_N);
    pack_weight_h_kernel<<<dim3(E_ / 128,    E_ / 32), 256>>>(W_o,    p_woP,    E_,   E_);
    pack_weight_h_kernel<<<dim3(FC_N / 128,  E_ / 32), 256>>>(W_fc,   p_wfcP,   E_,   FC_N);
    pack_weight_h_kernel<<<dim3(E_ / 128,  FC_N / 32), 256>>>(W_proj, p_wprojP, FC_N, E_);

    // 1. ln1 = LN(x) -> half
    layernorm_kernel<<<M_, 256>>>(x, ln1_g, ln1_b, p_lnH);
    // 2. qkv = ln1 @ W_qkv + b_qkv -> half
    gemm_h_kernel<3><<<dim3(QKV_N / 128, M_ / 128), 128, GEMM_H_SMEM>>>(
        p_lnH, p_wqkvP, b_qkv, nullptr, p_qkvH, QKV_N, E_);
    // 3. attention (fp16 flash, half out)
    attn_h_kernel<<<dim3(T_ / 64, B_ * H_), 128, ATT_SMEM>>>(p_qkvH, p_attnH);
    // 4. x1 = x + attn @ W_o + b_o (fp32 out)
    gemm_h_kernel<1><<<dim3(E_ / 128, M_ / 128), 128, GEMM_H_SMEM>>>(
        p_attnH, p_woP, b_o, x, p_x1, E_, E_);
    // 5. ln2 = LN(x1) -> half
    layernorm_kernel<<<M_, 256>>>(p_x1, ln2_g, ln2_b, p_lnH);
    // 6. fc = gelu(ln2 @ W_fc + b_fc) -> half
    gemm_h_kernel<2><<<dim3(FC_N / 128, M_ / 128), 128, GEMM_H_SMEM>>>(
        p_lnH, p_wfcP, b_fc, nullptr, p_fcH, FC_N, E_);
    // 7. out = x1 + fc @ W_proj + b_proj (fp32 out)
    gemm_h_kernel<1><<<dim3(E_ / 128, M_ / 128), 128, GEMM_H_SMEM>>>(
        p_fcH, p_wprojP, b_proj, p_x1, out, E_, FC_N);
}

// round 9
// speedup vs baseline: 10.8054x; 1.0650x over previous
#include <cuda_runtime.h>
#include <cuda_fp16.h>
#include <math.h>
#include <stdint.h>

// ---------------------------------------------------------------------------
// Problem constants
// ---------------------------------------------------------------------------
#define B_  2
#define T_  2048
#define E_  1024
#define H_  16
#define D_  64
#define M_  (B_ * T_)          // 4096
#define QKV_N (3 * E_)         // 3072
#define FC_N  (4 * E_)         // 4096

// ---------------------------------------------------------------------------
// Scratch (device globals; allocations forbidden)
// ---------------------------------------------------------------------------
__device__ __half g_lnH  [(size_t)M_ * E_];
__device__ __half g_qkvH [(size_t)M_ * QKV_N];
__device__ __half g_attnH[(size_t)M_ * E_];
__device__ float  g_x1   [(size_t)M_ * E_];
__device__ __half g_fcH  [(size_t)M_ * FC_N];
__device__ uint32_t g_wqkvP [(size_t)QKV_N * E_ / 2];
__device__ uint32_t g_woP   [(size_t)E_ * E_ / 2];
__device__ uint32_t g_wfcP  [(size_t)FC_N * E_ / 2];
__device__ uint32_t g_wprojP[(size_t)E_ * FC_N / 2];

// ---------------------------------------------------------------------------
// Helpers
// ---------------------------------------------------------------------------
__device__ __forceinline__ uint32_t smem_u32(const void* p) {
    uint32_t a;
    asm("{ .reg .u64 t; cvta.to.shared.u64 t, %1; cvt.u32.u64 %0, t; }" : "=r"(a) : "l"(p));
    return a;
}
#define CP_ASYNC16(dst, src) \
    asm volatile("cp.async.cg.shared.global [%0], [%1], 16;" :: "r"(dst), "l"(src) : "memory")
#define CP_COMMIT() asm volatile("cp.async.commit_group;" ::: "memory")

__device__ __forceinline__ void ldsm_x4(uint32_t (&r)[4], uint32_t addr) {
    asm volatile("ldmatrix.sync.aligned.m8n8.x4.shared.b16 {%0,%1,%2,%3}, [%4];"
                 : "=r"(r[0]), "=r"(r[1]), "=r"(r[2]), "=r"(r[3]) : "r"(addr));
}

// fp16 MMA: m16n8k16, fp32 accumulate
__device__ __forceinline__ void mma_f16(float (&c)[4],
                                        uint32_t a0, uint32_t a1, uint32_t a2, uint32_t a3,
                                        uint32_t b0, uint32_t b1) {
    asm volatile(
        "mma.sync.aligned.m16n8k16.row.col.f32.f16.f16.f32 "
        "{%0,%1,%2,%3}, {%4,%5,%6,%7}, {%8,%9}, {%0,%1,%2,%3};"
        : "+f"(c[0]), "+f"(c[1]), "+f"(c[2]), "+f"(c[3])
        : "r"(a0), "r"(a1), "r"(a2), "r"(a3), "r"(b0), "r"(b1));
}
__device__ __forceinline__ uint32_t pack_h2(float lo, float hi) {
    const __half2 h = __floats2half2_rn(lo, hi);
    return *(const uint32_t*)&h;
}

// ---------------------------------------------------------------------------
// Weight pack (fp16), smem-staged: coalesced fp32 tile read -> smem -> gather
// to fragment-major half2 words (same output layout as Round 7/8).
// ---------------------------------------------------------------------------
__global__ void pack_weight_h_kernel(const float* __restrict__ W, uint32_t* __restrict__ Wp,
                                     int K, int N)
{
    __shared__ float ws[32][132];
    const int nt = blockIdx.x, kt = blockIdx.y;
    const int tid = threadIdx.x;               // 256
    const float* src = W + (size_t)(kt * 32) * N + nt * 128;
    #pragma unroll
    for (int i = 0; i < 4; i++) {
        const int idx = tid + i * 256;         // 0..1023
        const int r = idx >> 5, c4 = idx & 31;
        const float4 v = *(const float4*)(src + (size_t)r * N + c4 * 4);
        *(float4*)&ws[r][c4 * 4] = v;
    }
    __syncthreads();

    uint32_t* dst = Wp + ((size_t)nt * (K >> 5) + kt) * 2048;
    #pragma unroll
    for (int i = 0; i < 8; i++) {
        const int o = tid + i * 256;           // 0..2047
        const int s = o >> 6;
        const int lane = (o >> 1) & 31;
        const int reg = o & 1;
        const int kbb = s >> 4, nb = s & 15;
        const int g = lane >> 2, tig = lane & 3;
        const int k = kbb * 16 + reg * 8 + 2 * tig;
        const int n = nb * 8 + g;
        dst[o] = pack_h2(ws[k][n], ws[k + 1][n]);
    }
}

// ---------------------------------------------------------------------------
// fp16 mma.sync GEMM: 3-stage cp.async pipeline + ldmatrix A fragments.
// BM=BN=128, BK=32, 128 threads, 4 warps (2M x 2N), warp tile 64x64.
// EPI: 0=bias (fp32 C), 1=bias+res (fp32 C), 2=bias+GELU (half C), 3=bias (half C)
// ---------------------------------------------------------------------------
#define SA_STR_H   40
#define SA_H_BYTES (128 * SA_STR_H * 2)      // 10240
#define SB_H_BYTES 8192
#define BUF_H      (SA_H_BYTES + SB_H_BYTES) // 18432
#define GEMM_H_SMEM (3 * BUF_H)              // 55296

template<int EPI>
__global__ void __launch_bounds__(128, 2)
gemm_h_kernel(const __half* __restrict__ A, const uint32_t* __restrict__ Wp,
              const float* __restrict__ bias, const float* __restrict__ res,
              void* __restrict__ Cv, int N, int K)
{
    extern __shared__ char smem[];
    const uint32_t sbase = smem_u32(smem);
    float* Cf = (float*)Cv;
    __half* Ch = (__half*)Cv;

    const int tid  = threadIdx.x;
    const int wid  = tid >> 5;
    const int lane = tid & 31;
    const int g    = lane >> 2;
    const int tig  = lane & 3;
    const int wm   = (wid >> 1) * 64;
    const int wn   = (wid & 1) * 64;
    const int m0   = blockIdx.y * 128;
    const int n0   = blockIdx.x * 128;

    const int ntile = K >> 5;
    const size_t wtile0 = (size_t)blockIdx.x * ntile * 2048;

    const int am = tid >> 2;
    const int ac = tid & 3;

    // ldmatrix per-lane source coords within a 16x16 A block
    const int arow = lane & 15;
    const int acol = (lane >> 4) * 8;

    float acc[4][8][4];
    #pragma unroll
    for (int mt = 0; mt < 4; mt++)
        #pragma unroll
        for (int nb = 0; nb < 8; nb++)
            #pragma unroll
            for (int r = 0; r < 4; r++) acc[mt][nb][r] = 0.f;

    auto load_tile = [&](int buf, int kt) {
        const uint32_t sA = sbase + buf * BUF_H;
        const uint32_t sB = sA + SA_H_BYTES;
        const __half* asrc = A + (size_t)(m0 + am) * K + kt * 32 + ac * 8;
        #pragma unroll
        for (int i = 0; i < 4; i++) {
            CP_ASYNC16(sA + (uint32_t)(am + i * 32) * (SA_STR_H * 2) + ac * 16,
                       asrc + (size_t)i * 32 * K);
        }
        const uint32_t* bsrc = Wp + wtile0 + (size_t)kt * 2048 + tid * 4;
        #pragma unroll
        for (int i = 0; i < 4; i++) {
            CP_ASYNC16(sB + (uint32_t)(tid + i * 128) * 16, bsrc + i * 512);
        }
        CP_COMMIT();
    };

    load_tile(0, 0);
    if (ntile > 1) load_tile(1, 1);

    for (int t = 0; t < ntile; t++) {
        if (t + 1 < ntile) {
            asm volatile("cp.async.wait_group 1;" ::: "memory");
        } else {
            asm volatile("cp.async.wait_group 0;" ::: "memory");
        }
        __syncthreads();
        // prefetch tile t+2 into the buffer tile t-1 just vacated
        if (t + 2 < ntile) load_tile((t + 2) % 3, t + 2);

        const int cur = t % 3;
        const uint32_t sA = sbase + cur * BUF_H;
        const uint32_t* Bs = (const uint32_t*)(smem + cur * BUF_H + SA_H_BYTES);

        #pragma unroll
        for (int kbb = 0; kbb < 2; kbb++) {
            uint32_t a[4][4];
            #pragma unroll
            for (int mt = 0; mt < 4; mt++) {
                const uint32_t addr = sA +
                    (uint32_t)((wm + mt * 16 + arow) * SA_STR_H + kbb * 16 + acol) * 2;
                ldsm_x4(a[mt], addr);
            }
            #pragma unroll
            for (int nb = 0; nb < 8; nb++) {
                const int s = kbb * 16 + (wn >> 3) + nb;
                const uint2 bb = *(const uint2*)(Bs + s * 64 + lane * 2);
                #pragma unroll
                for (int mt = 0; mt < 4; mt++)
                    mma_f16(acc[mt][nb], a[mt][0], a[mt][1], a[mt][2], a[mt][3],
                            bb.x, bb.y);
            }
        }
    }

    // ---- epilogue ----
    #pragma unroll
    for (int mt = 0; mt < 4; mt++) {
        const size_t r0 = (size_t)(m0 + wm + mt * 16 + g);
        #pragma unroll
        for (int nb = 0; nb < 8; nb++) {
            const int col = n0 + wn + nb * 8 + 2 * tig;
            const float2 bv = *(const float2*)(bias + col);
            #pragma unroll
            for (int hh = 0; hh < 2; hh++) {
                const size_t row = r0 + hh * 8;
                float vx = acc[mt][nb][hh * 2 + 0] + bv.x;
                float vy = acc[mt][nb][hh * 2 + 1] + bv.y;
                if (EPI == 1) {
                    const float2 r2 = *(const float2*)(res + row * N + col);
                    vx += r2.x; vy += r2.y;
                }
                if (EPI == 2) {
                    vx = 0.5f * vx * (1.0f + erff(vx * 0.70710678118654752f));
                    vy = 0.5f * vy * (1.0f + erff(vy * 0.70710678118654752f));
                }
                if (EPI == 2 || EPI == 3) {
                    *(__half2*)(Ch + row * N + col) = __floats2half2_rn(vx, vy);
                } else {
                    float2 o2; o2.x = vx; o2.y = vy;
                    *(float2*)(Cf + row * N + col) = o2;
                }
            }
        }
    }
}

// ---------------------------------------------------------------------------
// LayerNorm: fp32 in, half out
// ---------------------------------------------------------------------------
__global__ void layernorm_kernel(const float* __restrict__ x,
                                 const float* __restrict__ gamma,
                                 const float* __restrict__ beta,
                                 __half* __restrict__ out)
{
    const int row = blockIdx.x;
    const int tid = threadIdx.x;
    const float4 xv = ((const float4*)(x + (size_t)row * E_))[tid];

    float s  = xv.x + xv.y + xv.z + xv.w;
    float ss = xv.x*xv.x + xv.y*xv.y + xv.z*xv.z + xv.w*xv.w;
    #pragma unroll
    for (int o = 16; o > 0; o >>= 1) {
        s  += __shfl_xor_sync(0xffffffffu, s,  o);
        ss += __shfl_xor_sync(0xffffffffu, ss, o);
    }
    __shared__ float sbuf[8], ssbuf[8];
    const int wid = tid >> 5, lane = tid & 31;
    if (lane == 0) { sbuf[wid] = s; ssbuf[wid] = ss; }
    __syncthreads();
    float tot = 0.f, tots = 0.f;
    #pragma unroll
    for (int i = 0; i < 8; i++) { tot += sbuf[i]; tots += ssbuf[i]; }

    const float mean = tot * (1.0f / E_);
    const float var  = tots * (1.0f / E_) - mean * mean;
    const float r    = rsqrtf(var + 1e-5f);

    const float4 gv = ((const float4*)gamma)[tid];
    const float4 bv = ((const float4*)beta)[tid];
    __half2* op = (__half2*)(out + (size_t)row * E_ + tid * 4);
    op[0] = __floats2half2_rn((xv.x - mean) * r * gv.x + bv.x,
                              (xv.y - mean) * r * gv.y + bv.y);
    op[1] = __floats2half2_rn((xv.z - mean) * r * gv.z + bv.z,
                              (xv.w - mean) * r * gv.w + bv.w);
}

// ---------------------------------------------------------------------------
// Flash attention, fully fp16 mma (unchanged from Round 8)
// ---------------------------------------------------------------------------
#define KVSTR 72
#define ATT_SMEM (3 * 64 * KVSTR * 2)   // 27648

__global__ void __launch_bounds__(128, 2)
attn_h_kernel(const __half* __restrict__ qkv, __half* __restrict__ out)
{
    extern __shared__ __half smh[];
    __half* Qs = smh;
    __half* Ks = smh + 64 * KVSTR;
    __half* Vs = smh + 128 * KVSTR;
    const uint32_t sQs = smem_u32(Qs);
    const uint32_t sKs = smem_u32(Ks);
    const uint32_t sVs = smem_u32(Vs);

    const int bh  = blockIdx.y;
    const int b   = bh >> 4;
    const int h   = bh & 15;
    const int m0  = blockIdx.x * 64;
    const int tid = threadIdx.x;
    const int wid = tid >> 5;
    const int lane = tid & 31;
    const int g    = lane >> 2;
    const int tig  = lane & 3;
    const int qr   = wid * 16;
    const float NEG_INF = __int_as_float(0xff800000);

    const size_t baseQ = ((size_t)(b * T_ + m0)) * QKV_N + h * D_;
    #pragma unroll
    for (int i = 0; i < 4; i++) {
        const int idx = tid + i * 128;
        const int r = idx >> 3, c = idx & 7;
        CP_ASYNC16(sQs + (uint32_t)(r * KVSTR + c * 8) * 2,
                   qkv + baseQ + (size_t)r * QKV_N + c * 8);
    }
    CP_COMMIT();
    asm volatile("cp.async.wait_group 0;" ::: "memory");
    __syncthreads();

    uint32_t qf[4][4];
    #pragma unroll
    for (int kc = 0; kc < 4; kc++) {
        qf[kc][0] = *(const uint32_t*)(Qs + (qr + g)     * KVSTR + kc * 16 + 2 * tig);
        qf[kc][1] = *(const uint32_t*)(Qs + (qr + g + 8) * KVSTR + kc * 16 + 2 * tig);
        qf[kc][2] = *(const uint32_t*)(Qs + (qr + g)     * KVSTR + kc * 16 + 2 * tig + 8);
        qf[kc][3] = *(const uint32_t*)(Qs + (qr + g + 8) * KVSTR + kc * 16 + 2 * tig + 8);
    }

    float oacc[8][4];
    #pragma unroll
    for (int nb = 0; nb < 8; nb++)
        #pragma unroll
        for (int r = 0; r < 4; r++) oacc[nb][r] = 0.f;
    float mr0 = NEG_INF, mr1 = NEG_INF, l0 = 0.f, l1 = 0.f;

    const int tq0 = m0 + qr + g;
    const int tq1 = tq0 + 8;
    const int ntile = (m0 >> 6) + 1;

    for (int t = 0; t < ntile; t++) {
        const int j0 = t * 64;
        __syncthreads();

        const size_t baseK = ((size_t)(b * T_ + j0)) * QKV_N + E_ + h * D_;
        #pragma unroll
        for (int i = 0; i < 4; i++) {
            const int idx = tid + i * 128;
            const int r = idx >> 3, c = idx & 7;
            const __half* src = qkv + baseK + (size_t)r * QKV_N + c * 8;
            CP_ASYNC16(sKs + (uint32_t)(r * KVSTR + c * 8) * 2, src);
            CP_ASYNC16(sVs + (uint32_t)(r * KVSTR + c * 8) * 2, src + E_);
        }
        CP_COMMIT();
        asm volatile("cp.async.wait_group 0;" ::: "memory");
        __syncthreads();

        float sc[8][4];
        #pragma unroll
        for (int jb = 0; jb < 8; jb++) {
            sc[jb][0] = sc[jb][1] = sc[jb][2] = sc[jb][3] = 0.f;
            #pragma unroll
            for (int kc = 0; kc < 4; kc++) {
                const uint32_t b0 = *(const uint32_t*)(Ks + (jb * 8 + g) * KVSTR + kc * 16 + 2 * tig);
                const uint32_t b1 = *(const uint32_t*)(Ks + (jb * 8 + g) * KVSTR + kc * 16 + 2 * tig + 8);
                mma_f16(sc[jb], qf[kc][0], qf[kc][1], qf[kc][2], qf[kc][3], b0, b1);
            }
            sc[jb][0] *= 0.125f; sc[jb][1] *= 0.125f;
            sc[jb][2] *= 0.125f; sc[jb][3] *= 0.125f;
        }

        float tm0 = NEG_INF, tm1 = NEG_INF;
        #pragma unroll
        for (int jb = 0; jb < 8; jb++) {
            const int c0 = j0 + jb * 8 + 2 * tig;
            const int c1 = c0 + 1;
            if (c0 > tq0) sc[jb][0] = NEG_INF;
            if (c1 > tq0) sc[jb][1] = NEG_INF;
            if (c0 > tq1) sc[jb][2] = NEG_INF;
            if (c1 > tq1) sc[jb][3] = NEG_INF;
            tm0 = fmaxf(tm0, fmaxf(sc[jb][0], sc[jb][1]));
            tm1 = fmaxf(tm1, fmaxf(sc[jb][2], sc[jb][3]));
        }
        tm0 = fmaxf(tm0, __shfl_xor_sync(0xffffffffu, tm0, 1));
        tm0 = fmaxf(tm0, __shfl_xor_sync(0xffffffffu, tm0, 2));
        tm1 = fmaxf(tm1, __shfl_xor_sync(0xffffffffu, tm1, 1));
        tm1 = fmaxf(tm1, __shfl_xor_sync(0xffffffffu, tm1, 2));

        const float mn0 = fmaxf(mr0, tm0);
        const float mn1 = fmaxf(mr1, tm1);
        const float a0 = __expf(mr0 - mn0);
        const float a1 = __expf(mr1 - mn1);
        l0 *= a0; l1 *= a1;
        #pragma unroll
        for (int nb = 0; nb < 8; nb++) {
            oacc[nb][0] *= a0; oacc[nb][1] *= a0;
            oacc[nb][2] *= a1; oacc[nb][3] *= a1;
        }

        uint32_t af[4][4];
        float ps0 = 0.f, ps1 = 0.f;
        #pragma unroll
        for (int kc = 0; kc < 4; kc++) {
            const int jA = 2 * kc, jB = 2 * kc + 1;
            const float pA0 = __expf(sc[jA][0] - mn0);
            const float pA1 = __expf(sc[jA][1] - mn0);
            const float pA2 = __expf(sc[jA][2] - mn1);
            const float pA3 = __expf(sc[jA][3] - mn1);
            const float pB0 = __expf(sc[jB][0] - mn0);
            const float pB1 = __expf(sc[jB][1] - mn0);
            const float pB2 = __expf(sc[jB][2] - mn1);
            const float pB3 = __expf(sc[jB][3] - mn1);
            ps0 += (pA0 + pA1) + (pB0 + pB1);
            ps1 += (pA2 + pA3) + (pB2 + pB3);
            af[kc][0] = pack_h2(pA0, pA1);
            af[kc][1] = pack_h2(pA2, pA3);
            af[kc][2] = pack_h2(pB0, pB1);
            af[kc][3] = pack_h2(pB2, pB3);
        }
        ps0 += __shfl_xor_sync(0xffffffffu, ps0, 1);
        ps0 += __shfl_xor_sync(0xffffffffu, ps0, 2);
        ps1 += __shfl_xor_sync(0xffffffffu, ps1, 1);
        ps1 += __shfl_xor_sync(0xffffffffu, ps1, 2);
        l0 += ps0; l1 += ps1;
        mr0 = mn0; mr1 = mn1;

        #pragma unroll
        for (int nb = 0; nb < 8; nb++) {
            #pragma unroll
            for (int kc = 0; kc < 4; kc++) {
                const int kr = kc * 16 + 2 * tig;
                const int dc = nb * 8 + g;
                const __half2 b0h = __halves2half2(Vs[(kr)     * KVSTR + dc],
                                                   Vs[(kr + 1) * KVSTR + dc]);
                const __half2 b1h = __halves2half2(Vs[(kr + 8) * KVSTR + dc],
                                                   Vs[(kr + 9) * KVSTR + dc]);
                mma_f16(oacc[nb], af[kc][0], af[kc][1], af[kc][2], af[kc][3],
                        *(const uint32_t*)&b0h, *(const uint32_t*)&b1h);
            }
        }
    }

    const float inv0 = 1.0f / l0;
    const float inv1 = 1.0f / l1;
    const size_t row0 = (size_t)(b * T_ + tq0);
    const size_t row1 = (size_t)(b * T_ + tq1);
    #pragma unroll
    for (int nb = 0; nb < 8; nb++) {
        const int col = h * D_ + nb * 8 + 2 * tig;
        *(__half2*)(out + row0 * E_ + col) =
            __floats2half2_rn(oacc[nb][0] * inv0, oacc[nb][1] * inv0);
        *(__half2*)(out + row1 * E_ + col) =
            __floats2half2_rn(oacc[nb][2] * inv1, oacc[nb][3] * inv1);
    }
}

// ---------------------------------------------------------------------------
// Launch
// ---------------------------------------------------------------------------
extern "C" void kernel_launch(void* const* d_in, const int* in_sizes, int n_in,
                              void* d_out, int out_size)
{
    const float* x      = (const float*)d_in[0];
    const float* ln1_g  = (const float*)d_in[1];
    const float* ln1_b  = (const float*)d_in[2];
    const float* ln2_g  = (const float*)d_in[3];
    const float* ln2_b  = (const float*)d_in[4];
    const float* W_qkv  = (const float*)d_in[5];
    const float* b_qkv  = (const float*)d_in[6];
    const float* W_o    = (const float*)d_in[7];
    const float* b_o    = (const float*)d_in[8];
    const float* W_fc   = (const float*)d_in[9];
    const float* b_fc   = (const float*)d_in[10];
    const float* W_proj = (const float*)d_in[11];
    const float* b_proj = (const float*)d_in[12];
    float* out = (float*)d_out;

    __half *p_lnH, *p_qkvH, *p_attnH, *p_fcH;
    float *p_x1;
    uint32_t *p_wqkvP, *p_woP, *p_wfcP, *p_wprojP;
    cudaGetSymbolAddress((void**)&p_lnH,    g_lnH);
    cudaGetSymbolAddress((void**)&p_qkvH,   g_qkvH);
    cudaGetSymbolAddress((void**)&p_attnH,  g_attnH);
    cudaGetSymbolAddress((void**)&p_x1,     g_x1);
    cudaGetSymbolAddress((void**)&p_fcH,    g_fcH);
    cudaGetSymbolAddress((void**)&p_wqkvP,  g_wqkvP);
    cudaGetSymbolAddress((void**)&p_woP,    g_woP);
    cudaGetSymbolAddress((void**)&p_wfcP,   g_wfcP);
    cudaGetSymbolAddress((void**)&p_wprojP, g_wprojP);

    cudaFuncSetAttribute(gemm_h_kernel<0>, cudaFuncAttributeMaxDynamicSharedMemorySize, GEMM_H_SMEM);
    cudaFuncSetAttribute(gemm_h_kernel<1>, cudaFuncAttributeMaxDynamicSharedMemorySize, GEMM_H_SMEM);
    cudaFuncSetAttribute(gemm_h_kernel<2>, cudaFuncAttributeMaxDynamicSharedMemorySize, GEMM_H_SMEM);
    cudaFuncSetAttribute(gemm_h_kernel<3>, cudaFuncAttributeMaxDynamicSharedMemorySize, GEMM_H_SMEM);
    cudaFuncSetAttribute(attn_h_kernel,    cudaFuncAttributeMaxDynamicSharedMemorySize, ATT_SMEM);

    // weight packing (smem-staged, coalesced)
    pack_weight_h_kernel<<<dim3(QKV_N / 128, E_ / 32), 256>>>(W_qkv,  p_wqkvP,  E_,   QKV_N);
    pack_weight_h_kernel<<<dim3(E_ / 128,    E_ / 32), 256>>>(W_o,    p_woP,    E_,   E_);
    pack_weight_h_kernel<<<dim3(FC_N / 128,  E_ / 32), 256>>>(W_fc,   p_wfcP,   E_,   FC_N);
    pack_weight_h_kernel<<<dim3(E_ / 128,  FC_N / 32), 256>>>(W_proj, p_wprojP, FC_N, E_);

    // 1. ln1 = LN(x) -> half
    layernorm_kernel<<<M_, 256>>>(x, ln1_g, ln1_b, p_lnH);
    // 2. qkv = ln1 @ W_qkv + b_qkv -> half
    gemm_h_kernel<3><<<dim3(QKV_N / 128, M_ / 128), 128, GEMM_H_SMEM>>>(
        p_lnH, p_wqkvP, b_qkv, nullptr, p_qkvH, QKV_N, E_);
    // 3. attention (fp16 flash, half out)
    attn_h_kernel<<<dim3(T_ / 64, B_ * H_), 128, ATT_SMEM>>>(p_qkvH, p_attnH);
    // 4. x1 = x + attn @ W_o + b_o (fp32 out)
    gemm_h_kernel<1><<<dim3(E_ / 128, M_ / 128), 128, GEMM_H_SMEM>>>(
        p_attnH, p_woP, b_o, x, p_x1, E_, E_);
    // 5. ln2 = LN(x1) -> half
    layernorm_kernel<<<M_, 256>>>(p_x1, ln2_g, ln2_b, p_lnH);
    // 6. fc = gelu(ln2 @ W_fc + b_fc) -> half
    gemm_h_kernel<2><<<dim3(FC_N / 128, M_ / 128), 128, GEMM_H_SMEM>>>(
        p_lnH, p_wfcP, b_fc, nullptr, p_fcH, FC_N, E_);
    // 7. out = x1 + fc @ W_proj + b_proj (fp32 out)
    gemm_h_kernel<1><<<dim3(E_ / 128, M_ / 128), 128, GEMM_H_SMEM>>>(
        p_fcH, p_wprojP, b_proj, p_x1, out, E_, FC_N);
}

// round 10
// speedup vs baseline: 11.0716x; 1.0246x over previous
#include <cuda_runtime.h>
#include <cuda_fp16.h>
#include <math.h>
#include <stdint.h>

// ---------------------------------------------------------------------------
// Problem constants
// ---------------------------------------------------------------------------
#define B_  2
#define T_  2048
#define E_  1024
#define H_  16
#define D_  64
#define M_  (B_ * T_)          // 4096
#define QKV_N (3 * E_)         // 3072
#define FC_N  (4 * E_)         // 4096

// ---------------------------------------------------------------------------
// Scratch (device globals; allocations forbidden)
// ---------------------------------------------------------------------------
__device__ __half g_lnH  [(size_t)M_ * E_];
__device__ __half g_qkvH [(size_t)M_ * QKV_N];
__device__ __half g_attnH[(size_t)M_ * E_];
__device__ float  g_x1   [(size_t)M_ * E_];
__device__ __half g_fcH  [(size_t)M_ * FC_N];
__device__ uint32_t g_wqkvP [(size_t)QKV_N * E_ / 2];
__device__ uint32_t g_woP   [(size_t)E_ * E_ / 2];
__device__ uint32_t g_wfcP  [(size_t)FC_N * E_ / 2];
__device__ uint32_t g_wprojP[(size_t)E_ * FC_N / 2];

// ---------------------------------------------------------------------------
// Helpers
// ---------------------------------------------------------------------------
__device__ __forceinline__ uint32_t smem_u32(const void* p) {
    uint32_t a;
    asm("{ .reg .u64 t; cvta.to.shared.u64 t, %1; cvt.u32.u64 %0, t; }" : "=r"(a) : "l"(p));
    return a;
}
#define CP_ASYNC16(dst, src) \
    asm volatile("cp.async.cg.shared.global [%0], [%1], 16;" :: "r"(dst), "l"(src) : "memory")
#define CP_COMMIT() asm volatile("cp.async.commit_group;" ::: "memory")

__device__ __forceinline__ void ldsm_x4(uint32_t (&r)[4], uint32_t addr) {
    asm volatile("ldmatrix.sync.aligned.m8n8.x4.shared.b16 {%0,%1,%2,%3}, [%4];"
                 : "=r"(r[0]), "=r"(r[1]), "=r"(r[2]), "=r"(r[3]) : "r"(addr));
}

// fp16 MMA: m16n8k16, fp32 accumulate
__device__ __forceinline__ void mma_f16(float (&c)[4],
                                        uint32_t a0, uint32_t a1, uint32_t a2, uint32_t a3,
                                        uint32_t b0, uint32_t b1) {
    asm volatile(
        "mma.sync.aligned.m16n8k16.row.col.f32.f16.f16.f32 "
        "{%0,%1,%2,%3}, {%4,%5,%6,%7}, {%8,%9}, {%0,%1,%2,%3};"
        : "+f"(c[0]), "+f"(c[1]), "+f"(c[2]), "+f"(c[3])
        : "r"(a0), "r"(a1), "r"(a2), "r"(a3), "r"(b0), "r"(b1));
}
__device__ __forceinline__ uint32_t pack_h2(float lo, float hi) {
    const __half2 h = __floats2half2_rn(lo, hi);
    return *(const uint32_t*)&h;
}

// ---------------------------------------------------------------------------
// Merged weight pack: all 4 matrices in one launch (3072 blocks total).
// Same per-tile fragment layout as Rounds 7-9; smem-staged coalesced reads.
// Block ranges: [0,768) qkv | [768,1024) W_o | [1024,2048) W_fc | [2048,3072) W_proj
// ---------------------------------------------------------------------------
__global__ void pack_all_kernel(const float* __restrict__ W0, uint32_t* __restrict__ P0,
                                const float* __restrict__ W1, uint32_t* __restrict__ P1,
                                const float* __restrict__ W2, uint32_t* __restrict__ P2,
                                const float* __restrict__ W3, uint32_t* __restrict__ P3)
{
    __shared__ float ws[32][132];
    const int bid = blockIdx.x;
    const int tid = threadIdx.x;               // 256

    const float* W; uint32_t* Wp; int N, ntx, nkt, r;
    if (bid < 768)       { W = W0; Wp = P0; N = QKV_N; ntx = 24; nkt = 32;  r = bid; }
    else if (bid < 1024) { W = W1; Wp = P1; N = E_;    ntx = 8;  nkt = 32;  r = bid - 768; }
    else if (bid < 2048) { W = W2; Wp = P2; N = FC_N;  ntx = 32; nkt = 32;  r = bid - 1024; }
    else                 { W = W3; Wp = P3; N = E_;    ntx = 8;  nkt = 128; r = bid - 2048; }
    const int nt = r % ntx;
    const int kt = r / ntx;

    const float* src = W + (size_t)(kt * 32) * N + nt * 128;
    #pragma unroll
    for (int i = 0; i < 4; i++) {
        const int idx = tid + i * 256;
        const int rr = idx >> 5, c4 = idx & 31;
        *(float4*)&ws[rr][c4 * 4] = *(const float4*)(src + (size_t)rr * N + c4 * 4);
    }
    __syncthreads();

    uint32_t* dst = Wp + ((size_t)nt * nkt + kt) * 2048;
    #pragma unroll
    for (int i = 0; i < 8; i++) {
        const int o = tid + i * 256;
        const int s = o >> 6;
        const int lane = (o >> 1) & 31;
        const int reg = o & 1;
        const int kbb = s >> 4, nb = s & 15;
        const int g = lane >> 2, tig = lane & 3;
        const int k = kbb * 16 + reg * 8 + 2 * tig;
        const int n = nb * 8 + g;
        dst[o] = pack_h2(ws[k][n], ws[k + 1][n]);
    }
}

// ---------------------------------------------------------------------------
// fp16 mma.sync GEMM: BK=64 per stage, 2-stage cp.async, ldmatrix A fragments.
// BM=BN=128, 128 threads, 4 warps (2M x 2N), warp tile 64x64.
// EPI: 0=bias (fp32 C), 1=bias+res (fp32 C), 2=bias+GELU (half C), 3=bias (half C)
// ---------------------------------------------------------------------------
#define SA_STR_H   72                        // halfs per A smem row (64 + 8 pad)
#define SA_H_BYTES (128 * SA_STR_H * 2)      // 18432
#define SB_H_BYTES 16384                     // 64k x 128n halfs (two packed 32-k tiles)
#define BUF_H      (SA_H_BYTES + SB_H_BYTES) // 34816
#define GEMM_H_SMEM (2 * BUF_H)              // 69632

template<int EPI>
__global__ void __launch_bounds__(128, 2)
gemm_h_kernel(const __half* __restrict__ A, const uint32_t* __restrict__ Wp,
              const float* __restrict__ bias, const float* __restrict__ res,
              void* __restrict__ Cv, int N, int K)
{
    extern __shared__ char smem[];
    const uint32_t sbase = smem_u32(smem);
    float* Cf = (float*)Cv;
    __half* Ch = (__half*)Cv;

    const int tid  = threadIdx.x;
    const int wid  = tid >> 5;
    const int lane = tid & 31;
    const int g    = lane >> 2;
    const int tig  = lane & 3;
    const int wm   = (wid >> 1) * 64;
    const int wn   = (wid & 1) * 64;
    const int m0   = blockIdx.y * 128;
    const int n0   = blockIdx.x * 128;

    const int ntile = K >> 6;                                  // 64-k tiles
    const size_t wtile0 = (size_t)blockIdx.x * (K >> 5) * 2048;

    // A copy coords: 1024 chunks of 16B (128 rows x 8 chunks), 8 per thread
    const int am = tid >> 3;               // 0..15 (+16*i)
    const int ac = tid & 7;                // chunk within 64-half row

    // ldmatrix per-lane source coords within a 16x16 A block
    const int arow = lane & 15;
    const int acol = (lane >> 4) * 8;

    float acc[4][8][4];
    #pragma unroll
    for (int mt = 0; mt < 4; mt++)
        #pragma unroll
        for (int nb = 0; nb < 8; nb++)
            #pragma unroll
            for (int r = 0; r < 4; r++) acc[mt][nb][r] = 0.f;

    auto load_tile = [&](int buf, int kt) {
        const uint32_t sA = sbase + buf * BUF_H;
        const uint32_t sB = sA + SA_H_BYTES;
        const __half* asrc = A + (size_t)(m0 + am) * K + kt * 64 + ac * 8;
        #pragma unroll
        for (int i = 0; i < 8; i++) {
            CP_ASYNC16(sA + (uint32_t)(am + i * 16) * (SA_STR_H * 2) + ac * 16,
                       asrc + (size_t)i * 16 * K);
        }
        const uint32_t* bsrc = Wp + wtile0 + (size_t)kt * 4096 + tid * 4;
        #pragma unroll
        for (int i = 0; i < 8; i++) {
            CP_ASYNC16(sB + (uint32_t)(tid + i * 128) * 16, bsrc + i * 512);
        }
        CP_COMMIT();
    };

    load_tile(0, 0);

    for (int t = 0; t < ntile; t++) {
        const int cur = t & 1;
        if (t + 1 < ntile) {
            load_tile(cur ^ 1, t + 1);
            asm volatile("cp.async.wait_group 1;" ::: "memory");
        } else {
            asm volatile("cp.async.wait_group 0;" ::: "memory");
        }
        __syncthreads();

        const uint32_t sA = sbase + cur * BUF_H;
        const uint32_t* Bs = (const uint32_t*)(smem + cur * BUF_H + SA_H_BYTES);

        #pragma unroll
        for (int kbb = 0; kbb < 4; kbb++) {
            uint32_t a[4][4];
            #pragma unroll
            for (int mt = 0; mt < 4; mt++) {
                const uint32_t addr = sA +
                    (uint32_t)((wm + mt * 16 + arow) * SA_STR_H + kbb * 16 + acol) * 2;
                ldsm_x4(a[mt], addr);
            }
            const uint32_t* Bsub = Bs + (kbb >> 1) * 2048;
            #pragma unroll
            for (int nb = 0; nb < 8; nb++) {
                const int s = (kbb & 1) * 16 + (wn >> 3) + nb;
                const uint2 bb = *(const uint2*)(Bsub + s * 64 + lane * 2);
                #pragma unroll
                for (int mt = 0; mt < 4; mt++)
                    mma_f16(acc[mt][nb], a[mt][0], a[mt][1], a[mt][2], a[mt][3],
                            bb.x, bb.y);
            }
        }
        __syncthreads();
    }

    // ---- epilogue ----
    #pragma unroll
    for (int mt = 0; mt < 4; mt++) {
        const size_t r0 = (size_t)(m0 + wm + mt * 16 + g);
        #pragma unroll
        for (int nb = 0; nb < 8; nb++) {
            const int col = n0 + wn + nb * 8 + 2 * tig;
            const float2 bv = *(const float2*)(bias + col);
            #pragma unroll
            for (int hh = 0; hh < 2; hh++) {
                const size_t row = r0 + hh * 8;
                float vx = acc[mt][nb][hh * 2 + 0] + bv.x;
                float vy = acc[mt][nb][hh * 2 + 1] + bv.y;
                if (EPI == 1) {
                    const float2 r2 = *(const float2*)(res + row * N + col);
                    vx += r2.x; vy += r2.y;
                }
                if (EPI == 2) {
                    vx = 0.5f * vx * (1.0f + erff(vx * 0.70710678118654752f));
                    vy = 0.5f * vy * (1.0f + erff(vy * 0.70710678118654752f));
                }
                if (EPI == 2 || EPI == 3) {
                    *(__half2*)(Ch + row * N + col) = __floats2half2_rn(vx, vy);
                } else {
                    float2 o2; o2.x = vx; o2.y = vy;
                    *(float2*)(Cf + row * N + col) = o2;
                }
            }
        }
    }
}

// ---------------------------------------------------------------------------
// LayerNorm: warp-per-row (no smem, no block sync). Block 256 = 8 rows.
// ---------------------------------------------------------------------------
__global__ void layernorm_kernel(const float* __restrict__ x,
                                 const float* __restrict__ gamma,
                                 const float* __restrict__ beta,
                                 __half* __restrict__ out)
{
    const int wid  = threadIdx.x >> 5;
    const int lane = threadIdx.x & 31;
    const int row  = blockIdx.x * 8 + wid;

    const float4* xr = (const float4*)(x + (size_t)row * E_);
    float4 v[8];
    float s = 0.f, ss = 0.f;
    #pragma unroll
    for (int i = 0; i < 8; i++) {
        v[i] = xr[lane + 32 * i];
        s  += (v[i].x + v[i].y) + (v[i].z + v[i].w);
        ss += (v[i].x * v[i].x + v[i].y * v[i].y) + (v[i].z * v[i].z + v[i].w * v[i].w);
    }
    #pragma unroll
    for (int o = 16; o > 0; o >>= 1) {
        s  += __shfl_xor_sync(0xffffffffu, s,  o);
        ss += __shfl_xor_sync(0xffffffffu, ss, o);
    }
    const float mean = s * (1.0f / E_);
    const float var  = ss * (1.0f / E_) - mean * mean;
    const float r    = rsqrtf(var + 1e-5f);

    const float4* gp = (const float4*)gamma;
    const float4* bp = (const float4*)beta;
    __half2* op = (__half2*)(out + (size_t)row * E_);
    #pragma unroll
    for (int i = 0; i < 8; i++) {
        const int c4 = lane + 32 * i;
        const float4 gv = gp[c4];
        const float4 bv = bp[c4];
        op[c4 * 2 + 0] = __floats2half2_rn((v[i].x - mean) * r * gv.x + bv.x,
                                           (v[i].y - mean) * r * gv.y + bv.y);
        op[c4 * 2 + 1] = __floats2half2_rn((v[i].z - mean) * r * gv.z + bv.z,
                                           (v[i].w - mean) * r * gv.w + bv.w);
    }
}

// ---------------------------------------------------------------------------
// Flash attention, fully fp16 mma (unchanged from Round 8/9)
// ---------------------------------------------------------------------------
#define KVSTR 72
#define ATT_SMEM (3 * 64 * KVSTR * 2)   // 27648

__global__ void __launch_bounds__(128, 2)
attn_h_kernel(const __half* __restrict__ qkv, __half* __restrict__ out)
{
    extern __shared__ __half smh[];
    __half* Qs = smh;
    __half* Ks = smh + 64 * KVSTR;
    __half* Vs = smh + 128 * KVSTR;
    const uint32_t sQs = smem_u32(Qs);
    const uint32_t sKs = smem_u32(Ks);
    const uint32_t sVs = smem_u32(Vs);

    const int bh  = blockIdx.y;
    const int b   = bh >> 4;
    const int h   = bh & 15;
    const int m0  = blockIdx.x * 64;
    const int tid = threadIdx.x;
    const int wid = tid >> 5;
    const int lane = tid & 31;
    const int g    = lane >> 2;
    const int tig  = lane & 3;
    const int qr   = wid * 16;
    const float NEG_INF = __int_as_float(0xff800000);

    const size_t baseQ = ((size_t)(b * T_ + m0)) * QKV_N + h * D_;
    #pragma unroll
    for (int i = 0; i < 4; i++) {
        const int idx = tid + i * 128;
        const int r = idx >> 3, c = idx & 7;
        CP_ASYNC16(sQs + (uint32_t)(r * KVSTR + c * 8) * 2,
                   qkv + baseQ + (size_t)r * QKV_N + c * 8);
    }
    CP_COMMIT();
    asm volatile("cp.async.wait_group 0;" ::: "memory");
    __syncthreads();

    uint32_t qf[4][4];
    #pragma unroll
    for (int kc = 0; kc < 4; kc++) {
        qf[kc][0] = *(const uint32_t*)(Qs + (qr + g)     * KVSTR + kc * 16 + 2 * tig);
        qf[kc][1] = *(const uint32_t*)(Qs + (qr + g + 8) * KVSTR + kc * 16 + 2 * tig);
        qf[kc][2] = *(const uint32_t*)(Qs + (qr + g)     * KVSTR + kc * 16 + 2 * tig + 8);
        qf[kc][3] = *(const uint32_t*)(Qs + (qr + g + 8) * KVSTR + kc * 16 + 2 * tig + 8);
    }

    float oacc[8][4];
    #pragma unroll
    for (int nb = 0; nb < 8; nb++)
        #pragma unroll
        for (int r = 0; r < 4; r++) oacc[nb][r] = 0.f;
    float mr0 = NEG_INF, mr1 = NEG_INF, l0 = 0.f, l1 = 0.f;

    const int tq0 = m0 + qr + g;
    const int tq1 = tq0 + 8;
    const int ntile = (m0 >> 6) + 1;

    for (int t = 0; t < ntile; t++) {
        const int j0 = t * 64;
        __syncthreads();

        const size_t baseK = ((size_t)(b * T_ + j0)) * QKV_N + E_ + h * D_;
        #pragma unroll
        for (int i = 0; i < 4; i++) {
            const int idx = tid + i * 128;
            const int r = idx >> 3, c = idx & 7;
            const __half* src = qkv + baseK + (size_t)r * QKV_N + c * 8;
            CP_ASYNC16(sKs + (uint32_t)(r * KVSTR + c * 8) * 2, src);
            CP_ASYNC16(sVs + (uint32_t)(r * KVSTR + c * 8) * 2, src + E_);
        }
        CP_COMMIT();
        asm volatile("cp.async.wait_group 0;" ::: "memory");
        __syncthreads();

        float sc[8][4];
        #pragma unroll
        for (int jb = 0; jb < 8; jb++) {
            sc[jb][0] = sc[jb][1] = sc[jb][2] = sc[jb][3] = 0.f;
            #pragma unroll
            for (int kc = 0; kc < 4; kc++) {
                const uint32_t b0 = *(const uint32_t*)(Ks + (jb * 8 + g) * KVSTR + kc * 16 + 2 * tig);
                const uint32_t b1 = *(const uint32_t*)(Ks + (jb * 8 + g) * KVSTR + kc * 16 + 2 * tig + 8);
                mma_f16(sc[jb], qf[kc][0], qf[kc][1], qf[kc][2], qf[kc][3], b0, b1);
            }
            sc[jb][0] *= 0.125f; sc[jb][1] *= 0.125f;
            sc[jb][2] *= 0.125f; sc[jb][3] *= 0.125f;
        }

        float tm0 = NEG_INF, tm1 = NEG_INF;
        #pragma unroll
        for (int jb = 0; jb < 8; jb++) {
            const int c0 = j0 + jb * 8 + 2 * tig;
            const int c1 = c0 + 1;
            if (c0 > tq0) sc[jb][0] = NEG_INF;
            if (c1 > tq0) sc[jb][1] = NEG_INF;
            if (c0 > tq1) sc[jb][2] = NEG_INF;
            if (c1 > tq1) sc[jb][3] = NEG_INF;
            tm0 = fmaxf(tm0, fmaxf(sc[jb][0], sc[jb][1]));
            tm1 = fmaxf(tm1, fmaxf(sc[jb][2], sc[jb][3]));
        }
        tm0 = fmaxf(tm0, __shfl_xor_sync(0xffffffffu, tm0, 1));
        tm0 = fmaxf(tm0, __shfl_xor_sync(0xffffffffu, tm0, 2));
        tm1 = fmaxf(tm1, __shfl_xor_sync(0xffffffffu, tm1, 1));
        tm1 = fmaxf(tm1, __shfl_xor_sync(0xffffffffu, tm1, 2));

        const float mn0 = fmaxf(mr0, tm0);
        const float mn1 = fmaxf(mr1, tm1);
        const float a0 = __expf(mr0 - mn0);
        const float a1 = __expf(mr1 - mn1);
        l0 *= a0; l1 *= a1;
        #pragma unroll
        for (int nb = 0; nb < 8; nb++) {
            oacc[nb][0] *= a0; oacc[nb][1] *= a0;
            oacc[nb][2] *= a1; oacc[nb][3] *= a1;
        }

        uint32_t af[4][4];
        float ps0 = 0.f, ps1 = 0.f;
        #pragma unroll
        for (int kc = 0; kc < 4; kc++) {
            const int jA = 2 * kc, jB = 2 * kc + 1;
            const float pA0 = __expf(sc[jA][0] - mn0);
            const float pA1 = __expf(sc[jA][1] - mn0);
            const float pA2 = __expf(sc[jA][2] - mn1);
            const float pA3 = __expf(sc[jA][3] - mn1);
            const float pB0 = __expf(sc[jB][0] - mn0);
            const float pB1 = __expf(sc[jB][1] - mn0);
            const float pB2 = __expf(sc[jB][2] - mn1);
            const float pB3 = __expf(sc[jB][3] - mn1);
            ps0 += (pA0 + pA1) + (pB0 + pB1);
            ps1 += (pA2 + pA3) + (pB2 + pB3);
            af[kc][0] = pack_h2(pA0, pA1);
            af[kc][1] = pack_h2(pA2, pA3);
            af[kc][2] = pack_h2(pB0, pB1);
            af[kc][3] = pack_h2(pB2, pB3);
        }
        ps0 += __shfl_xor_sync(0xffffffffu, ps0, 1);
        ps0 += __shfl_xor_sync(0xffffffffu, ps0, 2);
        ps1 += __shfl_xor_sync(0xffffffffu, ps1, 1);
        ps1 += __shfl_xor_sync(0xffffffffu, ps1, 2);
        l0 += ps0; l1 += ps1;
        mr0 = mn0; mr1 = mn1;

        #pragma unroll
        for (int nb = 0; nb < 8; nb++) {
            #pragma unroll
            for (int kc = 0; kc < 4; kc++) {
                const int kr = kc * 16 + 2 * tig;
                const int dc = nb * 8 + g;
                const __half2 b0h = __halves2half2(Vs[(kr)     * KVSTR + dc],
                                                   Vs[(kr + 1) * KVSTR + dc]);
                const __half2 b1h = __halves2half2(Vs[(kr + 8) * KVSTR + dc],
                                                   Vs[(kr + 9) * KVSTR + dc]);
                mma_f16(oacc[nb], af[kc][0], af[kc][1], af[kc][2], af[kc][3],
                        *(const uint32_t*)&b0h, *(const uint32_t*)&b1h);
            }
        }
    }

    const float inv0 = 1.0f / l0;
    const float inv1 = 1.0f / l1;
    const size_t row0 = (size_t)(b * T_ + tq0);
    const size_t row1 = (size_t)(b * T_ + tq1);
    #pragma unroll
    for (int nb = 0; nb < 8; nb++) {
        const int col = h * D_ + nb * 8 + 2 * tig;
        *(__half2*)(out + row0 * E_ + col) =
            __floats2half2_rn(oacc[nb][0] * inv0, oacc[nb][1] * inv0);
        *(__half2*)(out + row1 * E_ + col) =
            __floats2half2_rn(oacc[nb][2] * inv1, oacc[nb][3] * inv1);
    }
}

// ---------------------------------------------------------------------------
// Launch
// ---------------------------------------------------------------------------
extern "C" void kernel_launch(void* const* d_in, const int* in_sizes, int n_in,
                              void* d_out, int out_size)
{
    const float* x      = (const float*)d_in[0];
    const float* ln1_g  = (const float*)d_in[1];
    const float* ln1_b  = (const float*)d_in[2];
    const float* ln2_g  = (const float*)d_in[3];
    const float* ln2_b  = (const float*)d_in[4];
    const float* W_qkv  = (const float*)d_in[5];
    const float* b_qkv  = (const float*)d_in[6];
    const float* W_o    = (const float*)d_in[7];
    const float* b_o    = (const float*)d_in[8];
    const float* W_fc   = (const float*)d_in[9];
    const float* b_fc   = (const float*)d_in[10];
    const float* W_proj = (const float*)d_in[11];
    const float* b_proj = (const float*)d_in[12];
    float* out = (float*)d_out;

    __half *p_lnH, *p_qkvH, *p_attnH, *p_fcH;
    float *p_x1;
    uint32_t *p_wqkvP, *p_woP, *p_wfcP, *p_wprojP;
    cudaGetSymbolAddress((void**)&p_lnH,    g_lnH);
    cudaGetSymbolAddress((void**)&p_qkvH,   g_qkvH);
    cudaGetSymbolAddress((void**)&p_attnH,  g_attnH);
    cudaGetSymbolAddress((void**)&p_x1,     g_x1);
    cudaGetSymbolAddress((void**)&p_fcH,    g_fcH);
    cudaGetSymbolAddress((void**)&p_wqkvP,  g_wqkvP);
    cudaGetSymbolAddress((void**)&p_woP,    g_woP);
    cudaGetSymbolAddress((void**)&p_wfcP,   g_wfcP);
    cudaGetSymbolAddress((void**)&p_wprojP, g_wprojP);

    cudaFuncSetAttribute(gemm_h_kernel<0>, cudaFuncAttributeMaxDynamicSharedMemorySize, GEMM_H_SMEM);
    cudaFuncSetAttribute(gemm_h_kernel<1>, cudaFuncAttributeMaxDynamicSharedMemorySize, GEMM_H_SMEM);
    cudaFuncSetAttribute(gemm_h_kernel<2>, cudaFuncAttributeMaxDynamicSharedMemorySize, GEMM_H_SMEM);
    cudaFuncSetAttribute(gemm_h_kernel<3>, cudaFuncAttributeMaxDynamicSharedMemorySize, GEMM_H_SMEM);
    cudaFuncSetAttribute(attn_h_kernel,    cudaFuncAttributeMaxDynamicSharedMemorySize, ATT_SMEM);

    // 0. all weight packs in one launch
    pack_all_kernel<<<3072, 256>>>(W_qkv, p_wqkvP, W_o, p_woP, W_fc, p_wfcP, W_proj, p_wprojP);

    // 1. ln1 = LN(x) -> half
    layernorm_kernel<<<M_ / 8, 256>>>(x, ln1_g, ln1_b, p_lnH);
    // 2. qkv = ln1 @ W_qkv + b_qkv -> half
    gemm_h_kernel<3><<<dim3(QKV_N / 128, M_ / 128), 128, GEMM_H_SMEM>>>(
        p_lnH, p_wqkvP, b_qkv, nullptr, p_qkvH, QKV_N, E_);
    // 3. attention (fp16 flash, half out)
    attn_h_kernel<<<dim3(T_ / 64, B_ * H_), 128, ATT_SMEM>>>(p_qkvH, p_attnH);
    // 4. x1 = x + attn @ W_o + b_o (fp32 out)
    gemm_h_kernel<1><<<dim3(E_ / 128, M_ / 128), 128, GEMM_H_SMEM>>>(
        p_attnH, p_woP, b_o, x, p_x1, E_, E_);
    // 5. ln2 = LN(x1) -> half
    layernorm_kernel<<<M_ / 8, 256>>>(p_x1, ln2_g, ln2_b, p_lnH);
    // 6. fc = gelu(ln2 @ W_fc + b_fc) -> half
    gemm_h_kernel<2><<<dim3(FC_N / 128, M_ / 128), 128, GEMM_H_SMEM>>>(
        p_lnH, p_wfcP, b_fc, nullptr, p_fcH, FC_N, E_);
    // 7. out = x1 + fc @ W_proj + b_proj (fp32 out)
    gemm_h_kernel<1><<<dim3(E_ / 128, M_ / 128), 128, GEMM_H_SMEM>>>(
        p_fcH, p_wprojP, b_proj, p_x1, out, E_, FC_N);
}

// round 11
// speedup vs baseline: 11.4545x; 1.0346x over previous
#include <cuda_runtime.h>
#include <cuda_fp16.h>
#include <math.h>
#include <stdint.h>

// ---------------------------------------------------------------------------
// Problem constants
// ---------------------------------------------------------------------------
#define B_  2
#define T_  2048
#define E_  1024
#define H_  16
#define D_  64
#define M_  (B_ * T_)          // 4096
#define QKV_N (3 * E_)         // 3072
#define FC_N  (4 * E_)         // 4096

// ---------------------------------------------------------------------------
// Scratch (device globals; allocations forbidden)
// ---------------------------------------------------------------------------
__device__ __half g_lnH  [(size_t)M_ * E_];
__device__ __half g_qkvH [(size_t)M_ * QKV_N];
__device__ __half g_attnH[(size_t)M_ * E_];
__device__ float  g_x1   [(size_t)M_ * E_];
__device__ __half g_fcH  [(size_t)M_ * FC_N];
__device__ uint32_t g_wqkvP [(size_t)QKV_N * E_ / 2];
__device__ uint32_t g_woP   [(size_t)E_ * E_ / 2];
__device__ uint32_t g_wfcP  [(size_t)FC_N * E_ / 2];
__device__ uint32_t g_wprojP[(size_t)E_ * FC_N / 2];

// ---------------------------------------------------------------------------
// Helpers
// ---------------------------------------------------------------------------
__device__ __forceinline__ uint32_t smem_u32(const void* p) {
    uint32_t a;
    asm("{ .reg .u64 t; cvta.to.shared.u64 t, %1; cvt.u32.u64 %0, t; }" : "=r"(a) : "l"(p));
    return a;
}
#define CP_ASYNC16(dst, src) \
    asm volatile("cp.async.cg.shared.global [%0], [%1], 16;" :: "r"(dst), "l"(src) : "memory")
#define CP_COMMIT() asm volatile("cp.async.commit_group;" ::: "memory")

__device__ __forceinline__ void ldsm_x4(uint32_t (&r)[4], uint32_t addr) {
    asm volatile("ldmatrix.sync.aligned.m8n8.x4.shared.b16 {%0,%1,%2,%3}, [%4];"
                 : "=r"(r[0]), "=r"(r[1]), "=r"(r[2]), "=r"(r[3]) : "r"(addr));
}
__device__ __forceinline__ void ldsm_x4_trans(uint32_t (&r)[4], uint32_t addr) {
    asm volatile("ldmatrix.sync.aligned.m8n8.x4.trans.shared.b16 {%0,%1,%2,%3}, [%4];"
                 : "=r"(r[0]), "=r"(r[1]), "=r"(r[2]), "=r"(r[3]) : "r"(addr));
}

// fp16 MMA: m16n8k16, fp32 accumulate
__device__ __forceinline__ void mma_f16(float (&c)[4],
                                        uint32_t a0, uint32_t a1, uint32_t a2, uint32_t a3,
                                        uint32_t b0, uint32_t b1) {
    asm volatile(
        "mma.sync.aligned.m16n8k16.row.col.f32.f16.f16.f32 "
        "{%0,%1,%2,%3}, {%4,%5,%6,%7}, {%8,%9}, {%0,%1,%2,%3};"
        : "+f"(c[0]), "+f"(c[1]), "+f"(c[2]), "+f"(c[3])
        : "r"(a0), "r"(a1), "r"(a2), "r"(a3), "r"(b0), "r"(b1));
}
__device__ __forceinline__ uint32_t pack_h2(float lo, float hi) {
    const __half2 h = __floats2half2_rn(lo, hi);
    return *(const uint32_t*)&h;
}

// ---------------------------------------------------------------------------
// Merged weight pack (unchanged from Round 10)
// ---------------------------------------------------------------------------
__global__ void pack_all_kernel(const float* __restrict__ W0, uint32_t* __restrict__ P0,
                                const float* __restrict__ W1, uint32_t* __restrict__ P1,
                                const float* __restrict__ W2, uint32_t* __restrict__ P2,
                                const float* __restrict__ W3, uint32_t* __restrict__ P3)
{
    __shared__ float ws[32][132];
    const int bid = blockIdx.x;
    const int tid = threadIdx.x;               // 256

    const float* W; uint32_t* Wp; int N, ntx, nkt, r;
    if (bid < 768)       { W = W0; Wp = P0; N = QKV_N; ntx = 24; nkt = 32;  r = bid; }
    else if (bid < 1024) { W = W1; Wp = P1; N = E_;    ntx = 8;  nkt = 32;  r = bid - 768; }
    else if (bid < 2048) { W = W2; Wp = P2; N = FC_N;  ntx = 32; nkt = 32;  r = bid - 1024; }
    else                 { W = W3; Wp = P3; N = E_;    ntx = 8;  nkt = 128; r = bid - 2048; }
    const int nt = r % ntx;
    const int kt = r / ntx;

    const float* src = W + (size_t)(kt * 32) * N + nt * 128;
    #pragma unroll
    for (int i = 0; i < 4; i++) {
        const int idx = tid + i * 256;
        const int rr = idx >> 5, c4 = idx & 31;
        *(float4*)&ws[rr][c4 * 4] = *(const float4*)(src + (size_t)rr * N + c4 * 4);
    }
    __syncthreads();

    uint32_t* dst = Wp + ((size_t)nt * nkt + kt) * 2048;
    #pragma unroll
    for (int i = 0; i < 8; i++) {
        const int o = tid + i * 256;
        const int s = o >> 6;
        const int lane = (o >> 1) & 31;
        const int reg = o & 1;
        const int kbb = s >> 4, nb = s & 15;
        const int g = lane >> 2, tig = lane & 3;
        const int k = kbb * 16 + reg * 8 + 2 * tig;
        const int n = nb * 8 + g;
        dst[o] = pack_h2(ws[k][n], ws[k + 1][n]);
    }
}

// ---------------------------------------------------------------------------
// fp16 mma.sync GEMM (unchanged from Round 10)
// ---------------------------------------------------------------------------
#define SA_STR_H   72
#define SA_H_BYTES (128 * SA_STR_H * 2)
#define SB_H_BYTES 16384
#define BUF_H      (SA_H_BYTES + SB_H_BYTES)
#define GEMM_H_SMEM (2 * BUF_H)

template<int EPI>
__global__ void __launch_bounds__(128, 2)
gemm_h_kernel(const __half* __restrict__ A, const uint32_t* __restrict__ Wp,
              const float* __restrict__ bias, const float* __restrict__ res,
              void* __restrict__ Cv, int N, int K)
{
    extern __shared__ char smem[];
    const uint32_t sbase = smem_u32(smem);
    float* Cf = (float*)Cv;
    __half* Ch = (__half*)Cv;

    const int tid  = threadIdx.x;
    const int wid  = tid >> 5;
    const int lane = tid & 31;
    const int g    = lane >> 2;
    const int tig  = lane & 3;
    const int wm   = (wid >> 1) * 64;
    const int wn   = (wid & 1) * 64;
    const int m0   = blockIdx.y * 128;
    const int n0   = blockIdx.x * 128;

    const int ntile = K >> 6;
    const size_t wtile0 = (size_t)blockIdx.x * (K >> 5) * 2048;

    const int am = tid >> 3;
    const int ac = tid & 7;

    const int arow = lane & 15;
    const int acol = (lane >> 4) * 8;

    float acc[4][8][4];
    #pragma unroll
    for (int mt = 0; mt < 4; mt++)
        #pragma unroll
        for (int nb = 0; nb < 8; nb++)
            #pragma unroll
            for (int r = 0; r < 4; r++) acc[mt][nb][r] = 0.f;

    auto load_tile = [&](int buf, int kt) {
        const uint32_t sA = sbase + buf * BUF_H;
        const uint32_t sB = sA + SA_H_BYTES;
        const __half* asrc = A + (size_t)(m0 + am) * K + kt * 64 + ac * 8;
        #pragma unroll
        for (int i = 0; i < 8; i++) {
            CP_ASYNC16(sA + (uint32_t)(am + i * 16) * (SA_STR_H * 2) + ac * 16,
                       asrc + (size_t)i * 16 * K);
        }
        const uint32_t* bsrc = Wp + wtile0 + (size_t)kt * 4096 + tid * 4;
        #pragma unroll
        for (int i = 0; i < 8; i++) {
            CP_ASYNC16(sB + (uint32_t)(tid + i * 128) * 16, bsrc + i * 512);
        }
        CP_COMMIT();
    };

    load_tile(0, 0);

    for (int t = 0; t < ntile; t++) {
        const int cur = t & 1;
        if (t + 1 < ntile) {
            load_tile(cur ^ 1, t + 1);
            asm volatile("cp.async.wait_group 1;" ::: "memory");
        } else {
            asm volatile("cp.async.wait_group 0;" ::: "memory");
        }
        __syncthreads();

        const uint32_t sA = sbase + cur * BUF_H;
        const uint32_t* Bs = (const uint32_t*)(smem + cur * BUF_H + SA_H_BYTES);

        #pragma unroll
        for (int kbb = 0; kbb < 4; kbb++) {
            uint32_t a[4][4];
            #pragma unroll
            for (int mt = 0; mt < 4; mt++) {
                const uint32_t addr = sA +
                    (uint32_t)((wm + mt * 16 + arow) * SA_STR_H + kbb * 16 + acol) * 2;
                ldsm_x4(a[mt], addr);
            }
            const uint32_t* Bsub = Bs + (kbb >> 1) * 2048;
            #pragma unroll
            for (int nb = 0; nb < 8; nb++) {
                const int s = (kbb & 1) * 16 + (wn >> 3) + nb;
                const uint2 bb = *(const uint2*)(Bsub + s * 64 + lane * 2);
                #pragma unroll
                for (int mt = 0; mt < 4; mt++)
                    mma_f16(acc[mt][nb], a[mt][0], a[mt][1], a[mt][2], a[mt][3],
                            bb.x, bb.y);
            }
        }
        __syncthreads();
    }

    #pragma unroll
    for (int mt = 0; mt < 4; mt++) {
        const size_t r0 = (size_t)(m0 + wm + mt * 16 + g);
        #pragma unroll
        for (int nb = 0; nb < 8; nb++) {
            const int col = n0 + wn + nb * 8 + 2 * tig;
            const float2 bv = *(const float2*)(bias + col);
            #pragma unroll
            for (int hh = 0; hh < 2; hh++) {
                const size_t row = r0 + hh * 8;
                float vx = acc[mt][nb][hh * 2 + 0] + bv.x;
                float vy = acc[mt][nb][hh * 2 + 1] + bv.y;
                if (EPI == 1) {
                    const float2 r2 = *(const float2*)(res + row * N + col);
                    vx += r2.x; vy += r2.y;
                }
                if (EPI == 2) {
                    vx = 0.5f * vx * (1.0f + erff(vx * 0.70710678118654752f));
                    vy = 0.5f * vy * (1.0f + erff(vy * 0.70710678118654752f));
                }
                if (EPI == 2 || EPI == 3) {
                    *(__half2*)(Ch + row * N + col) = __floats2half2_rn(vx, vy);
                } else {
                    float2 o2; o2.x = vx; o2.y = vy;
                    *(float2*)(Cf + row * N + col) = o2;
                }
            }
        }
    }
}

// ---------------------------------------------------------------------------
// LayerNorm: warp-per-row (unchanged from Round 10)
// ---------------------------------------------------------------------------
__global__ void layernorm_kernel(const float* __restrict__ x,
                                 const float* __restrict__ gamma,
                                 const float* __restrict__ beta,
                                 __half* __restrict__ out)
{
    const int wid  = threadIdx.x >> 5;
    const int lane = threadIdx.x & 31;
    const int row  = blockIdx.x * 8 + wid;

    const float4* xr = (const float4*)(x + (size_t)row * E_);
    float4 v[8];
    float s = 0.f, ss = 0.f;
    #pragma unroll
    for (int i = 0; i < 8; i++) {
        v[i] = xr[lane + 32 * i];
        s  += (v[i].x + v[i].y) + (v[i].z + v[i].w);
        ss += (v[i].x * v[i].x + v[i].y * v[i].y) + (v[i].z * v[i].z + v[i].w * v[i].w);
    }
    #pragma unroll
    for (int o = 16; o > 0; o >>= 1) {
        s  += __shfl_xor_sync(0xffffffffu, s,  o);
        ss += __shfl_xor_sync(0xffffffffu, ss, o);
    }
    const float mean = s * (1.0f / E_);
    const float var  = ss * (1.0f / E_) - mean * mean;
    const float r    = rsqrtf(var + 1e-5f);

    const float4* gp = (const float4*)gamma;
    const float4* bp = (const float4*)beta;
    __half2* op = (__half2*)(out + (size_t)row * E_);
    #pragma unroll
    for (int i = 0; i < 8; i++) {
        const int c4 = lane + 32 * i;
        const float4 gv = gp[c4];
        const float4 bv = bp[c4];
        op[c4 * 2 + 0] = __floats2half2_rn((v[i].x - mean) * r * gv.x + bv.x,
                                           (v[i].y - mean) * r * gv.y + bv.y);
        op[c4 * 2 + 1] = __floats2half2_rn((v[i].z - mean) * r * gv.z + bv.z,
                                           (v[i].w - mean) * r * gv.w + bv.w);
    }
}

// ---------------------------------------------------------------------------
// Flash attention, fp16 mma + ldmatrix fragments + double-buffered K/V.
// Block = 64 queries x 1 head, 128 threads (4 warps x 16 queries).
// smem: Qs[64][72] | stage0: Ks,Vs[64][72] | stage1: Ks,Vs[64][72]
// ---------------------------------------------------------------------------
#define KVSTR 72
#define KVT   (64 * KVSTR)                 // halfs per 64x72 tile
#define ATT_SMEM (5 * KVT * 2)             // 46080 bytes

__global__ void __launch_bounds__(128, 3)
attn_h_kernel(const __half* __restrict__ qkv, __half* __restrict__ out)
{
    extern __shared__ __half smh[];
    const uint32_t sQ = smem_u32(smh);

    const int bh  = blockIdx.y;
    const int b   = bh >> 4;
    const int h   = bh & 15;
    const int m0  = blockIdx.x * 64;
    const int tid = threadIdx.x;
    const int wid = tid >> 5;
    const int lane = tid & 31;
    const int g    = lane >> 2;
    const int tig  = lane & 3;
    const int qr   = wid * 16;
    const int lq   = lane >> 3;            // ldmatrix lane quadrant 0..3
    const int lr   = lane & 7;             // row within quadrant
    const float NEG_INF = __int_as_float(0xff800000);

    // ---- stage Q tile + first K/V tile ----
    const size_t baseQ = ((size_t)(b * T_ + m0)) * QKV_N + h * D_;
    #pragma unroll
    for (int i = 0; i < 4; i++) {
        const int idx = tid + i * 128;
        const int r = idx >> 3, c = idx & 7;
        CP_ASYNC16(sQ + (uint32_t)(r * KVSTR + c * 8) * 2,
                   qkv + baseQ + (size_t)r * QKV_N + c * 8);
    }
    CP_COMMIT();

    auto load_kv = [&](int stage, int t) {
        const uint32_t sK = sQ + (uint32_t)(1 + 2 * stage) * (KVT * 2);
        const uint32_t sV = sK + KVT * 2;
        const size_t baseK = ((size_t)(b * T_ + t * 64)) * QKV_N + E_ + h * D_;
        #pragma unroll
        for (int i = 0; i < 4; i++) {
            const int idx = tid + i * 128;
            const int r = idx >> 3, c = idx & 7;
            const __half* src = qkv + baseK + (size_t)r * QKV_N + c * 8;
            CP_ASYNC16(sK + (uint32_t)(r * KVSTR + c * 8) * 2, src);
            CP_ASYNC16(sV + (uint32_t)(r * KVSTR + c * 8) * 2, src + E_);
        }
        CP_COMMIT();
    };
    load_kv(0, 0);

    asm volatile("cp.async.wait_group 0;" ::: "memory");
    __syncthreads();

    uint32_t qf[4][4];
    #pragma unroll
    for (int kc = 0; kc < 4; kc++) {
        const __half* Qp = smh;
        qf[kc][0] = *(const uint32_t*)(Qp + (qr + g)     * KVSTR + kc * 16 + 2 * tig);
        qf[kc][1] = *(const uint32_t*)(Qp + (qr + g + 8) * KVSTR + kc * 16 + 2 * tig);
        qf[kc][2] = *(const uint32_t*)(Qp + (qr + g)     * KVSTR + kc * 16 + 2 * tig + 8);
        qf[kc][3] = *(const uint32_t*)(Qp + (qr + g + 8) * KVSTR + kc * 16 + 2 * tig + 8);
    }

    float oacc[8][4];
    #pragma unroll
    for (int nb = 0; nb < 8; nb++)
        #pragma unroll
        for (int r = 0; r < 4; r++) oacc[nb][r] = 0.f;
    float mr0 = NEG_INF, mr1 = NEG_INF, l0 = 0.f, l1 = 0.f;

    const int tq0 = m0 + qr + g;
    const int tq1 = tq0 + 8;
    const int ntile = (m0 >> 6) + 1;

    for (int t = 0; t < ntile; t++) {
        const int j0 = t * 64;
        const int cur = t & 1;
        if (t + 1 < ntile) {
            load_kv(cur ^ 1, t + 1);
            asm volatile("cp.async.wait_group 1;" ::: "memory");
        } else {
            asm volatile("cp.async.wait_group 0;" ::: "memory");
        }
        __syncthreads();

        const uint32_t sK = sQ + (uint32_t)(1 + 2 * cur) * (KVT * 2);
        const uint32_t sV = sK + KVT * 2;

        // ---- QK^T via ldmatrix K fragments ----
        float sc[8][4];
        #pragma unroll
        for (int jb = 0; jb < 8; jb++)
            sc[jb][0] = sc[jb][1] = sc[jb][2] = sc[jb][3] = 0.f;
        #pragma unroll
        for (int jp = 0; jp < 4; jp++) {       // jb pairs
            #pragma unroll
            for (int kc = 0; kc < 4; kc++) {
                uint32_t kb[4];
                const uint32_t addr = sK + (uint32_t)(
                    ((2 * jp + (lq >> 1)) * 8 + lr) * KVSTR + kc * 16 + (lq & 1) * 8) * 2;
                ldsm_x4(kb, addr);
                mma_f16(sc[2 * jp],     qf[kc][0], qf[kc][1], qf[kc][2], qf[kc][3], kb[0], kb[1]);
                mma_f16(sc[2 * jp + 1], qf[kc][0], qf[kc][1], qf[kc][2], qf[kc][3], kb[2], kb[3]);
            }
        }
        #pragma unroll
        for (int jb = 0; jb < 8; jb++) {
            sc[jb][0] *= 0.125f; sc[jb][1] *= 0.125f;
            sc[jb][2] *= 0.125f; sc[jb][3] *= 0.125f;
        }

        // ---- causal mask + row max ----
        float tm0 = NEG_INF, tm1 = NEG_INF;
        #pragma unroll
        for (int jb = 0; jb < 8; jb++) {
            const int c0 = j0 + jb * 8 + 2 * tig;
            const int c1 = c0 + 1;
            if (c0 > tq0) sc[jb][0] = NEG_INF;
            if (c1 > tq0) sc[jb][1] = NEG_INF;
            if (c0 > tq1) sc[jb][2] = NEG_INF;
            if (c1 > tq1) sc[jb][3] = NEG_INF;
            tm0 = fmaxf(tm0, fmaxf(sc[jb][0], sc[jb][1]));
            tm1 = fmaxf(tm1, fmaxf(sc[jb][2], sc[jb][3]));
        }
        tm0 = fmaxf(tm0, __shfl_xor_sync(0xffffffffu, tm0, 1));
        tm0 = fmaxf(tm0, __shfl_xor_sync(0xffffffffu, tm0, 2));
        tm1 = fmaxf(tm1, __shfl_xor_sync(0xffffffffu, tm1, 1));
        tm1 = fmaxf(tm1, __shfl_xor_sync(0xffffffffu, tm1, 2));

        const float mn0 = fmaxf(mr0, tm0);
        const float mn1 = fmaxf(mr1, tm1);
        const float a0 = __expf(mr0 - mn0);
        const float a1 = __expf(mr1 - mn1);
        l0 *= a0; l1 *= a1;
        #pragma unroll
        for (int nb = 0; nb < 8; nb++) {
            oacc[nb][0] *= a0; oacc[nb][1] *= a0;
            oacc[nb][2] *= a1; oacc[nb][3] *= a1;
        }

        // ---- P = exp(S - m): straight into A-fragment registers ----
        uint32_t af[4][4];
        float ps0 = 0.f, ps1 = 0.f;
        #pragma unroll
        for (int kc = 0; kc < 4; kc++) {
            const int jA = 2 * kc, jB = 2 * kc + 1;
            const float pA0 = __expf(sc[jA][0] - mn0);
            const float pA1 = __expf(sc[jA][1] - mn0);
            const float pA2 = __expf(sc[jA][2] - mn1);
            const float pA3 = __expf(sc[jA][3] - mn1);
            const float pB0 = __expf(sc[jB][0] - mn0);
            const float pB1 = __expf(sc[jB][1] - mn0);
            const float pB2 = __expf(sc[jB][2] - mn1);
            const float pB3 = __expf(sc[jB][3] - mn1);
            ps0 += (pA0 + pA1) + (pB0 + pB1);
            ps1 += (pA2 + pA3) + (pB2 + pB3);
            af[kc][0] = pack_h2(pA0, pA1);
            af[kc][1] = pack_h2(pA2, pA3);
            af[kc][2] = pack_h2(pB0, pB1);
            af[kc][3] = pack_h2(pB2, pB3);
        }
        ps0 += __shfl_xor_sync(0xffffffffu, ps0, 1);
        ps0 += __shfl_xor_sync(0xffffffffu, ps0, 2);
        ps1 += __shfl_xor_sync(0xffffffffu, ps1, 1);
        ps1 += __shfl_xor_sync(0xffffffffu, ps1, 2);
        l0 += ps0; l1 += ps1;
        mr0 = mn0; mr1 = mn1;

        // ---- PV via ldmatrix.trans V fragments ----
        #pragma unroll
        for (int p = 0; p < 4; p++) {          // d blocks of 16 -> nb = 2p, 2p+1
            #pragma unroll
            for (int kc = 0; kc < 4; kc++) {
                uint32_t vb[4];
                const uint32_t addr = sV + (uint32_t)(
                    (kc * 16 + (lq & 1) * 8 + lr) * KVSTR + p * 16 + (lq >> 1) * 8) * 2;
                ldsm_x4_trans(vb, addr);
                mma_f16(oacc[2 * p],     af[kc][0], af[kc][1], af[kc][2], af[kc][3], vb[0], vb[1]);
                mma_f16(oacc[2 * p + 1], af[kc][0], af[kc][1], af[kc][2], af[kc][3], vb[2], vb[3]);
            }
        }
        __syncthreads();   // all warps done with stage cur before next load overwrites
    }

    // ---- epilogue: normalize, half out ----
    const float inv0 = 1.0f / l0;
    const float inv1 = 1.0f / l1;
    const size_t row0 = (size_t)(b * T_ + tq0);
    const size_t row1 = (size_t)(b * T_ + tq1);
    #pragma unroll
    for (int nb = 0; nb < 8; nb++) {
        const int col = h * D_ + nb * 8 + 2 * tig;
        *(__half2*)(out + row0 * E_ + col) =
            __floats2half2_rn(oacc[nb][0] * inv0, oacc[nb][1] * inv0);
        *(__half2*)(out + row1 * E_ + col) =
            __floats2half2_rn(oacc[nb][2] * inv1, oacc[nb][3] * inv1);
    }
}

// ---------------------------------------------------------------------------
// Launch
// ---------------------------------------------------------------------------
extern "C" void kernel_launch(void* const* d_in, const int* in_sizes, int n_in,
                              void* d_out, int out_size)
{
    const float* x      = (const float*)d_in[0];
    const float* ln1_g  = (const float*)d_in[1];
    const float* ln1_b  = (const float*)d_in[2];
    const float* ln2_g  = (const float*)d_in[3];
    const float* ln2_b  = (const float*)d_in[4];
    const float* W_qkv  = (const float*)d_in[5];
    const float* b_qkv  = (const float*)d_in[6];
    const float* W_o    = (const float*)d_in[7];
    const float* b_o    = (const float*)d_in[8];
    const float* W_fc   = (const float*)d_in[9];
    const float* b_fc   = (const float*)d_in[10];
    const float* W_proj = (const float*)d_in[11];
    const float* b_proj = (const float*)d_in[12];
    float* out = (float*)d_out;

    __half *p_lnH, *p_qkvH, *p_attnH, *p_fcH;
    float *p_x1;
    uint32_t *p_wqkvP, *p_woP, *p_wfcP, *p_wprojP;
    cudaGetSymbolAddress((void**)&p_lnH,    g_lnH);
    cudaGetSymbolAddress((void**)&p_qkvH,   g_qkvH);
    cudaGetSymbolAddress((void**)&p_attnH,  g_attnH);
    cudaGetSymbolAddress((void**)&p_x1,     g_x1);
    cudaGetSymbolAddress((void**)&p_fcH,    g_fcH);
    cudaGetSymbolAddress((void**)&p_wqkvP,  g_wqkvP);
    cudaGetSymbolAddress((void**)&p_woP,    g_woP);
    cudaGetSymbolAddress((void**)&p_wfcP,   g_wfcP);
    cudaGetSymbolAddress((void**)&p_wprojP, g_wprojP);

    cudaFuncSetAttribute(gemm_h_kernel<0>, cudaFuncAttributeMaxDynamicSharedMemorySize, GEMM_H_SMEM);
    cudaFuncSetAttribute(gemm_h_kernel<1>, cudaFuncAttributeMaxDynamicSharedMemorySize, GEMM_H_SMEM);
    cudaFuncSetAttribute(gemm_h_kernel<2>, cudaFuncAttributeMaxDynamicSharedMemorySize, GEMM_H_SMEM);
    cudaFuncSetAttribute(gemm_h_kernel<3>, cudaFuncAttributeMaxDynamicSharedMemorySize, GEMM_H_SMEM);
    cudaFuncSetAttribute(attn_h_kernel,    cudaFuncAttributeMaxDynamicSharedMemorySize, ATT_SMEM);

    // 0. all weight packs in one launch
    pack_all_kernel<<<3072, 256>>>(W_qkv, p_wqkvP, W_o, p_woP, W_fc, p_wfcP, W_proj, p_wprojP);

    // 1. ln1 = LN(x) -> half
    layernorm_kernel<<<M_ / 8, 256>>>(x, ln1_g, ln1_b, p_lnH);
    // 2. qkv = ln1 @ W_qkv + b_qkv -> half
    gemm_h_kernel<3><<<dim3(QKV_N / 128, M_ / 128), 128, GEMM_H_SMEM>>>(
        p_lnH, p_wqkvP, b_qkv, nullptr, p_qkvH, QKV_N, E_);
    // 3. attention (fp16 flash, ldmatrix + double-buffered K/V)
    attn_h_kernel<<<dim3(T_ / 64, B_ * H_), 128, ATT_SMEM>>>(p_qkvH, p_attnH);
    // 4. x1 = x + attn @ W_o + b_o (fp32 out)
    gemm_h_kernel<1><<<dim3(E_ / 128, M_ / 128), 128, GEMM_H_SMEM>>>(
        p_attnH, p_woP, b_o, x, p_x1, E_, E_);
    // 5. ln2 = LN(x1) -> half
    layernorm_kernel<<<M_ / 8, 256>>>(p_x1, ln2_g, ln2_b, p_lnH);
    // 6. fc = gelu(ln2 @ W_fc + b_fc) -> half
    gemm_h_kernel<2><<<dim3(FC_N / 128, M_ / 128), 128, GEMM_H_SMEM>>>(
        p_lnH, p_wfcP, b_fc, nullptr, p_fcH, FC_N, E_);
    // 7. out = x1 + fc @ W_proj + b_proj (fp32 out)
    gemm_h_kernel<1><<<dim3(E_ / 128, M_ / 128), 128, GEMM_H_SMEM>>>(
        p_fcH, p_wprojP, b_proj, p_x1, out, E_, FC_N);
}

// round 12
// speedup vs baseline: 11.8332x; 1.0331x over previous
#include <cuda_runtime.h>
#include <cuda_fp16.h>
#include <math.h>
#include <stdint.h>

// ---------------------------------------------------------------------------
// Problem constants
// ---------------------------------------------------------------------------
#define B_  2
#define T_  2048
#define E_  1024
#define H_  16
#define D_  64
#define M_  (B_ * T_)          // 4096
#define QKV_N (3 * E_)         // 3072
#define FC_N  (4 * E_)         // 4096

// ---------------------------------------------------------------------------
// Scratch (device globals; allocations forbidden)
// ---------------------------------------------------------------------------
__device__ __half g_lnH  [(size_t)M_ * E_];
__device__ __half g_qkvH [(size_t)M_ * QKV_N];
__device__ __half g_attnH[(size_t)M_ * E_];
__device__ float  g_x1   [(size_t)M_ * E_];
__device__ __half g_fcH  [(size_t)M_ * FC_N];
__device__ uint32_t g_wqkvP [(size_t)QKV_N * E_ / 2];
__device__ uint32_t g_woP   [(size_t)E_ * E_ / 2];
__device__ uint32_t g_wfcP  [(size_t)FC_N * E_ / 2];
__device__ uint32_t g_wprojP[(size_t)E_ * FC_N / 2];

// ---------------------------------------------------------------------------
// Helpers
// ---------------------------------------------------------------------------
__device__ __forceinline__ uint32_t smem_u32(const void* p) {
    uint32_t a;
    asm("{ .reg .u64 t; cvta.to.shared.u64 t, %1; cvt.u32.u64 %0, t; }" : "=r"(a) : "l"(p));
    return a;
}
#define CP_ASYNC16(dst, src) \
    asm volatile("cp.async.cg.shared.global [%0], [%1], 16;" :: "r"(dst), "l"(src) : "memory")
#define CP_COMMIT() asm volatile("cp.async.commit_group;" ::: "memory")

__device__ __forceinline__ void ldsm_x4(uint32_t (&r)[4], uint32_t addr) {
    asm volatile("ldmatrix.sync.aligned.m8n8.x4.shared.b16 {%0,%1,%2,%3}, [%4];"
                 : "=r"(r[0]), "=r"(r[1]), "=r"(r[2]), "=r"(r[3]) : "r"(addr));
}
__device__ __forceinline__ void ldsm_x4_trans(uint32_t (&r)[4], uint32_t addr) {
    asm volatile("ldmatrix.sync.aligned.m8n8.x4.trans.shared.b16 {%0,%1,%2,%3}, [%4];"
                 : "=r"(r[0]), "=r"(r[1]), "=r"(r[2]), "=r"(r[3]) : "r"(addr));
}

// fp16 MMA: m16n8k16, fp32 accumulate
__device__ __forceinline__ void mma_f16(float (&c)[4],
                                        uint32_t a0, uint32_t a1, uint32_t a2, uint32_t a3,
                                        uint32_t b0, uint32_t b1) {
    asm volatile(
        "mma.sync.aligned.m16n8k16.row.col.f32.f16.f16.f32 "
        "{%0,%1,%2,%3}, {%4,%5,%6,%7}, {%8,%9}, {%0,%1,%2,%3};"
        : "+f"(c[0]), "+f"(c[1]), "+f"(c[2]), "+f"(c[3])
        : "r"(a0), "r"(a1), "r"(a2), "r"(a3), "r"(b0), "r"(b1));
}
__device__ __forceinline__ uint32_t pack_h2(float lo, float hi) {
    const __half2 h = __floats2half2_rn(lo, hi);
    return *(const uint32_t*)&h;
}

// ---------------------------------------------------------------------------
// Merged weight pack (unchanged)
// ---------------------------------------------------------------------------
__global__ void pack_all_kernel(const float* __restrict__ W0, uint32_t* __restrict__ P0,
                                const float* __restrict__ W1, uint32_t* __restrict__ P1,
                                const float* __restrict__ W2, uint32_t* __restrict__ P2,
                                const float* __restrict__ W3, uint32_t* __restrict__ P3)
{
    __shared__ float ws[32][132];
    const int bid = blockIdx.x;
    const int tid = threadIdx.x;               // 256

    const float* W; uint32_t* Wp; int N, ntx, nkt, r;
    if (bid < 768)       { W = W0; Wp = P0; N = QKV_N; ntx = 24; nkt = 32;  r = bid; }
    else if (bid < 1024) { W = W1; Wp = P1; N = E_;    ntx = 8;  nkt = 32;  r = bid - 768; }
    else if (bid < 2048) { W = W2; Wp = P2; N = FC_N;  ntx = 32; nkt = 32;  r = bid - 1024; }
    else                 { W = W3; Wp = P3; N = E_;    ntx = 8;  nkt = 128; r = bid - 2048; }
    const int nt = r % ntx;
    const int kt = r / ntx;

    const float* src = W + (size_t)(kt * 32) * N + nt * 128;
    #pragma unroll
    for (int i = 0; i < 4; i++) {
        const int idx = tid + i * 256;
        const int rr = idx >> 5, c4 = idx & 31;
        *(float4*)&ws[rr][c4 * 4] = *(const float4*)(src + (size_t)rr * N + c4 * 4);
    }
    __syncthreads();

    uint32_t* dst = Wp + ((size_t)nt * nkt + kt) * 2048;
    #pragma unroll
    for (int i = 0; i < 8; i++) {
        const int o = tid + i * 256;
        const int s = o >> 6;
        const int lane = (o >> 1) & 31;
        const int reg = o & 1;
        const int kbb = s >> 4, nb = s & 15;
        const int g = lane >> 2, tig = lane & 3;
        const int k = kbb * 16 + reg * 8 + 2 * tig;
        const int n = nb * 8 + g;
        dst[o] = pack_h2(ws[k][n], ws[k + 1][n]);
    }
}

// ---------------------------------------------------------------------------
// fp16 mma.sync GEMM (unchanged from Round 10/11)
// ---------------------------------------------------------------------------
#define SA_STR_H   72
#define SA_H_BYTES (128 * SA_STR_H * 2)
#define SB_H_BYTES 16384
#define BUF_H      (SA_H_BYTES + SB_H_BYTES)
#define GEMM_H_SMEM (2 * BUF_H)

template<int EPI>
__global__ void __launch_bounds__(128, 2)
gemm_h_kernel(const __half* __restrict__ A, const uint32_t* __restrict__ Wp,
              const float* __restrict__ bias, const float* __restrict__ res,
              void* __restrict__ Cv, int N, int K)
{
    extern __shared__ char smem[];
    const uint32_t sbase = smem_u32(smem);
    float* Cf = (float*)Cv;
    __half* Ch = (__half*)Cv;

    const int tid  = threadIdx.x;
    const int wid  = tid >> 5;
    const int lane = tid & 31;
    const int g    = lane >> 2;
    const int tig  = lane & 3;
    const int wm   = (wid >> 1) * 64;
    const int wn   = (wid & 1) * 64;
    const int m0   = blockIdx.y * 128;
    const int n0   = blockIdx.x * 128;

    const int ntile = K >> 6;
    const size_t wtile0 = (size_t)blockIdx.x * (K >> 5) * 2048;

    const int am = tid >> 3;
    const int ac = tid & 7;

    const int arow = lane & 15;
    const int acol = (lane >> 4) * 8;

    float acc[4][8][4];
    #pragma unroll
    for (int mt = 0; mt < 4; mt++)
        #pragma unroll
        for (int nb = 0; nb < 8; nb++)
            #pragma unroll
            for (int r = 0; r < 4; r++) acc[mt][nb][r] = 0.f;

    auto load_tile = [&](int buf, int kt) {
        const uint32_t sA = sbase + buf * BUF_H;
        const uint32_t sB = sA + SA_H_BYTES;
        const __half* asrc = A + (size_t)(m0 + am) * K + kt * 64 + ac * 8;
        #pragma unroll
        for (int i = 0; i < 8; i++) {
            CP_ASYNC16(sA + (uint32_t)(am + i * 16) * (SA_STR_H * 2) + ac * 16,
                       asrc + (size_t)i * 16 * K);
        }
        const uint32_t* bsrc = Wp + wtile0 + (size_t)kt * 4096 + tid * 4;
        #pragma unroll
        for (int i = 0; i < 8; i++) {
            CP_ASYNC16(sB + (uint32_t)(tid + i * 128) * 16, bsrc + i * 512);
        }
        CP_COMMIT();
    };

    load_tile(0, 0);

    for (int t = 0; t < ntile; t++) {
        const int cur = t & 1;
        if (t + 1 < ntile) {
            load_tile(cur ^ 1, t + 1);
            asm volatile("cp.async.wait_group 1;" ::: "memory");
        } else {
            asm volatile("cp.async.wait_group 0;" ::: "memory");
        }
        __syncthreads();

        const uint32_t sA = sbase + cur * BUF_H;
        const uint32_t* Bs = (const uint32_t*)(smem + cur * BUF_H + SA_H_BYTES);

        #pragma unroll
        for (int kbb = 0; kbb < 4; kbb++) {
            uint32_t a[4][4];
            #pragma unroll
            for (int mt = 0; mt < 4; mt++) {
                const uint32_t addr = sA +
                    (uint32_t)((wm + mt * 16 + arow) * SA_STR_H + kbb * 16 + acol) * 2;
                ldsm_x4(a[mt], addr);
            }
            const uint32_t* Bsub = Bs + (kbb >> 1) * 2048;
            #pragma unroll
            for (int nb = 0; nb < 8; nb++) {
                const int s = (kbb & 1) * 16 + (wn >> 3) + nb;
                const uint2 bb = *(const uint2*)(Bsub + s * 64 + lane * 2);
                #pragma unroll
                for (int mt = 0; mt < 4; mt++)
                    mma_f16(acc[mt][nb], a[mt][0], a[mt][1], a[mt][2], a[mt][3],
                            bb.x, bb.y);
            }
        }
        __syncthreads();
    }

    #pragma unroll
    for (int mt = 0; mt < 4; mt++) {
        const size_t r0 = (size_t)(m0 + wm + mt * 16 + g);
        #pragma unroll
        for (int nb = 0; nb < 8; nb++) {
            const int col = n0 + wn + nb * 8 + 2 * tig;
            const float2 bv = *(const float2*)(bias + col);
            #pragma unroll
            for (int hh = 0; hh < 2; hh++) {
                const size_t row = r0 + hh * 8;
                float vx = acc[mt][nb][hh * 2 + 0] + bv.x;
                float vy = acc[mt][nb][hh * 2 + 1] + bv.y;
                if (EPI == 1) {
                    const float2 r2 = *(const float2*)(res + row * N + col);
                    vx += r2.x; vy += r2.y;
                }
                if (EPI == 2) {
                    vx = 0.5f * vx * (1.0f + erff(vx * 0.70710678118654752f));
                    vy = 0.5f * vy * (1.0f + erff(vy * 0.70710678118654752f));
                }
                if (EPI == 2 || EPI == 3) {
                    *(__half2*)(Ch + row * N + col) = __floats2half2_rn(vx, vy);
                } else {
                    float2 o2; o2.x = vx; o2.y = vy;
                    *(float2*)(Cf + row * N + col) = o2;
                }
            }
        }
    }
}

// ---------------------------------------------------------------------------
// LayerNorm: warp-per-row (unchanged)
// ---------------------------------------------------------------------------
__global__ void layernorm_kernel(const float* __restrict__ x,
                                 const float* __restrict__ gamma,
                                 const float* __restrict__ beta,
                                 __half* __restrict__ out)
{
    const int wid  = threadIdx.x >> 5;
    const int lane = threadIdx.x & 31;
    const int row  = blockIdx.x * 8 + wid;

    const float4* xr = (const float4*)(x + (size_t)row * E_);
    float4 v[8];
    float s = 0.f, ss = 0.f;
    #pragma unroll
    for (int i = 0; i < 8; i++) {
        v[i] = xr[lane + 32 * i];
        s  += (v[i].x + v[i].y) + (v[i].z + v[i].w);
        ss += (v[i].x * v[i].x + v[i].y * v[i].y) + (v[i].z * v[i].z + v[i].w * v[i].w);
    }
    #pragma unroll
    for (int o = 16; o > 0; o >>= 1) {
        s  += __shfl_xor_sync(0xffffffffu, s,  o);
        ss += __shfl_xor_sync(0xffffffffu, ss, o);
    }
    const float mean = s * (1.0f / E_);
    const float var  = ss * (1.0f / E_) - mean * mean;
    const float r    = rsqrtf(var + 1e-5f);

    const float4* gp = (const float4*)gamma;
    const float4* bp = (const float4*)beta;
    __half2* op = (__half2*)(out + (size_t)row * E_);
    #pragma unroll
    for (int i = 0; i < 8; i++) {
        const int c4 = lane + 32 * i;
        const float4 gv = gp[c4];
        const float4 bv = bp[c4];
        op[c4 * 2 + 0] = __floats2half2_rn((v[i].x - mean) * r * gv.x + bv.x,
                                           (v[i].y - mean) * r * gv.y + bv.y);
        op[c4 * 2 + 1] = __floats2half2_rn((v[i].z - mean) * r * gv.z + bv.z,
                                           (v[i].w - mean) * r * gv.w + bv.w);
    }
}

// ---------------------------------------------------------------------------
// Flash attention, fp16 mma + ldmatrix + double-buffered K/V.
// Changes vs Round 11: longest-block-first scheduling, diagonal-only masking,
// 1/sqrt(d) folded exactly into Q fragments (2^-3 exact in fp16).
// ---------------------------------------------------------------------------
#define KVSTR 72
#define KVT   (64 * KVSTR)
#define ATT_SMEM (5 * KVT * 2)             // 46080 bytes

__global__ void __launch_bounds__(128, 3)
attn_h_kernel(const __half* __restrict__ qkv, __half* __restrict__ out)
{
    extern __shared__ __half smh[];
    const uint32_t sQ = smem_u32(smh);

    const int bh  = blockIdx.y;
    const int b   = bh >> 4;
    const int h   = bh & 15;
    const int m0  = (gridDim.x - 1 - blockIdx.x) * 64;   // longest blocks first
    const int tid = threadIdx.x;
    const int wid = tid >> 5;
    const int lane = tid & 31;
    const int g    = lane >> 2;
    const int tig  = lane & 3;
    const int qr   = wid * 16;
    const int lq   = lane >> 3;
    const int lr   = lane & 7;
    const float NEG_INF = __int_as_float(0xff800000);

    // ---- stage Q tile + first K/V tile ----
    const size_t baseQ = ((size_t)(b * T_ + m0)) * QKV_N + h * D_;
    #pragma unroll
    for (int i = 0; i < 4; i++) {
        const int idx = tid + i * 128;
        const int r = idx >> 3, c = idx & 7;
        CP_ASYNC16(sQ + (uint32_t)(r * KVSTR + c * 8) * 2,
                   qkv + baseQ + (size_t)r * QKV_N + c * 8);
    }
    CP_COMMIT();

    auto load_kv = [&](int stage, int t) {
        const uint32_t sK = sQ + (uint32_t)(1 + 2 * stage) * (KVT * 2);
        const uint32_t sV = sK + KVT * 2;
        const size_t baseK = ((size_t)(b * T_ + t * 64)) * QKV_N + E_ + h * D_;
        #pragma unroll
        for (int i = 0; i < 4; i++) {
            const int idx = tid + i * 128;
            const int r = idx >> 3, c = idx & 7;
            const __half* src = qkv + baseK + (size_t)r * QKV_N + c * 8;
            CP_ASYNC16(sK + (uint32_t)(r * KVSTR + c * 8) * 2, src);
            CP_ASYNC16(sV + (uint32_t)(r * KVSTR + c * 8) * 2, src + E_);
        }
        CP_COMMIT();
    };
    load_kv(0, 0);

    asm volatile("cp.async.wait_group 0;" ::: "memory");
    __syncthreads();

    // Q fragments, scaled by 2^-3 (exact in fp16)
    const __half2 qscale = __half2half2(__float2half_rn(0.125f));
    uint32_t qf[4][4];
    #pragma unroll
    for (int kc = 0; kc < 4; kc++) {
        const __half* Qp = smh;
        #pragma unroll
        for (int j = 0; j < 4; j++) {
            const int rr = qr + g + (j & 1) * 8;
            const int cc = kc * 16 + 2 * tig + (j >> 1) * 8;
            __half2 q2 = *(const __half2*)(Qp + rr * KVSTR + cc);
            q2 = __hmul2(q2, qscale);
            qf[kc][j] = *(const uint32_t*)&q2;
        }
    }

    float oacc[8][4];
    #pragma unroll
    for (int nb = 0; nb < 8; nb++)
        #pragma unroll
        for (int r = 0; r < 4; r++) oacc[nb][r] = 0.f;
    float mr0 = NEG_INF, mr1 = NEG_INF, l0 = 0.f, l1 = 0.f;

    const int tq0 = m0 + qr + g;
    const int tq1 = tq0 + 8;
    const int ntile = (m0 >> 6) + 1;

    for (int t = 0; t < ntile; t++) {
        const int j0 = t * 64;
        const int cur = t & 1;
        if (t + 1 < ntile) {
            load_kv(cur ^ 1, t + 1);
            asm volatile("cp.async.wait_group 1;" ::: "memory");
        } else {
            asm volatile("cp.async.wait_group 0;" ::: "memory");
        }
        __syncthreads();

        const uint32_t sK = sQ + (uint32_t)(1 + 2 * cur) * (KVT * 2);
        const uint32_t sV = sK + KVT * 2;

        // ---- QK^T via ldmatrix K fragments (scores pre-scaled via Q) ----
        float sc[8][4];
        #pragma unroll
        for (int jb = 0; jb < 8; jb++)
            sc[jb][0] = sc[jb][1] = sc[jb][2] = sc[jb][3] = 0.f;
        #pragma unroll
        for (int jp = 0; jp < 4; jp++) {
            #pragma unroll
            for (int kc = 0; kc < 4; kc++) {
                uint32_t kb[4];
                const uint32_t addr = sK + (uint32_t)(
                    ((2 * jp + (lq >> 1)) * 8 + lr) * KVSTR + kc * 16 + (lq & 1) * 8) * 2;
                ldsm_x4(kb, addr);
                mma_f16(sc[2 * jp],     qf[kc][0], qf[kc][1], qf[kc][2], qf[kc][3], kb[0], kb[1]);
                mma_f16(sc[2 * jp + 1], qf[kc][0], qf[kc][1], qf[kc][2], qf[kc][3], kb[2], kb[3]);
            }
        }

        // ---- causal mask (diagonal tile only) + row max ----
        if (t == ntile - 1) {
            #pragma unroll
            for (int jb = 0; jb < 8; jb++) {
                const int c0 = j0 + jb * 8 + 2 * tig;
                const int c1 = c0 + 1;
                if (c0 > tq0) sc[jb][0] = NEG_INF;
                if (c1 > tq0) sc[jb][1] = NEG_INF;
                if (c0 > tq1) sc[jb][2] = NEG_INF;
                if (c1 > tq1) sc[jb][3] = NEG_INF;
            }
        }
        float tm0 = NEG_INF, tm1 = NEG_INF;
        #pragma unroll
        for (int jb = 0; jb < 8; jb++) {
            tm0 = fmaxf(tm0, fmaxf(sc[jb][0], sc[jb][1]));
            tm1 = fmaxf(tm1, fmaxf(sc[jb][2], sc[jb][3]));
        }
        tm0 = fmaxf(tm0, __shfl_xor_sync(0xffffffffu, tm0, 1));
        tm0 = fmaxf(tm0, __shfl_xor_sync(0xffffffffu, tm0, 2));
        tm1 = fmaxf(tm1, __shfl_xor_sync(0xffffffffu, tm1, 1));
        tm1 = fmaxf(tm1, __shfl_xor_sync(0xffffffffu, tm1, 2));

        const float mn0 = fmaxf(mr0, tm0);
        const float mn1 = fmaxf(mr1, tm1);
        const float a0 = __expf(mr0 - mn0);
        const float a1 = __expf(mr1 - mn1);
        l0 *= a0; l1 *= a1;
        #pragma unroll
        for (int nb = 0; nb < 8; nb++) {
            oacc[nb][0] *= a0; oacc[nb][1] *= a0;
            oacc[nb][2] *= a1; oacc[nb][3] *= a1;
        }

        // ---- P = exp(S - m) -> A fragments ----
        uint32_t af[4][4];
        float ps0 = 0.f, ps1 = 0.f;
        #pragma unroll
        for (int kc = 0; kc < 4; kc++) {
            const int jA = 2 * kc, jB = 2 * kc + 1;
            const float pA0 = __expf(sc[jA][0] - mn0);
            const float pA1 = __expf(sc[jA][1] - mn0);
            const float pA2 = __expf(sc[jA][2] - mn1);
            const float pA3 = __expf(sc[jA][3] - mn1);
            const float pB0 = __expf(sc[jB][0] - mn0);
            const float pB1 = __expf(sc[jB][1] - mn0);
            const float pB2 = __expf(sc[jB][2] - mn1);
            const float pB3 = __expf(sc[jB][3] - mn1);
            ps0 += (pA0 + pA1) + (pB0 + pB1);
            ps1 += (pA2 + pA3) + (pB2 + pB3);
            af[kc][0] = pack_h2(pA0, pA1);
            af[kc][1] = pack_h2(pA2, pA3);
            af[kc][2] = pack_h2(pB0, pB1);
            af[kc][3] = pack_h2(pB2, pB3);
        }
        ps0 += __shfl_xor_sync(0xffffffffu, ps0, 1);
        ps0 += __shfl_xor_sync(0xffffffffu, ps0, 2);
        ps1 += __shfl_xor_sync(0xffffffffu, ps1, 1);
        ps1 += __shfl_xor_sync(0xffffffffu, ps1, 2);
        l0 += ps0; l1 += ps1;
        mr0 = mn0; mr1 = mn1;

        // ---- PV via ldmatrix.trans V fragments ----
        #pragma unroll
        for (int p = 0; p < 4; p++) {
            #pragma unroll
            for (int kc = 0; kc < 4; kc++) {
                uint32_t vb[4];
                const uint32_t addr = sV + (uint32_t)(
                    (kc * 16 + (lq & 1) * 8 + lr) * KVSTR + p * 16 + (lq >> 1) * 8) * 2;
                ldsm_x4_trans(vb, addr);
                mma_f16(oacc[2 * p],     af[kc][0], af[kc][1], af[kc][2], af[kc][3], vb[0], vb[1]);
                mma_f16(oacc[2 * p + 1], af[kc][0], af[kc][1], af[kc][2], af[kc][3], vb[2], vb[3]);
            }
        }
        __syncthreads();
    }

    // ---- epilogue: normalize, half out ----
    const float inv0 = 1.0f / l0;
    const float inv1 = 1.0f / l1;
    const size_t row0 = (size_t)(b * T_ + tq0);
    const size_t row1 = (size_t)(b * T_ + tq1);
    #pragma unroll
    for (int nb = 0; nb < 8; nb++) {
        const int col = h * D_ + nb * 8 + 2 * tig;
        *(__half2*)(out + row0 * E_ + col) =
            __floats2half2_rn(oacc[nb][0] * inv0, oacc[nb][1] * inv0);
        *(__half2*)(out + row1 * E_ + col) =
            __floats2half2_rn(oacc[nb][2] * inv1, oacc[nb][3] * inv1);
    }
}

// ---------------------------------------------------------------------------
// Launch
// ---------------------------------------------------------------------------
extern "C" void kernel_launch(void* const* d_in, const int* in_sizes, int n_in,
                              void* d_out, int out_size)
{
    const float* x      = (const float*)d_in[0];
    const float* ln1_g  = (const float*)d_in[1];
    const float* ln1_b  = (const float*)d_in[2];
    const float* ln2_g  = (const float*)d_in[3];
    const float* ln2_b  = (const float*)d_in[4];
    const float* W_qkv  = (const float*)d_in[5];
    const float* b_qkv  = (const float*)d_in[6];
    const float* W_o    = (const float*)d_in[7];
    const float* b_o    = (const float*)d_in[8];
    const float* W_fc   = (const float*)d_in[9];
    const float* b_fc   = (const float*)d_in[10];
    const float* W_proj = (const float*)d_in[11];
    const float* b_proj = (const float*)d_in[12];
    float* out = (float*)d_out;

    __half *p_lnH, *p_qkvH, *p_attnH, *p_fcH;
    float *p_x1;
    uint32_t *p_wqkvP, *p_woP, *p_wfcP, *p_wprojP;
    cudaGetSymbolAddress((void**)&p_lnH,    g_lnH);
    cudaGetSymbolAddress((void**)&p_qkvH,   g_qkvH);
    cudaGetSymbolAddress((void**)&p_attnH,  g_attnH);
    cudaGetSymbolAddress((void**)&p_x1,     g_x1);
    cudaGetSymbolAddress((void**)&p_fcH,    g_fcH);
    cudaGetSymbolAddress((void**)&p_wqkvP,  g_wqkvP);
    cudaGetSymbolAddress((void**)&p_woP,    g_woP);
    cudaGetSymbolAddress((void**)&p_wfcP,   g_wfcP);
    cudaGetSymbolAddress((void**)&p_wprojP, g_wprojP);

    cudaFuncSetAttribute(gemm_h_kernel<0>, cudaFuncAttributeMaxDynamicSharedMemorySize, GEMM_H_SMEM);
    cudaFuncSetAttribute(gemm_h_kernel<1>, cudaFuncAttributeMaxDynamicSharedMemorySize, GEMM_H_SMEM);
    cudaFuncSetAttribute(gemm_h_kernel<2>, cudaFuncAttributeMaxDynamicSharedMemorySize, GEMM_H_SMEM);
    cudaFuncSetAttribute(gemm_h_kernel<3>, cudaFuncAttributeMaxDynamicSharedMemorySize, GEMM_H_SMEM);
    cudaFuncSetAttribute(attn_h_kernel,    cudaFuncAttributeMaxDynamicSharedMemorySize, ATT_SMEM);

    // 0. all weight packs in one launch
    pack_all_kernel<<<3072, 256>>>(W_qkv, p_wqkvP, W_o, p_woP, W_fc, p_wfcP, W_proj, p_wprojP);

    // 1. ln1 = LN(x) -> half
    layernorm_kernel<<<M_ / 8, 256>>>(x, ln1_g, ln1_b, p_lnH);
    // 2. qkv = ln1 @ W_qkv + b_qkv -> half
    gemm_h_kernel<3><<<dim3(QKV_N / 128, M_ / 128), 128, GEMM_H_SMEM>>>(
        p_lnH, p_wqkvP, b_qkv, nullptr, p_qkvH, QKV_N, E_);
    // 3. attention
    attn_h_kernel<<<dim3(T_ / 64, B_ * H_), 128, ATT_SMEM>>>(p_qkvH, p_attnH);
    // 4. x1 = x + attn @ W_o + b_o (fp32 out)
    gemm_h_kernel<1><<<dim3(E_ / 128, M_ / 128), 128, GEMM_H_SMEM>>>(
        p_attnH, p_woP, b_o, x, p_x1, E_, E_);
    // 5. ln2 = LN(x1) -> half
    layernorm_kernel<<<M_ / 8, 256>>>(p_x1, ln2_g, ln2_b, p_lnH);
    // 6. fc = gelu(ln2 @ W_fc + b_fc) -> half
    gemm_h_kernel<2><<<dim3(FC_N / 128, M_ / 128), 128, GEMM_H_SMEM>>>(
        p_lnH, p_wfcP, b_fc, nullptr, p_fcH, FC_N, E_);
    // 7. out = x1 + fc @ W_proj + b_proj (fp32 out)
    gemm_h_kernel<1><<<dim3(E_ / 128, M_ / 128), 128, GEMM_H_SMEM>>>(
        p_fcH, p_wprojP, b_proj, p_x1, out, E_, FC_N);
}